// round 1
// baseline (speedup 1.0000x reference)
#include <cuda_runtime.h>

// ---------------------------------------------------------------------------
// GeneralizedBilinearAttention  (B=128, T=256, N=128, ATTN=VEC=512, fp32)
//
//  G1: aM[b,n,v]   = sum_a AO[b,n,a] * W[a,v]
//  L : lin_a[b,n]  = AO[b,n,:]. a_w ;  lin_b[b,t] = IN[b,t,:] . b_w
//  G2: sim[b,t,n]  = IN[b,t,:] . aM[b,n,:] + lin_a + lin_b + bias
//      attn        = mask * exp(tanh(sim)) / sum_n mask * exp(tanh(sim))
//  G3: out[b,t,v]  = sum_n attn[b,t,n] * AO[b,n,v]
// ---------------------------------------------------------------------------

#define CB 128   // batch
#define CT 256   // query positions
#define CN 128   // bunch size
#define CAD 512  // attn dim
#define CVD 512  // vec dim

// ---- scratch (device globals: allocation-free, graph-capturable) ----------
__device__ __align__(16) float g_aM[CB * CN * CVD];    // 33.5 MB
__device__ __align__(16) float g_attn[CB * CT * CN];   // 16.8 MB
__device__ __align__(16) float g_lina[CB * CN];
__device__ __align__(16) float g_linb[CB * CT];
__device__ __align__(16) float g_maskf[CB * CN];
__device__ int g_mode[1];

// ---------------------------------------------------------------------------
// Mask dtype classifier: the reference mask is bool; the harness may hand us
// u8 (1B), i32 (4B) or f32 (4B). Inspect the first 16384 bytes (in-bounds for
// every layout since the element count is 16384).
//   f32: value 1.0f has bytes {00,00,80,3F} -> bytes outside {0,1}
//   i32: only byte (i%4==0) can be 1
//   u8 : random 0/1 bytes at all positions
// ---------------------------------------------------------------------------
__global__ void mask_classify(const unsigned char* __restrict__ m) {
    __shared__ int s_notbin, s_odd;
    if (threadIdx.x == 0) { s_notbin = 0; s_odd = 0; }
    __syncthreads();
    int notbin = 0, odd = 0;
    for (int i = threadIdx.x; i < CB * CN; i += blockDim.x) {
        unsigned char v = m[i];
        if (v > 1) notbin = 1;
        if ((i & 3) && v == 1) odd = 1;
    }
    if (notbin) atomicOr(&s_notbin, 1);
    if (odd)    atomicOr(&s_odd, 1);
    __syncthreads();
    if (threadIdx.x == 0)
        g_mode[0] = s_notbin ? 2 : (s_odd ? 0 : 1);  // 0=u8, 1=i32, 2=f32
}

__global__ void mask_norm(const void* __restrict__ m) {
    int i = blockIdx.x * blockDim.x + threadIdx.x;
    if (i >= CB * CN) return;
    int md = g_mode[0];
    float v;
    if (md == 0)      v = (((const unsigned char*)m)[i] != 0) ? 1.f : 0.f;
    else if (md == 1) v = (((const int*)m)[i] != 0) ? 1.f : 0.f;
    else              v = (((const float*)m)[i] != 0.f) ? 1.f : 0.f;
    g_maskf[i] = v;
}

// ---------------------------------------------------------------------------
// Linear terms: one warp per 512-dim dot product.
//   warps [0, B*N)            -> lin_a
//   warps [B*N, B*N + B*T)    -> lin_b
// ---------------------------------------------------------------------------
__global__ void __launch_bounds__(256) lin_kernel(const float* __restrict__ IN,
                                                  const float* __restrict__ AO,
                                                  const float* __restrict__ a_w,
                                                  const float* __restrict__ b_w) {
    int w = (blockIdx.x * blockDim.x + threadIdx.x) >> 5;
    int lane = threadIdx.x & 31;
    if (w >= CB * CN + CB * CT) return;
    const float* row; const float* wv; float* out; int idx;
    if (w < CB * CN) {
        idx = w; row = AO + (long)w * CAD; wv = a_w; out = g_lina;
    } else {
        idx = w - CB * CN; row = IN + (long)idx * CVD; wv = b_w; out = g_linb;
    }
    float s = 0.f;
#pragma unroll
    for (int k = 0; k < 512; k += 128) {
        float4 x = *(const float4*)(row + k + lane * 4);
        float4 y = *(const float4*)(wv  + k + lane * 4);
        s += x.x * y.x + x.y * y.y + x.z * y.z + x.w * y.w;
    }
#pragma unroll
    for (int o = 16; o; o >>= 1) s += __shfl_xor_sync(0xffffffffu, s, o);
    if (lane == 0) out[idx] = s;
}

// ---------------------------------------------------------------------------
// G1: aM = AO_flat(16384x512) @ W(512x512).  128x128x16 tile, 8x8 microtile.
// ---------------------------------------------------------------------------
__global__ void __launch_bounds__(256) g1_gemm(const float* __restrict__ AO,
                                               const float* __restrict__ W) {
    __shared__ float As[16][132];   // k-major (transposed), padded, 16B-aligned rows
    __shared__ float Bs[16][128];
    const int tid = threadIdx.x;
    const int tx  = tid & 15;
    const int ty  = tid >> 4;
    const int m0  = blockIdx.y * 128;
    const int n0  = blockIdx.x * 128;
    const int lm  = tid >> 2;          // 0..63
    const int lk4 = (tid & 3) * 4;     // 0,4,8,12
    const int bk  = tid >> 5;          // 0..7
    const int bn4 = (tid & 31) * 4;    // 0..124

    float c[8][8];
#pragma unroll
    for (int i = 0; i < 8; ++i)
#pragma unroll
        for (int j = 0; j < 8; ++j) c[i][j] = 0.f;

    const float* Abase = AO + (long)(m0 + lm) * CAD + lk4;
    const float* Bbase = W  + (long)bk * CVD + n0 + bn4;

    for (int k0 = 0; k0 < CAD; k0 += 16) {
        float4 a0 = *(const float4*)(Abase + k0);
        float4 a1 = *(const float4*)(Abase + (long)64 * CAD + k0);
        float4 b0 = *(const float4*)(Bbase + (long)k0 * CVD);
        float4 b1 = *(const float4*)(Bbase + (long)(k0 + 8) * CVD);
        __syncthreads();
        As[lk4 + 0][lm] = a0.x; As[lk4 + 1][lm] = a0.y;
        As[lk4 + 2][lm] = a0.z; As[lk4 + 3][lm] = a0.w;
        As[lk4 + 0][lm + 64] = a1.x; As[lk4 + 1][lm + 64] = a1.y;
        As[lk4 + 2][lm + 64] = a1.z; As[lk4 + 3][lm + 64] = a1.w;
        *(float4*)&Bs[bk][bn4]     = b0;
        *(float4*)&Bs[bk + 8][bn4] = b1;
        __syncthreads();
#pragma unroll
        for (int k = 0; k < 16; ++k) {
            float4 A0 = *(const float4*)&As[k][ty * 8];
            float4 A1 = *(const float4*)&As[k][ty * 8 + 4];
            float4 B0 = *(const float4*)&Bs[k][tx * 8];
            float4 B1 = *(const float4*)&Bs[k][tx * 8 + 4];
            float av[8] = {A0.x, A0.y, A0.z, A0.w, A1.x, A1.y, A1.z, A1.w};
            float bv[8] = {B0.x, B0.y, B0.z, B0.w, B1.x, B1.y, B1.z, B1.w};
#pragma unroll
            for (int i = 0; i < 8; ++i)
#pragma unroll
                for (int j = 0; j < 8; ++j)
                    c[i][j] = fmaf(av[i], bv[j], c[i][j]);
        }
    }
#pragma unroll
    for (int i = 0; i < 8; ++i) {
        float* dst = g_aM + (long)(m0 + ty * 8 + i) * CVD + n0 + tx * 8;
        *(float4*)dst       = make_float4(c[i][0], c[i][1], c[i][2], c[i][3]);
        *(float4*)(dst + 4) = make_float4(c[i][4], c[i][5], c[i][6], c[i][7]);
    }
}

// ---------------------------------------------------------------------------
// G2: per batch, sim(64x128) = IN_tile(64x512) @ aM(128x512)^T, fused
//     tanh + masked softmax over full N=128, writes attn.
//     64x128x16 tile, 4x8 microtile, 256 threads.
// ---------------------------------------------------------------------------
__global__ void __launch_bounds__(256) g2_attn(const float* __restrict__ IN,
                                               const float* __restrict__ biasp) {
    __shared__ float As[16][68];
    __shared__ float Bs[16][132];
    __shared__ float red[64][17];
    __shared__ float rowsum[64];
    const int tid = threadIdx.x;
    const int tx  = tid & 15;
    const int ty  = tid >> 4;
    const int b   = blockIdx.y;
    const int m0  = blockIdx.x * 64;
    const int lm  = tid >> 2;
    const int lk4 = (tid & 3) * 4;

    const float* A = IN   + ((long)b * CT + m0) * CVD;
    const float* M = g_aM + (long)b * CN * CVD;

    float c[4][8];
#pragma unroll
    for (int i = 0; i < 4; ++i)
#pragma unroll
        for (int j = 0; j < 8; ++j) c[i][j] = 0.f;

    for (int k0 = 0; k0 < CVD; k0 += 16) {
        float4 av = *(const float4*)(A + (long)lm * CVD + k0 + lk4);
        float4 b0 = *(const float4*)(M + (long)lm * CVD + k0 + lk4);
        float4 b1 = *(const float4*)(M + (long)(lm + 64) * CVD + k0 + lk4);
        __syncthreads();
        As[lk4 + 0][lm] = av.x; As[lk4 + 1][lm] = av.y;
        As[lk4 + 2][lm] = av.z; As[lk4 + 3][lm] = av.w;
        Bs[lk4 + 0][lm] = b0.x; Bs[lk4 + 1][lm] = b0.y;
        Bs[lk4 + 2][lm] = b0.z; Bs[lk4 + 3][lm] = b0.w;
        Bs[lk4 + 0][lm + 64] = b1.x; Bs[lk4 + 1][lm + 64] = b1.y;
        Bs[lk4 + 2][lm + 64] = b1.z; Bs[lk4 + 3][lm + 64] = b1.w;
        __syncthreads();
#pragma unroll
        for (int k = 0; k < 16; ++k) {
            float4 A0 = *(const float4*)&As[k][ty * 4];
            float4 B0 = *(const float4*)&Bs[k][tx * 8];
            float4 B1 = *(const float4*)&Bs[k][tx * 8 + 4];
            float av_[4] = {A0.x, A0.y, A0.z, A0.w};
            float bv[8]  = {B0.x, B0.y, B0.z, B0.w, B1.x, B1.y, B1.z, B1.w};
#pragma unroll
            for (int i = 0; i < 4; ++i)
#pragma unroll
                for (int j = 0; j < 8; ++j)
                    c[i][j] = fmaf(av_[i], bv[j], c[i][j]);
        }
    }

    // ---- fused epilogue: tanh, masked exp, row-normalize over N=128 ----
    const float biasv = biasp[0];
    float la[8], mk[8];
#pragma unroll
    for (int j = 0; j < 8; ++j) {
        int n = tx * 8 + j;
        la[j] = g_lina[b * CN + n];
        mk[j] = g_maskf[b * CN + n];
    }
#pragma unroll
    for (int i = 0; i < 4; ++i) {
        int r = ty * 4 + i;
        float lb = g_linb[b * CT + m0 + r];
        float p = 0.f;
#pragma unroll
        for (int j = 0; j < 8; ++j) {
            float s = tanhf(c[i][j] + la[j] + lb + biasv);
            float e = mk[j] * __expf(s);   // tanh in [-1,1]: no max-shift needed
            c[i][j] = e;
            p += e;
        }
        red[r][tx] = p;
    }
    __syncthreads();
    if (tid < 64) {
        float s = 0.f;
#pragma unroll
        for (int j = 0; j < 16; ++j) s += red[tid][j];
        rowsum[tid] = s + 1e-30f;          // all-masked row -> attn = 0 (matches ref)
    }
    __syncthreads();
#pragma unroll
    for (int i = 0; i < 4; ++i) {
        int r = ty * 4 + i;
        float inv = 1.0f / rowsum[r];
        float* dst = g_attn + ((long)b * CT + m0 + r) * CN + tx * 8;
        *(float4*)dst       = make_float4(c[i][0] * inv, c[i][1] * inv,
                                          c[i][2] * inv, c[i][3] * inv);
        *(float4*)(dst + 4) = make_float4(c[i][4] * inv, c[i][5] * inv,
                                          c[i][6] * inv, c[i][7] * inv);
    }
}

// ---------------------------------------------------------------------------
// G3: per batch, out(64x128 tile) = attn(256x128) @ AO(128x512).
//     64x128x16 tile, 4x8 microtile.
// ---------------------------------------------------------------------------
__global__ void __launch_bounds__(256) g3_ctx(const float* __restrict__ AO,
                                              float* __restrict__ OUT) {
    __shared__ float As[16][68];
    __shared__ float Bs[16][128];
    const int tid = threadIdx.x;
    const int tx  = tid & 15;
    const int ty  = tid >> 4;
    const int b   = blockIdx.z;
    const int m0  = blockIdx.y * 64;
    const int n0  = blockIdx.x * 128;
    const int lm  = tid >> 2;
    const int lk4 = (tid & 3) * 4;
    const int bk  = tid >> 5;
    const int bn4 = (tid & 31) * 4;

    const float* P = g_attn + (long)b * CT * CN;
    const float* V = AO     + (long)b * CN * CAD;

    float c[4][8];
#pragma unroll
    for (int i = 0; i < 4; ++i)
#pragma unroll
        for (int j = 0; j < 8; ++j) c[i][j] = 0.f;

    for (int k0 = 0; k0 < CN; k0 += 16) {
        float4 av = *(const float4*)(P + (long)(m0 + lm) * CN + k0 + lk4);
        float4 b0 = *(const float4*)(V + (long)(k0 + bk) * CAD + n0 + bn4);
        float4 b1 = *(const float4*)(V + (long)(k0 + bk + 8) * CAD + n0 + bn4);
        __syncthreads();
        As[lk4 + 0][lm] = av.x; As[lk4 + 1][lm] = av.y;
        As[lk4 + 2][lm] = av.z; As[lk4 + 3][lm] = av.w;
        *(float4*)&Bs[bk][bn4]     = b0;
        *(float4*)&Bs[bk + 8][bn4] = b1;
        __syncthreads();
#pragma unroll
        for (int k = 0; k < 16; ++k) {
            float4 A0 = *(const float4*)&As[k][ty * 4];
            float4 B0 = *(const float4*)&Bs[k][tx * 8];
            float4 B1 = *(const float4*)&Bs[k][tx * 8 + 4];
            float av_[4] = {A0.x, A0.y, A0.z, A0.w};
            float bv[8]  = {B0.x, B0.y, B0.z, B0.w, B1.x, B1.y, B1.z, B1.w};
#pragma unroll
            for (int i = 0; i < 4; ++i)
#pragma unroll
                for (int j = 0; j < 8; ++j)
                    c[i][j] = fmaf(av_[i], bv[j], c[i][j]);
        }
    }
#pragma unroll
    for (int i = 0; i < 4; ++i) {
        float* dst = OUT + ((long)b * CT + m0 + ty * 4 + i) * CAD + n0 + tx * 8;
        *(float4*)dst       = make_float4(c[i][0], c[i][1], c[i][2], c[i][3]);
        *(float4*)(dst + 4) = make_float4(c[i][4], c[i][5], c[i][6], c[i][7]);
    }
}

// ---------------------------------------------------------------------------
extern "C" void kernel_launch(void* const* d_in, const int* in_sizes, int n_in,
                              void* d_out, int out_size) {
    const float* inputs = (const float*)d_in[0];  // (B,T,VD)
    const float* ao     = (const float*)d_in[1];  // (B,N,AD)
    const void*  mask   = d_in[2];                // (B,N) bool-ish
    const float* W      = (const float*)d_in[3];  // (AD,VD)
    const float* a_w    = (const float*)d_in[4];  // (AD,)
    const float* b_w    = (const float*)d_in[5];  // (VD,)
    const float* bias   = (const float*)d_in[6];  // (1,)
    float* out = (float*)d_out;                   // (B,T,AD)

    mask_classify<<<1, 256>>>((const unsigned char*)mask);
    mask_norm<<<(CB * CN + 255) / 256, 256>>>(mask);

    int nwarps = CB * CN + CB * CT;               // 49152
    lin_kernel<<<(nwarps * 32 + 255) / 256, 256>>>(inputs, ao, a_w, b_w);

    g1_gemm<<<dim3(CVD / 128, (CB * CN) / 128), 256>>>(ao, W);
    g2_attn<<<dim3(CT / 64, CB), 256>>>(inputs, bias);
    g3_ctx<<<dim3(CAD / 128, CT / 64, CB), 256>>>(ao, out);
}

// round 3
// speedup vs baseline: 2.1190x; 2.1190x over previous
#include <cuda_runtime.h>
#include <cuda_bf16.h>
#include <cstdint>

// ---------------------------------------------------------------------------
// GeneralizedBilinearAttention via mma.sync bf16 (base sm_103 ISA).
//   G1: aM   = AO_flat(16384x512) @ WT(512x512)   (TN, k-major both sides)
//   G2: sim  = IN(256x512) @ aM_b(128x512)^T  + fused tanh/masked-softmax
//   G3: out  = attn(256x128) @ AOT_b(512x128)^T
// fp32 operands split to bf16 hi/lo; 3 MMA products (hh + hl + lh), fp32 acc.
// ---------------------------------------------------------------------------

#define CB 128
#define CT 256
#define CN 128
#define CAD 512
#define CVD 512

// ---- scratch ----------------------------------------------------------------
__device__ __align__(16) unsigned short g_AOhi[CB * CN * CAD];
__device__ __align__(16) unsigned short g_AOlo[CB * CN * CAD];
__device__ __align__(16) unsigned short g_INhi[CB * CT * CVD];
__device__ __align__(16) unsigned short g_INlo[CB * CT * CVD];
__device__ __align__(16) unsigned short g_WThi[CVD * CAD];
__device__ __align__(16) unsigned short g_WTlo[CVD * CAD];
__device__ __align__(16) unsigned short g_aMhi[CB * CN * CVD];
__device__ __align__(16) unsigned short g_aMlo[CB * CN * CVD];
__device__ __align__(16) unsigned short g_AOThi[CB * CAD * CN];
__device__ __align__(16) unsigned short g_AOTlo[CB * CAD * CN];
__device__ __align__(16) unsigned short g_athi[CB * CT * CN];
__device__ __align__(16) unsigned short g_atlo[CB * CT * CN];
__device__ __align__(16) float g_lina[CB * CN];
__device__ __align__(16) float g_linb[CB * CT];
__device__ __align__(16) float g_maskf[CB * CN];
__device__ int g_mode[1];

// ---- smem layout (double-buffered 128x64 bf16 tiles, SW128 swizzle) ---------
#define STAGE   65536
#define SM_AHI  0
#define SM_ALO  16384
#define SM_BHI  32768
#define SM_BLO  49152
#define SM_LIN  131072
#define SM_MSK  (SM_LIN + 512)
#define SM_LNB  (SM_MSK + 512)
#define SMEM_G13 131072
#define SMEM_G2  (SM_LNB + 512)

// ---- helpers ----------------------------------------------------------------
__device__ __forceinline__ uint32_t smem_u32(const void* p) {
    return (uint32_t)__cvta_generic_to_shared(p);
}
__device__ __forceinline__ void ldsm4(uint32_t* r, uint32_t addr) {
    asm volatile("ldmatrix.sync.aligned.m8n8.x4.shared.b16 {%0,%1,%2,%3}, [%4];"
                 : "=r"(r[0]), "=r"(r[1]), "=r"(r[2]), "=r"(r[3]) : "r"(addr));
}
__device__ __forceinline__ void mma_bf16(float* c, const uint32_t* a,
                                         uint32_t b0, uint32_t b1) {
    asm volatile("mma.sync.aligned.m16n8k16.row.col.f32.bf16.bf16.f32 "
                 "{%0,%1,%2,%3}, {%4,%5,%6,%7}, {%8,%9}, {%0,%1,%2,%3};"
                 : "+f"(c[0]), "+f"(c[1]), "+f"(c[2]), "+f"(c[3])
                 : "r"(a[0]), "r"(a[1]), "r"(a[2]), "r"(a[3]), "r"(b0), "r"(b1));
}
__device__ __forceinline__ uint32_t fragaddr(uint32_t base, int row, int cu) {
    int off = row * 128 + cu * 16;
    off ^= (off >> 3) & 0x70;       // SW128
    return base + off;
}
// 16B cp.async of a 128x64-bf16 tile (k-major rows), SW128-swizzled dest.
__device__ __forceinline__ void cp_tile(uint32_t dst, const unsigned short* src,
                                        int ld, int k0, int tid) {
#pragma unroll
    for (int i = 0; i < 4; ++i) {
        int u = i * 256 + tid;
        int row = u >> 3, c = u & 7;
        int off = row * 128 + c * 16;
        off ^= (off >> 3) & 0x70;
        const void* g = src + (size_t)row * ld + k0 + c * 8;
        asm volatile("cp.async.cg.shared.global [%0], [%1], 16;"
                     :: "r"(dst + off), "l"(g) : "memory");
    }
}
__device__ __forceinline__ void split2u(float x, float y, uint32_t& h, uint32_t& l) {
    __nv_bfloat16 xh = __float2bfloat16(x), yh = __float2bfloat16(y);
    __nv_bfloat16 xl = __float2bfloat16(x - __bfloat162float(xh));
    __nv_bfloat16 yl = __float2bfloat16(y - __bfloat162float(yh));
    h = ((uint32_t)__bfloat16_as_ushort(yh) << 16) | __bfloat16_as_ushort(xh);
    l = ((uint32_t)__bfloat16_as_ushort(yl) << 16) | __bfloat16_as_ushort(xl);
}

// ---- mma mainloop: C(128x128) += (Ah+Al) @ (Bh+Bl)^T over K (k-major TN) ----
__device__ __forceinline__ void compute_chunk(uint32_t st, float acc[4][4][4],
                                              const int* rowm, const int* rowb,
                                              int cgrp) {
#pragma unroll
    for (int ks = 0; ks < 4; ++ks) {
        const int cu = 2 * ks + cgrp;
        uint32_t ah[4][4], al[4][4], bh[2][4], bl[2][4];
#pragma unroll
        for (int j = 0; j < 2; ++j) {
            ldsm4(bh[j], fragaddr(st + SM_BHI, rowb[j], cu));
            ldsm4(bl[j], fragaddr(st + SM_BLO, rowb[j], cu));
        }
#pragma unroll
        for (int mi = 0; mi < 4; ++mi) {
            ldsm4(ah[mi], fragaddr(st + SM_AHI, rowm[mi], cu));
            ldsm4(al[mi], fragaddr(st + SM_ALO, rowm[mi], cu));
        }
#pragma unroll
        for (int mi = 0; mi < 4; ++mi)
#pragma unroll
            for (int nj = 0; nj < 4; ++nj) {
                const int j = nj >> 1, o = nj & 1;
                mma_bf16(acc[mi][nj], ah[mi], bh[j][o], bh[j][o + 2]);
                mma_bf16(acc[mi][nj], ah[mi], bl[j][o], bl[j][o + 2]);
                mma_bf16(acc[mi][nj], al[mi], bh[j][o], bh[j][o + 2]);
            }
    }
}

__device__ __forceinline__ void gemm_main(uint32_t smb, float acc[4][4][4],
    const unsigned short* Ah, const unsigned short* Al, int lda,
    const unsigned short* Bh, const unsigned short* Bl, int ldb, int K) {
    const int tid = threadIdx.x, lane = tid & 31, w = tid >> 5;
    const int mw = (w & 1) * 64, nw = (w >> 1) * 32;
    const int grp = lane >> 3, rin = lane & 7;
    int rowm[4], rowb[2];
#pragma unroll
    for (int mi = 0; mi < 4; ++mi) rowm[mi] = mw + mi * 16 + rin + ((grp & 1) << 3);
#pragma unroll
    for (int j = 0; j < 2; ++j)    rowb[j] = nw + j * 16 + rin + ((grp & 1) << 3);
    const int cgrp = grp >> 1;
    const int nch = K >> 6;

    cp_tile(smb + SM_AHI, Ah, lda, 0, tid);
    cp_tile(smb + SM_ALO, Al, lda, 0, tid);
    cp_tile(smb + SM_BHI, Bh, ldb, 0, tid);
    cp_tile(smb + SM_BLO, Bl, ldb, 0, tid);
    asm volatile("cp.async.commit_group;" ::: "memory");

    for (int c = 0; c < nch; ++c) {
        const uint32_t st = smb + (uint32_t)(c & 1) * STAGE;
        if (c + 1 < nch) {
            const uint32_t st2 = smb + (uint32_t)((c + 1) & 1) * STAGE;
            const int k0 = (c + 1) << 6;
            cp_tile(st2 + SM_AHI, Ah, lda, k0, tid);
            cp_tile(st2 + SM_ALO, Al, lda, k0, tid);
            cp_tile(st2 + SM_BHI, Bh, ldb, k0, tid);
            cp_tile(st2 + SM_BLO, Bl, ldb, k0, tid);
            asm volatile("cp.async.commit_group;" ::: "memory");
            asm volatile("cp.async.wait_group 1;" ::: "memory");
        } else {
            asm volatile("cp.async.wait_group 0;" ::: "memory");
        }
        __syncthreads();
        compute_chunk(st, acc, rowm, rowb, cgrp);
        __syncthreads();
    }
}

// ---------------------------------------------------------------------------
// Preprocessing
// ---------------------------------------------------------------------------
__global__ void mask_classify(const unsigned char* __restrict__ m) {
    __shared__ int s_notbin, s_odd;
    if (threadIdx.x == 0) { s_notbin = 0; s_odd = 0; }
    __syncthreads();
    int notbin = 0, odd = 0;
    for (int i = threadIdx.x; i < CB * CN; i += blockDim.x) {
        unsigned char v = m[i];
        if (v > 1) notbin = 1;
        if ((i & 3) && v == 1) odd = 1;
    }
    if (notbin) atomicOr(&s_notbin, 1);
    if (odd)    atomicOr(&s_odd, 1);
    __syncthreads();
    if (threadIdx.x == 0) g_mode[0] = s_notbin ? 2 : (s_odd ? 0 : 1);
}
__global__ void mask_norm(const void* __restrict__ m) {
    int i = blockIdx.x * blockDim.x + threadIdx.x;
    if (i >= CB * CN) return;
    int md = g_mode[0];
    float v;
    if (md == 0)      v = (((const unsigned char*)m)[i] != 0) ? 1.f : 0.f;
    else if (md == 1) v = (((const int*)m)[i] != 0) ? 1.f : 0.f;
    else              v = (((const float*)m)[i] != 0.f) ? 1.f : 0.f;
    g_maskf[i] = v;
}

// One warp per 512-row: lin dot product + bf16 hi/lo split write.
__global__ void __launch_bounds__(256) lin_split(const float* __restrict__ IN,
                                                 const float* __restrict__ AO,
                                                 const float* __restrict__ a_w,
                                                 const float* __restrict__ b_w) {
    int w = (blockIdx.x * blockDim.x + threadIdx.x) >> 5;
    int lane = threadIdx.x & 31;
    const int nAO = CB * CN;
    if (w >= nAO + CB * CT) return;
    const float* row; const float* wv; float* outd; int idx;
    uint32_t *dhi, *dlo;
    if (w < nAO) {
        idx = w; row = AO + (size_t)w * CAD; wv = a_w; outd = g_lina;
        dhi = (uint32_t*)g_AOhi + (size_t)w * 256;
        dlo = (uint32_t*)g_AOlo + (size_t)w * 256;
    } else {
        idx = w - nAO; row = IN + (size_t)idx * CVD; wv = b_w; outd = g_linb;
        dhi = (uint32_t*)g_INhi + (size_t)idx * 256;
        dlo = (uint32_t*)g_INlo + (size_t)idx * 256;
    }
    float s = 0.f;
#pragma unroll
    for (int k = 0; k < 512; k += 128) {
        int e = k + lane * 4;
        float4 x = *(const float4*)(row + e);
        float4 y = *(const float4*)(wv + e);
        s += x.x * y.x + x.y * y.y + x.z * y.z + x.w * y.w;
        uint32_t h0, l0, h1, l1;
        split2u(x.x, x.y, h0, l0);
        split2u(x.z, x.w, h1, l1);
        dhi[e >> 1] = h0; dhi[(e >> 1) + 1] = h1;
        dlo[e >> 1] = l0; dlo[(e >> 1) + 1] = l1;
    }
#pragma unroll
    for (int o = 16; o; o >>= 1) s += __shfl_xor_sync(0xffffffffu, s, o);
    if (lane == 0) outd[idx] = s;
}

// W(512x512) -> WT hi/lo
__global__ void wt_split(const float* __restrict__ W) {
    __shared__ float t[32][33];
    int tx = threadIdx.x, ty = threadIdx.y;
    int a0 = blockIdx.y * 32, v0 = blockIdx.x * 32;
    for (int i = ty; i < 32; i += 8)
        t[i][tx] = W[(size_t)(a0 + i) * CVD + v0 + tx];
    __syncthreads();
    for (int i = ty; i < 32; i += 8) {
        float x = t[tx][i];
        __nv_bfloat16 h = __float2bfloat16(x);
        __nv_bfloat16 l = __float2bfloat16(x - __bfloat162float(h));
        size_t o = (size_t)(v0 + i) * CAD + a0 + tx;
        g_WThi[o] = __bfloat16_as_ushort(h);
        g_WTlo[o] = __bfloat16_as_ushort(l);
    }
}

// AO per batch (128n x 512v) -> AOT (512v x 128n) hi/lo
__global__ void aot_split(const float* __restrict__ AO) {
    __shared__ float t[32][33];
    int tx = threadIdx.x, ty = threadIdx.y;
    int b = blockIdx.z;
    int v0 = blockIdx.x * 32, n0 = blockIdx.y * 32;
    const float* src = AO + (size_t)b * CN * CAD;
    for (int i = ty; i < 32; i += 8)
        t[i][tx] = src[(size_t)(n0 + i) * CAD + v0 + tx];
    __syncthreads();
    unsigned short* dh = g_AOThi + (size_t)b * CAD * CN;
    unsigned short* dl = g_AOTlo + (size_t)b * CAD * CN;
    for (int i = ty; i < 32; i += 8) {
        float x = t[tx][i];
        __nv_bfloat16 h = __float2bfloat16(x);
        __nv_bfloat16 l = __float2bfloat16(x - __bfloat162float(h));
        size_t o = (size_t)(v0 + i) * CN + n0 + tx;
        dh[o] = __bfloat16_as_ushort(h);
        dl[o] = __bfloat16_as_ushort(l);
    }
}

// ---------------------------------------------------------------------------
// G1: aM = AO_flat @ WT^T -> aM hi/lo.  grid (4 Ntiles, 128 Mtiles)
// ---------------------------------------------------------------------------
__global__ void __launch_bounds__(256, 1) g1_mma() {
    extern __shared__ char sm[];
    const uint32_t smb = smem_u32(sm);
    const int n0 = blockIdx.x * 128;
    const size_t m0 = (size_t)blockIdx.y * 128;
    float acc[4][4][4];
#pragma unroll
    for (int a = 0; a < 4; ++a)
#pragma unroll
        for (int b = 0; b < 4; ++b)
#pragma unroll
            for (int cc = 0; cc < 4; ++cc) acc[a][b][cc] = 0.f;

    gemm_main(smb, acc, g_AOhi + m0 * CAD, g_AOlo + m0 * CAD, CAD,
              g_WThi + (size_t)n0 * CAD, g_WTlo + (size_t)n0 * CAD, CAD, CAD);

    const int lane = threadIdx.x & 31, w = threadIdx.x >> 5;
    const int mw = (w & 1) * 64, nw = (w >> 1) * 32;
    const int qr = lane >> 2, qc = (lane & 3) * 2;
    uint32_t* ghi = (uint32_t*)g_aMhi;
    uint32_t* glo = (uint32_t*)g_aMlo;
#pragma unroll
    for (int mi = 0; mi < 4; ++mi)
#pragma unroll
        for (int nj = 0; nj < 4; ++nj) {
            size_t r0 = m0 + mw + mi * 16 + qr;
            size_t cp = (size_t)(n0 + nw + nj * 8 + qc) >> 1;
            uint32_t h, l;
            split2u(acc[mi][nj][0], acc[mi][nj][1], h, l);
            ghi[r0 * (CVD >> 1) + cp] = h; glo[r0 * (CVD >> 1) + cp] = l;
            split2u(acc[mi][nj][2], acc[mi][nj][3], h, l);
            ghi[(r0 + 8) * (CVD >> 1) + cp] = h; glo[(r0 + 8) * (CVD >> 1) + cp] = l;
        }
}

// ---------------------------------------------------------------------------
// G2: sim = IN_tile @ aM_b^T + fused tanh/masked-softmax -> attn hi/lo.
//     grid (2 Mtiles, B)
// ---------------------------------------------------------------------------
__global__ void __launch_bounds__(256, 1) g2_mma(const float* __restrict__ biasp) {
    extern __shared__ char sm[];
    const uint32_t smb = smem_u32(sm);
    const int tid = threadIdx.x;
    const int b = blockIdx.y;
    const int m0 = blockIdx.x * 128;
    float* sl  = (float*)(sm + SM_LIN);
    float* sk  = (float*)(sm + SM_MSK);
    float* slb = (float*)(sm + SM_LNB);
    if (tid < 128) {
        sl[tid]  = g_lina[b * CN + tid];
        sk[tid]  = g_maskf[b * CN + tid];
        slb[tid] = g_linb[b * CT + m0 + tid];
    }
    float acc[4][4][4];
#pragma unroll
    for (int a = 0; a < 4; ++a)
#pragma unroll
        for (int bb = 0; bb < 4; ++bb)
#pragma unroll
            for (int cc = 0; cc < 4; ++cc) acc[a][bb][cc] = 0.f;

    gemm_main(smb, acc,
              g_INhi + ((size_t)b * CT + m0) * CVD,
              g_INlo + ((size_t)b * CT + m0) * CVD, CVD,
              g_aMhi + (size_t)b * CN * CVD,
              g_aMlo + (size_t)b * CN * CVD, CVD, CVD);

    // stage exp(tanh(.)) * mask into smem (reuses tile buffers; mainloop synced)
    const int lane = tid & 31, w = tid >> 5;
    const int mw = (w & 1) * 64, nw = (w >> 1) * 32;
    const int qr = lane >> 2, qc = (lane & 3) * 2;
    const float bs = biasp[0];
    float* ssim = (float*)sm;                      // 128 x 132 floats
#pragma unroll
    for (int mi = 0; mi < 4; ++mi)
#pragma unroll
        for (int nj = 0; nj < 4; ++nj) {
            int c0 = nw + nj * 8 + qc;
            float sla = sl[c0], slA = sl[c0 + 1];
            float mk0 = sk[c0], mk1 = sk[c0 + 1];
#pragma unroll
            for (int p = 0; p < 2; ++p) {
                int r = mw + mi * 16 + qr + p * 8;
                float lb = slb[r] + bs;
                float e0 = mk0 * __expf(tanhf(acc[mi][nj][2 * p] + sla + lb));
                float e1 = mk1 * __expf(tanhf(acc[mi][nj][2 * p + 1] + slA + lb));
                ssim[r * 132 + c0] = e0;
                ssim[r * 132 + c0 + 1] = e1;
            }
        }
    __syncthreads();
    if (tid < 128) {
        const float* rowp = ssim + tid * 132;
        float s = 0.f;
#pragma unroll
        for (int n = 0; n < 128; ++n) s += rowp[n];
        const float inv = 1.0f / (s + 1e-30f);
        const size_t t = (size_t)b * CT + m0 + tid;
        uint32_t* ohi = (uint32_t*)g_athi + t * 64;
        uint32_t* olo = (uint32_t*)g_atlo + t * 64;
#pragma unroll
        for (int j = 0; j < 64; ++j) {
            uint32_t h, l;
            split2u(rowp[2 * j] * inv, rowp[2 * j + 1] * inv, h, l);
            ohi[j] = h; olo[j] = l;
        }
    }
}

// ---------------------------------------------------------------------------
// G3: out = attn_tile @ AOT_b^T (fp32 out).  grid (4 Ntiles, 2 Mtiles, B)
// ---------------------------------------------------------------------------
__global__ void __launch_bounds__(256, 1) g3_mma(float* __restrict__ OUT) {
    extern __shared__ char sm[];
    const uint32_t smb = smem_u32(sm);
    const int b = blockIdx.z;
    const int m0 = blockIdx.y * 128;
    const int n0 = blockIdx.x * 128;
    float acc[4][4][4];
#pragma unroll
    for (int a = 0; a < 4; ++a)
#pragma unroll
        for (int bb = 0; bb < 4; ++bb)
#pragma unroll
            for (int cc = 0; cc < 4; ++cc) acc[a][bb][cc] = 0.f;

    gemm_main(smb, acc,
              g_athi + ((size_t)b * CT + m0) * CN,
              g_atlo + ((size_t)b * CT + m0) * CN, CN,
              g_AOThi + ((size_t)b * CAD + n0) * CN,
              g_AOTlo + ((size_t)b * CAD + n0) * CN, CN, CN);

    const int lane = threadIdx.x & 31, w = threadIdx.x >> 5;
    const int mw = (w & 1) * 64, nw = (w >> 1) * 32;
    const int qr = lane >> 2, qc = (lane & 3) * 2;
#pragma unroll
    for (int mi = 0; mi < 4; ++mi)
#pragma unroll
        for (int nj = 0; nj < 4; ++nj) {
            size_t r0 = (size_t)b * CT + m0 + mw + mi * 16 + qr;
            int gc = n0 + nw + nj * 8 + qc;
            *(float2*)(OUT + r0 * CAD + gc) =
                make_float2(acc[mi][nj][0], acc[mi][nj][1]);
            *(float2*)(OUT + (r0 + 8) * CAD + gc) =
                make_float2(acc[mi][nj][2], acc[mi][nj][3]);
        }
}

// ---------------------------------------------------------------------------
extern "C" void kernel_launch(void* const* d_in, const int* in_sizes, int n_in,
                              void* d_out, int out_size) {
    const float* inputs = (const float*)d_in[0];
    const float* ao     = (const float*)d_in[1];
    const void*  mask   = d_in[2];
    const float* W      = (const float*)d_in[3];
    const float* a_w    = (const float*)d_in[4];
    const float* b_w    = (const float*)d_in[5];
    const float* bias   = (const float*)d_in[6];
    float* out = (float*)d_out;

    static int attr_done = 0;
    if (!attr_done) {
        cudaFuncSetAttribute(g1_mma, cudaFuncAttributeMaxDynamicSharedMemorySize, SMEM_G13);
        cudaFuncSetAttribute(g2_mma, cudaFuncAttributeMaxDynamicSharedMemorySize, SMEM_G2);
        cudaFuncSetAttribute(g3_mma, cudaFuncAttributeMaxDynamicSharedMemorySize, SMEM_G13);
        attr_done = 1;
    }

    mask_classify<<<1, 256>>>((const unsigned char*)mask);
    mask_norm<<<(CB * CN + 255) / 256, 256>>>(mask);

    int nwarps = CB * CN + CB * CT;
    lin_split<<<(nwarps * 32 + 255) / 256, 256>>>(inputs, ao, a_w, b_w);
    wt_split<<<dim3(16, 16), dim3(32, 8)>>>(W);
    aot_split<<<dim3(16, 4, CB), dim3(32, 8)>>>(ao);

    g1_mma<<<dim3(4, 128), 256, SMEM_G13>>>();
    g2_mma<<<dim3(2, CB), 256, SMEM_G2>>>(bias);
    g3_mma<<<dim3(4, 2, CB), 256, SMEM_G13>>>(out);
}

// round 4
// speedup vs baseline: 2.2011x; 1.0388x over previous
#include <cuda_runtime.h>
#include <cuda_bf16.h>
#include <cstdint>

// ---------------------------------------------------------------------------
// GeneralizedBilinearAttention via mma.sync bf16 (base sm_103 ISA).
//   G1: aM   = AO_flat(16384x512) @ WT(512x512)   (TN, k-major both sides)
//   G2: sim  = IN(256x512) @ aM_b(128x512)^T  + fused tanh/masked-softmax
//   G3: out  = attn(256x128) @ AOT_b(512x128)^T
// fp32 operands split to bf16 hi/lo; 3 MMA products (hh + hl + lh), fp32 acc.
// Mainloop: K32 chunks, 3-stage cp.async pipeline, 2 CTAs/SM.
// ---------------------------------------------------------------------------

#define CB 128
#define CT 256
#define CN 128
#define CAD 512
#define CVD 512

// ---- scratch ----------------------------------------------------------------
__device__ __align__(16) unsigned short g_AOhi[CB * CN * CAD];
__device__ __align__(16) unsigned short g_AOlo[CB * CN * CAD];
__device__ __align__(16) unsigned short g_INhi[CB * CT * CVD];
__device__ __align__(16) unsigned short g_INlo[CB * CT * CVD];
__device__ __align__(16) unsigned short g_WThi[CVD * CAD];
__device__ __align__(16) unsigned short g_WTlo[CVD * CAD];
__device__ __align__(16) unsigned short g_aMhi[CB * CN * CVD];
__device__ __align__(16) unsigned short g_aMlo[CB * CN * CVD];
__device__ __align__(16) unsigned short g_AOThi[CB * CAD * CN];
__device__ __align__(16) unsigned short g_AOTlo[CB * CAD * CN];
__device__ __align__(16) unsigned short g_athi[CB * CT * CN];
__device__ __align__(16) unsigned short g_atlo[CB * CT * CN];
__device__ __align__(16) float g_lina[CB * CN];
__device__ __align__(16) float g_linb[CB * CT];
__device__ __align__(16) float g_maskf[CB * CN];
__device__ int g_mode[1];

// ---- smem layout: 3-stage, 128x32 bf16 tiles (64B rows) ---------------------
#define TILEB 8192                 // 128 rows * 64 bytes
#define SM_AHI 0
#define SM_ALO TILEB
#define SM_BHI (2 * TILEB)
#define SM_BLO (3 * TILEB)
#define STAGE  (4 * TILEB)         // 32768
#define NST 3
#define SMEM_MAIN (NST * STAGE)    // 98304
#define SM_LIN SMEM_MAIN
#define SM_MSK (SM_LIN + 512)
#define SM_LNB (SM_MSK + 512)
#define SMEM_G13 SMEM_MAIN
#define SMEM_G2  (SM_LNB + 512)

// ---- helpers ----------------------------------------------------------------
__device__ __forceinline__ uint32_t smem_u32(const void* p) {
    return (uint32_t)__cvta_generic_to_shared(p);
}
// 64B-row swizzle: granule = 4*row + (c16 ^ ((row>>1)&3)) — conflict-free for
// ldmatrix 8-lane groups (8 distinct granules mod 8) and cp.async stores.
__device__ __forceinline__ uint32_t swz(int row, int c16) {
    return (uint32_t)(row * 64 + ((c16 ^ ((row >> 1) & 3)) << 4));
}
__device__ __forceinline__ void ldsm4(uint32_t* r, uint32_t addr) {
    asm volatile("ldmatrix.sync.aligned.m8n8.x4.shared.b16 {%0,%1,%2,%3}, [%4];"
                 : "=r"(r[0]), "=r"(r[1]), "=r"(r[2]), "=r"(r[3]) : "r"(addr));
}
__device__ __forceinline__ void mma_bf16(float* c, const uint32_t* a,
                                         uint32_t b0, uint32_t b1) {
    asm volatile("mma.sync.aligned.m16n8k16.row.col.f32.bf16.bf16.f32 "
                 "{%0,%1,%2,%3}, {%4,%5,%6,%7}, {%8,%9}, {%0,%1,%2,%3};"
                 : "+f"(c[0]), "+f"(c[1]), "+f"(c[2]), "+f"(c[3])
                 : "r"(a[0]), "r"(a[1]), "r"(a[2]), "r"(a[3]), "r"(b0), "r"(b1));
}
// cp.async a 128x32-bf16 tile (k-major rows), swizzled dest. 256 thr, 2 ea.
__device__ __forceinline__ void cp_tile(uint32_t dst, const unsigned short* src,
                                        int ld, int k0, int tid) {
#pragma unroll
    for (int i = 0; i < 2; ++i) {
        int u = i * 256 + tid;          // 0..511
        int row = u >> 2, c = u & 3;
        const void* g = src + (size_t)row * ld + k0 + c * 8;
        asm volatile("cp.async.cg.shared.global [%0], [%1], 16;"
                     :: "r"(dst + swz(row, c)), "l"(g) : "memory");
    }
}
__device__ __forceinline__ void split2u(float x, float y, uint32_t& h, uint32_t& l) {
    __nv_bfloat16 xh = __float2bfloat16(x), yh = __float2bfloat16(y);
    __nv_bfloat16 xl = __float2bfloat16(x - __bfloat162float(xh));
    __nv_bfloat16 yl = __float2bfloat16(y - __bfloat162float(yh));
    h = ((uint32_t)__bfloat16_as_ushort(yh) << 16) | __bfloat16_as_ushort(xh);
    l = ((uint32_t)__bfloat16_as_ushort(yl) << 16) | __bfloat16_as_ushort(xl);
}

// ---- compute one K32 chunk from stage st ------------------------------------
__device__ __forceinline__ void compute_chunk(uint32_t st, float acc[4][4][4],
                                              const int* rowm, const int* rowb,
                                              int cgrp) {
#pragma unroll
    for (int ks = 0; ks < 2; ++ks) {
        const int cu = 2 * ks + cgrp;
        uint32_t bh[2][4], bl[2][4];
#pragma unroll
        for (int j = 0; j < 2; ++j) {
            ldsm4(bh[j], st + SM_BHI + swz(rowb[j], cu));
            ldsm4(bl[j], st + SM_BLO + swz(rowb[j], cu));
        }
#pragma unroll
        for (int mi = 0; mi < 4; ++mi) {
            uint32_t ah[4], al[4];
            ldsm4(ah, st + SM_AHI + swz(rowm[mi], cu));
            ldsm4(al, st + SM_ALO + swz(rowm[mi], cu));
#pragma unroll
            for (int nj = 0; nj < 4; ++nj) {
                const int j = nj >> 1, o = nj & 1;
                mma_bf16(acc[mi][nj], ah, bh[j][o], bh[j][o + 2]);
                mma_bf16(acc[mi][nj], ah, bl[j][o], bl[j][o + 2]);
                mma_bf16(acc[mi][nj], al, bh[j][o], bh[j][o + 2]);
            }
        }
    }
}

// ---- 3-stage pipelined mainloop: C(128x128) += (Ah+Al)(Bh+Bl)^T over K ------
__device__ __forceinline__ void gemm_main(uint32_t smb, float acc[4][4][4],
    const unsigned short* Ah, const unsigned short* Al, int lda,
    const unsigned short* Bh, const unsigned short* Bl, int ldb, int K) {
    const int tid = threadIdx.x, lane = tid & 31, w = tid >> 5;
    const int mw = (w & 1) * 64, nw = (w >> 1) * 32;
    const int grp = lane >> 3, rin = lane & 7;
    int rowm[4], rowb[2];
#pragma unroll
    for (int mi = 0; mi < 4; ++mi) rowm[mi] = mw + mi * 16 + rin + ((grp & 1) << 3);
#pragma unroll
    for (int j = 0; j < 2; ++j)    rowb[j] = nw + j * 16 + rin + ((grp & 1) << 3);
    const int cgrp = grp >> 1;
    const int nch = K >> 5;

#pragma unroll
    for (int s = 0; s < 2; ++s) {
        const uint32_t st = smb + (uint32_t)s * STAGE;
        const int k0 = s << 5;
        cp_tile(st + SM_AHI, Ah, lda, k0, tid);
        cp_tile(st + SM_ALO, Al, lda, k0, tid);
        cp_tile(st + SM_BHI, Bh, ldb, k0, tid);
        cp_tile(st + SM_BLO, Bl, ldb, k0, tid);
        asm volatile("cp.async.commit_group;" ::: "memory");
    }

    uint32_t stg = 0;   // stage index of chunk c (c % 3)
    for (int c = 0; c < nch; ++c) {
        if (c == nch - 1) asm volatile("cp.async.wait_group 0;" ::: "memory");
        else              asm volatile("cp.async.wait_group 1;" ::: "memory");
        __syncthreads();
        if (c + 2 < nch) {
            uint32_t s2 = stg + 2; if (s2 >= NST) s2 -= NST;
            const uint32_t st2 = smb + s2 * STAGE;
            const int k0 = (c + 2) << 5;
            cp_tile(st2 + SM_AHI, Ah, lda, k0, tid);
            cp_tile(st2 + SM_ALO, Al, lda, k0, tid);
            cp_tile(st2 + SM_BHI, Bh, ldb, k0, tid);
            cp_tile(st2 + SM_BLO, Bl, ldb, k0, tid);
            asm volatile("cp.async.commit_group;" ::: "memory");
        }
        compute_chunk(smb + stg * STAGE, acc, rowm, rowb, cgrp);
        if (++stg == NST) stg = 0;
    }
}

// ---------------------------------------------------------------------------
// Preprocessing
// ---------------------------------------------------------------------------
__global__ void mask_classify(const unsigned char* __restrict__ m) {
    __shared__ int s_notbin, s_odd;
    if (threadIdx.x == 0) { s_notbin = 0; s_odd = 0; }
    __syncthreads();
    int notbin = 0, odd = 0;
    for (int i = threadIdx.x; i < CB * CN; i += blockDim.x) {
        unsigned char v = m[i];
        if (v > 1) notbin = 1;
        if ((i & 3) && v == 1) odd = 1;
    }
    if (notbin) atomicOr(&s_notbin, 1);
    if (odd)    atomicOr(&s_odd, 1);
    __syncthreads();
    if (threadIdx.x == 0) g_mode[0] = s_notbin ? 2 : (s_odd ? 0 : 1);
}
__global__ void mask_norm(const void* __restrict__ m) {
    int i = blockIdx.x * blockDim.x + threadIdx.x;
    if (i >= CB * CN) return;
    int md = g_mode[0];
    float v;
    if (md == 0)      v = (((const unsigned char*)m)[i] != 0) ? 1.f : 0.f;
    else if (md == 1) v = (((const int*)m)[i] != 0) ? 1.f : 0.f;
    else              v = (((const float*)m)[i] != 0.f) ? 1.f : 0.f;
    g_maskf[i] = v;
}

// One warp per 512-row: lin dot product + bf16 hi/lo split write.
__global__ void __launch_bounds__(256) lin_split(const float* __restrict__ IN,
                                                 const float* __restrict__ AO,
                                                 const float* __restrict__ a_w,
                                                 const float* __restrict__ b_w) {
    int w = (blockIdx.x * blockDim.x + threadIdx.x) >> 5;
    int lane = threadIdx.x & 31;
    const int nAO = CB * CN;
    if (w >= nAO + CB * CT) return;
    const float* row; const float* wv; float* outd; int idx;
    uint32_t *dhi, *dlo;
    if (w < nAO) {
        idx = w; row = AO + (size_t)w * CAD; wv = a_w; outd = g_lina;
        dhi = (uint32_t*)g_AOhi + (size_t)w * 256;
        dlo = (uint32_t*)g_AOlo + (size_t)w * 256;
    } else {
        idx = w - nAO; row = IN + (size_t)idx * CVD; wv = b_w; outd = g_linb;
        dhi = (uint32_t*)g_INhi + (size_t)idx * 256;
        dlo = (uint32_t*)g_INlo + (size_t)idx * 256;
    }
    float s = 0.f;
#pragma unroll
    for (int k = 0; k < 512; k += 128) {
        int e = k + lane * 4;
        float4 x = *(const float4*)(row + e);
        float4 y = *(const float4*)(wv + e);
        s += x.x * y.x + x.y * y.y + x.z * y.z + x.w * y.w;
        uint32_t h0, l0, h1, l1;
        split2u(x.x, x.y, h0, l0);
        split2u(x.z, x.w, h1, l1);
        dhi[e >> 1] = h0; dhi[(e >> 1) + 1] = h1;
        dlo[e >> 1] = l0; dlo[(e >> 1) + 1] = l1;
    }
#pragma unroll
    for (int o = 16; o; o >>= 1) s += __shfl_xor_sync(0xffffffffu, s, o);
    if (lane == 0) outd[idx] = s;
}

// W(512x512) -> WT hi/lo
__global__ void wt_split(const float* __restrict__ W) {
    __shared__ float t[32][33];
    int tx = threadIdx.x, ty = threadIdx.y;
    int a0 = blockIdx.y * 32, v0 = blockIdx.x * 32;
    for (int i = ty; i < 32; i += 8)
        t[i][tx] = W[(size_t)(a0 + i) * CVD + v0 + tx];
    __syncthreads();
    for (int i = ty; i < 32; i += 8) {
        float x = t[tx][i];
        __nv_bfloat16 h = __float2bfloat16(x);
        __nv_bfloat16 l = __float2bfloat16(x - __bfloat162float(h));
        size_t o = (size_t)(v0 + i) * CAD + a0 + tx;
        g_WThi[o] = __bfloat16_as_ushort(h);
        g_WTlo[o] = __bfloat16_as_ushort(l);
    }
}

// AO per batch (128n x 512v) -> AOT (512v x 128n) hi/lo
__global__ void aot_split(const float* __restrict__ AO) {
    __shared__ float t[32][33];
    int tx = threadIdx.x, ty = threadIdx.y;
    int b = blockIdx.z;
    int v0 = blockIdx.x * 32, n0 = blockIdx.y * 32;
    const float* src = AO + (size_t)b * CN * CAD;
    for (int i = ty; i < 32; i += 8)
        t[i][tx] = src[(size_t)(n0 + i) * CAD + v0 + tx];
    __syncthreads();
    unsigned short* dh = g_AOThi + (size_t)b * CAD * CN;
    unsigned short* dl = g_AOTlo + (size_t)b * CAD * CN;
    for (int i = ty; i < 32; i += 8) {
        float x = t[tx][i];
        __nv_bfloat16 h = __float2bfloat16(x);
        __nv_bfloat16 l = __float2bfloat16(x - __bfloat162float(h));
        size_t o = (size_t)(v0 + i) * CN + n0 + tx;
        dh[o] = __bfloat16_as_ushort(h);
        dl[o] = __bfloat16_as_ushort(l);
    }
}

// ---------------------------------------------------------------------------
// G1: aM = AO_flat @ WT^T -> aM hi/lo.  grid (4 Ntiles, 128 Mtiles)
// ---------------------------------------------------------------------------
__global__ void __launch_bounds__(256, 2) g1_mma() {
    extern __shared__ char sm[];
    const uint32_t smb = smem_u32(sm);
    const int n0 = blockIdx.x * 128;
    const size_t m0 = (size_t)blockIdx.y * 128;
    float acc[4][4][4];
#pragma unroll
    for (int a = 0; a < 4; ++a)
#pragma unroll
        for (int b = 0; b < 4; ++b)
#pragma unroll
            for (int cc = 0; cc < 4; ++cc) acc[a][b][cc] = 0.f;

    gemm_main(smb, acc, g_AOhi + m0 * CAD, g_AOlo + m0 * CAD, CAD,
              g_WThi + (size_t)n0 * CAD, g_WTlo + (size_t)n0 * CAD, CAD, CAD);

    const int lane = threadIdx.x & 31, w = threadIdx.x >> 5;
    const int mw = (w & 1) * 64, nw = (w >> 1) * 32;
    const int qr = lane >> 2, qc = (lane & 3) * 2;
    uint32_t* ghi = (uint32_t*)g_aMhi;
    uint32_t* glo = (uint32_t*)g_aMlo;
#pragma unroll
    for (int mi = 0; mi < 4; ++mi)
#pragma unroll
        for (int nj = 0; nj < 4; ++nj) {
            size_t r0 = m0 + mw + mi * 16 + qr;
            size_t cp = (size_t)(n0 + nw + nj * 8 + qc) >> 1;
            uint32_t h, l;
            split2u(acc[mi][nj][0], acc[mi][nj][1], h, l);
            ghi[r0 * (CVD >> 1) + cp] = h; glo[r0 * (CVD >> 1) + cp] = l;
            split2u(acc[mi][nj][2], acc[mi][nj][3], h, l);
            ghi[(r0 + 8) * (CVD >> 1) + cp] = h; glo[(r0 + 8) * (CVD >> 1) + cp] = l;
        }
}

// ---------------------------------------------------------------------------
// G2: sim = IN_tile @ aM_b^T + fused tanh/masked-softmax -> attn hi/lo.
//     grid (2 Mtiles, B)
// ---------------------------------------------------------------------------
__global__ void __launch_bounds__(256, 2) g2_mma(const float* __restrict__ biasp) {
    extern __shared__ char sm[];
    const uint32_t smb = smem_u32(sm);
    const int tid = threadIdx.x;
    const int b = blockIdx.y;
    const int m0 = blockIdx.x * 128;
    float* sl  = (float*)(sm + SM_LIN);
    float* sk  = (float*)(sm + SM_MSK);
    float* slb = (float*)(sm + SM_LNB);
    if (tid < 128) {
        sl[tid]  = g_lina[b * CN + tid];
        sk[tid]  = g_maskf[b * CN + tid];
        slb[tid] = g_linb[b * CT + m0 + tid];
    }
    float acc[4][4][4];
#pragma unroll
    for (int a = 0; a < 4; ++a)
#pragma unroll
        for (int bb = 0; bb < 4; ++bb)
#pragma unroll
            for (int cc = 0; cc < 4; ++cc) acc[a][bb][cc] = 0.f;

    gemm_main(smb, acc,
              g_INhi + ((size_t)b * CT + m0) * CVD,
              g_INlo + ((size_t)b * CT + m0) * CVD, CVD,
              g_aMhi + (size_t)b * CN * CVD,
              g_aMlo + (size_t)b * CN * CVD, CVD, CVD);
    __syncthreads();   // all warps done with tile smem before ssim reuse

    // stage exp(tanh(.)) * mask into smem, stride 129 (conflict-free sums)
    const int lane = tid & 31, w = tid >> 5;
    const int mw = (w & 1) * 64, nw = (w >> 1) * 32;
    const int qr = lane >> 2, qc = (lane & 3) * 2;
    const float bs = biasp[0];
    float* ssim = (float*)sm;                      // 128 x 129 floats (66KB)
#pragma unroll
    for (int mi = 0; mi < 4; ++mi)
#pragma unroll
        for (int nj = 0; nj < 4; ++nj) {
            int c0 = nw + nj * 8 + qc;
            float sla = sl[c0], slA = sl[c0 + 1];
            float mk0 = sk[c0], mk1 = sk[c0 + 1];
#pragma unroll
            for (int p = 0; p < 2; ++p) {
                int r = mw + mi * 16 + qr + p * 8;
                float lb = slb[r] + bs;
                float e0 = mk0 * __expf(tanhf(acc[mi][nj][2 * p] + sla + lb));
                float e1 = mk1 * __expf(tanhf(acc[mi][nj][2 * p + 1] + slA + lb));
                ssim[r * 129 + c0] = e0;
                ssim[r * 129 + c0 + 1] = e1;
            }
        }
    __syncthreads();
    {
        const int r = tid >> 1, half = tid & 1;    // 2 threads per row
        const float* rowp = ssim + r * 129;
        float s = 0.f;
#pragma unroll
        for (int n = 0; n < 64; ++n) s += rowp[half * 64 + n];
        s += __shfl_xor_sync(0xffffffffu, s, 1);
        const float inv = 1.0f / (s + 1e-30f);
        const size_t t = (size_t)b * CT + m0 + r;
        uint32_t* ohi = (uint32_t*)g_athi + t * 64;
        uint32_t* olo = (uint32_t*)g_atlo + t * 64;
#pragma unroll
        for (int jj = 0; jj < 32; ++jj) {
            int j = half * 32 + jj;
            uint32_t h, l;
            split2u(rowp[2 * j] * inv, rowp[2 * j + 1] * inv, h, l);
            ohi[j] = h; olo[j] = l;
        }
    }
}

// ---------------------------------------------------------------------------
// G3: out = attn_tile @ AOT_b^T (fp32 out).  grid (4 Ntiles, 2 Mtiles, B)
// ---------------------------------------------------------------------------
__global__ void __launch_bounds__(256, 2) g3_mma(float* __restrict__ OUT) {
    extern __shared__ char sm[];
    const uint32_t smb = smem_u32(sm);
    const int b = blockIdx.z;
    const int m0 = blockIdx.y * 128;
    const int n0 = blockIdx.x * 128;
    float acc[4][4][4];
#pragma unroll
    for (int a = 0; a < 4; ++a)
#pragma unroll
        for (int bb = 0; bb < 4; ++bb)
#pragma unroll
            for (int cc = 0; cc < 4; ++cc) acc[a][bb][cc] = 0.f;

    gemm_main(smb, acc,
              g_athi + ((size_t)b * CT + m0) * CN,
              g_atlo + ((size_t)b * CT + m0) * CN, CN,
              g_AOThi + ((size_t)b * CAD + n0) * CN,
              g_AOTlo + ((size_t)b * CAD + n0) * CN, CN, CN);

    const int lane = threadIdx.x & 31, w = threadIdx.x >> 5;
    const int mw = (w & 1) * 64, nw = (w >> 1) * 32;
    const int qr = lane >> 2, qc = (lane & 3) * 2;
#pragma unroll
    for (int mi = 0; mi < 4; ++mi)
#pragma unroll
        for (int nj = 0; nj < 4; ++nj) {
            size_t r0 = (size_t)b * CT + m0 + mw + mi * 16 + qr;
            int gc = n0 + nw + nj * 8 + qc;
            *(float2*)(OUT + r0 * CAD + gc) =
                make_float2(acc[mi][nj][0], acc[mi][nj][1]);
            *(float2*)(OUT + (r0 + 8) * CAD + gc) =
                make_float2(acc[mi][nj][2], acc[mi][nj][3]);
        }
}

// ---------------------------------------------------------------------------
extern "C" void kernel_launch(void* const* d_in, const int* in_sizes, int n_in,
                              void* d_out, int out_size) {
    const float* inputs = (const float*)d_in[0];
    const float* ao     = (const float*)d_in[1];
    const void*  mask   = d_in[2];
    const float* W      = (const float*)d_in[3];
    const float* a_w    = (const float*)d_in[4];
    const float* b_w    = (const float*)d_in[5];
    const float* bias   = (const float*)d_in[6];
    float* out = (float*)d_out;

    cudaFuncSetAttribute(g1_mma, cudaFuncAttributeMaxDynamicSharedMemorySize, SMEM_G13);
    cudaFuncSetAttribute(g2_mma, cudaFuncAttributeMaxDynamicSharedMemorySize, SMEM_G2);
    cudaFuncSetAttribute(g3_mma, cudaFuncAttributeMaxDynamicSharedMemorySize, SMEM_G13);

    mask_classify<<<1, 256>>>((const unsigned char*)mask);
    mask_norm<<<(CB * CN + 255) / 256, 256>>>(mask);

    int nwarps = CB * CN + CB * CT;
    lin_split<<<(nwarps * 32 + 255) / 256, 256>>>(inputs, ao, a_w, b_w);
    wt_split<<<dim3(16, 16), dim3(32, 8)>>>(W);
    aot_split<<<dim3(16, 4, CB), dim3(32, 8)>>>(ao);

    g1_mma<<<dim3(4, 128), 256, SMEM_G13>>>();
    g2_mma<<<dim3(2, CB), 256, SMEM_G2>>>(bias);
    g3_mma<<<dim3(4, 2, CB), 256, SMEM_G13>>>(out);
}

// round 5
// speedup vs baseline: 2.4485x; 1.1124x over previous
#include <cuda_runtime.h>
#include <cuda_bf16.h>
#include <cstdint>

// ---------------------------------------------------------------------------
// GeneralizedBilinearAttention via mma.sync bf16 (base sm_103 ISA).
//   G1: aM   = AO_flat(16384x512) @ WT(512x512)   (TN, k-major both sides)
//   G2: sim  = IN(256x512) @ aM_b(128x512)^T  + fused tanh/masked-softmax
//   G3: out  = attn(256x128) @ AO_b(128x512)  (B via ldmatrix.trans)
// fp32 operands split to bf16 hi/lo; 3 MMA products (hh + hl + lh), fp32 acc.
// Mainloop: K32 chunks, 3-stage cp.async pipeline.
// ---------------------------------------------------------------------------

#define CB 128
#define CT 256
#define CN 128
#define CAD 512
#define CVD 512

// ---- scratch ----------------------------------------------------------------
__device__ __align__(16) unsigned short g_AOhi[CB * CN * CAD];
__device__ __align__(16) unsigned short g_AOlo[CB * CN * CAD];
__device__ __align__(16) unsigned short g_INhi[CB * CT * CVD];
__device__ __align__(16) unsigned short g_INlo[CB * CT * CVD];
__device__ __align__(16) unsigned short g_WThi[CVD * CAD];
__device__ __align__(16) unsigned short g_WTlo[CVD * CAD];
__device__ __align__(16) unsigned short g_aMhi[CB * CN * CVD];
__device__ __align__(16) unsigned short g_aMlo[CB * CN * CVD];
__device__ __align__(16) unsigned short g_athi[CB * CT * CN];
__device__ __align__(16) unsigned short g_atlo[CB * CT * CN];
__device__ __align__(16) float g_lina[CB * CN];
__device__ __align__(16) float g_linb[CB * CT];
__device__ __align__(16) float g_maskf[CB * CN];

// ---- smem layout: 3-stage, 8KB tiles ----------------------------------------
#define TILEB 8192
#define SM_AHI 0
#define SM_ALO TILEB
#define SM_BHI (2 * TILEB)
#define SM_BLO (3 * TILEB)
#define STAGE  (4 * TILEB)         // 32768
#define NST 3
#define SMEM_MAIN (NST * STAGE)    // 98304
#define SM_LIN SMEM_MAIN
#define SM_MSK (SM_LIN + 512)
#define SM_LNB (SM_MSK + 512)
#define SMEM_G13 SMEM_MAIN
#define SMEM_G2  (SM_LNB + 512)

// ---- helpers ----------------------------------------------------------------
__device__ __forceinline__ uint32_t smem_u32(const void* p) {
    return (uint32_t)__cvta_generic_to_shared(p);
}
// 64B-row swizzle (128 rows x 32 bf16): conflict-free for ldsm + cp.async.
__device__ __forceinline__ uint32_t swz(int row, int c16) {
    return (uint32_t)(row * 64 + ((c16 ^ ((row >> 1) & 3)) << 4));
}
// 256B-row swizzle (32 rows x 128 bf16) for the G3 trans-B tile.
__device__ __forceinline__ uint32_t swzbt(int row, int c16) {
    return (uint32_t)(row * 256 + ((c16 ^ (row & 7)) << 4));
}
__device__ __forceinline__ void ldsm4(uint32_t* r, uint32_t addr) {
    asm volatile("ldmatrix.sync.aligned.m8n8.x4.shared.b16 {%0,%1,%2,%3}, [%4];"
                 : "=r"(r[0]), "=r"(r[1]), "=r"(r[2]), "=r"(r[3]) : "r"(addr));
}
__device__ __forceinline__ void ldsm4t(uint32_t* r, uint32_t addr) {
    asm volatile("ldmatrix.sync.aligned.m8n8.x4.trans.shared.b16 {%0,%1,%2,%3}, [%4];"
                 : "=r"(r[0]), "=r"(r[1]), "=r"(r[2]), "=r"(r[3]) : "r"(addr));
}
__device__ __forceinline__ void mma_bf16(float* c, const uint32_t* a,
                                         uint32_t b0, uint32_t b1) {
    asm volatile("mma.sync.aligned.m16n8k16.row.col.f32.bf16.bf16.f32 "
                 "{%0,%1,%2,%3}, {%4,%5,%6,%7}, {%8,%9}, {%0,%1,%2,%3};"
                 : "+f"(c[0]), "+f"(c[1]), "+f"(c[2]), "+f"(c[3])
                 : "r"(a[0]), "r"(a[1]), "r"(a[2]), "r"(a[3]), "r"(b0), "r"(b1));
}
// cp.async a 128x32-bf16 k-major tile, swizzled. 256 thr, 2 ea.
__device__ __forceinline__ void cp_tile(uint32_t dst, const unsigned short* src,
                                        int ld, int k0, int tid) {
#pragma unroll
    for (int i = 0; i < 2; ++i) {
        int u = i * 256 + tid;
        int row = u >> 2, c = u & 3;
        const void* g = src + (size_t)row * ld + k0 + c * 8;
        asm volatile("cp.async.cg.shared.global [%0], [%1], 16;"
                     :: "r"(dst + swz(row, c)), "l"(g) : "memory");
    }
}
// cp.async a 32x128-bf16 tile (rows = k(n-dim), cols = v), swizzled for trans.
__device__ __forceinline__ void cp_tile_bt(uint32_t dst, const unsigned short* src,
                                           int ld, int k0, int v0, int tid) {
#pragma unroll
    for (int i = 0; i < 2; ++i) {
        int u = i * 256 + tid;
        int row = u >> 4, c = u & 15;
        const void* g = src + (size_t)(k0 + row) * ld + v0 + c * 8;
        asm volatile("cp.async.cg.shared.global [%0], [%1], 16;"
                     :: "r"(dst + swzbt(row, c)), "l"(g) : "memory");
    }
}
__device__ __forceinline__ void split2u(float x, float y, uint32_t& h, uint32_t& l) {
    __nv_bfloat16 xh = __float2bfloat16(x), yh = __float2bfloat16(y);
    __nv_bfloat16 xl = __float2bfloat16(x - __bfloat162float(xh));
    __nv_bfloat16 yl = __float2bfloat16(y - __bfloat162float(yh));
    h = ((uint32_t)__bfloat16_as_ushort(yh) << 16) | __bfloat16_as_ushort(xh);
    l = ((uint32_t)__bfloat16_as_ushort(yl) << 16) | __bfloat16_as_ushort(xl);
}

// ---- compute one K32 chunk (standard TN, B k-major) --------------------------
__device__ __forceinline__ void compute_chunk(uint32_t st, float acc[4][4][4],
                                              const int* rowm, const int* rowb,
                                              int cgrp) {
#pragma unroll
    for (int ks = 0; ks < 2; ++ks) {
        const int cu = 2 * ks + cgrp;
        uint32_t bh[2][4], bl[2][4];
#pragma unroll
        for (int j = 0; j < 2; ++j) {
            ldsm4(bh[j], st + SM_BHI + swz(rowb[j], cu));
            ldsm4(bl[j], st + SM_BLO + swz(rowb[j], cu));
        }
#pragma unroll
        for (int mi = 0; mi < 4; ++mi) {
            uint32_t ah[4], al[4];
            ldsm4(ah, st + SM_AHI + swz(rowm[mi], cu));
            ldsm4(al, st + SM_ALO + swz(rowm[mi], cu));
#pragma unroll
            for (int nj = 0; nj < 4; ++nj) {
                const int j = nj >> 1, o = nj & 1;
                mma_bf16(acc[mi][nj], ah, bh[j][o], bh[j][o + 2]);
                mma_bf16(acc[mi][nj], ah, bl[j][o], bl[j][o + 2]);
                mma_bf16(acc[mi][nj], al, bh[j][o], bh[j][o + 2]);
            }
        }
    }
}

// ---- compute one K32 chunk (B loaded transposed via ldsm4t) ------------------
// B tile stored [k-row 0..31][v 0..127]; per .x4: r0=(klo,vlo) r1=(klo,vhi)
// r2=(khi,vlo) r3=(khi,vhi) -> identical b[o]/b[o+2] usage.
__device__ __forceinline__ void compute_chunk_bt(uint32_t st, float acc[4][4][4],
                                                 const int* rowm, int nw,
                                                 int rin, int grp, int cgrp) {
#pragma unroll
    for (int ks = 0; ks < 2; ++ks) {
        const int cu = 2 * ks + cgrp;
        const int browk = 16 * ks + rin + ((grp >> 1) << 3);
        uint32_t bh[2][4], bl[2][4];
#pragma unroll
        for (int j = 0; j < 2; ++j) {
            const int bc = (nw >> 3) + 2 * j + (grp & 1);
            ldsm4t(bh[j], st + SM_BHI + swzbt(browk, bc));
            ldsm4t(bl[j], st + SM_BLO + swzbt(browk, bc));
        }
#pragma unroll
        for (int mi = 0; mi < 4; ++mi) {
            uint32_t ah[4], al[4];
            ldsm4(ah, st + SM_AHI + swz(rowm[mi], cu));
            ldsm4(al, st + SM_ALO + swz(rowm[mi], cu));
#pragma unroll
            for (int nj = 0; nj < 4; ++nj) {
                const int j = nj >> 1, o = nj & 1;
                mma_bf16(acc[mi][nj], ah, bh[j][o], bh[j][o + 2]);
                mma_bf16(acc[mi][nj], ah, bl[j][o], bl[j][o + 2]);
                mma_bf16(acc[mi][nj], al, bh[j][o], bh[j][o + 2]);
            }
        }
    }
}

// ---- 3-stage pipelined mainloop (standard) -----------------------------------
__device__ __forceinline__ void gemm_main(uint32_t smb, float acc[4][4][4],
    const unsigned short* Ah, const unsigned short* Al, int lda,
    const unsigned short* Bh, const unsigned short* Bl, int ldb, int K) {
    const int tid = threadIdx.x, lane = tid & 31, w = tid >> 5;
    const int mw = (w & 1) * 64, nw = (w >> 1) * 32;
    const int grp = lane >> 3, rin = lane & 7;
    int rowm[4], rowb[2];
#pragma unroll
    for (int mi = 0; mi < 4; ++mi) rowm[mi] = mw + mi * 16 + rin + ((grp & 1) << 3);
#pragma unroll
    for (int j = 0; j < 2; ++j)    rowb[j] = nw + j * 16 + rin + ((grp & 1) << 3);
    const int cgrp = grp >> 1;
    const int nch = K >> 5;

#pragma unroll
    for (int s = 0; s < 2; ++s) {
        const uint32_t st = smb + (uint32_t)s * STAGE;
        const int k0 = s << 5;
        cp_tile(st + SM_AHI, Ah, lda, k0, tid);
        cp_tile(st + SM_ALO, Al, lda, k0, tid);
        cp_tile(st + SM_BHI, Bh, ldb, k0, tid);
        cp_tile(st + SM_BLO, Bl, ldb, k0, tid);
        asm volatile("cp.async.commit_group;" ::: "memory");
    }
    uint32_t stg = 0;
    for (int c = 0; c < nch; ++c) {
        if (c == nch - 1) asm volatile("cp.async.wait_group 0;" ::: "memory");
        else              asm volatile("cp.async.wait_group 1;" ::: "memory");
        __syncthreads();
        if (c + 2 < nch) {
            uint32_t s2 = stg + 2; if (s2 >= NST) s2 -= NST;
            const uint32_t st2 = smb + s2 * STAGE;
            const int k0 = (c + 2) << 5;
            cp_tile(st2 + SM_AHI, Ah, lda, k0, tid);
            cp_tile(st2 + SM_ALO, Al, lda, k0, tid);
            cp_tile(st2 + SM_BHI, Bh, ldb, k0, tid);
            cp_tile(st2 + SM_BLO, Bl, ldb, k0, tid);
            asm volatile("cp.async.commit_group;" ::: "memory");
        }
        compute_chunk(smb + stg * STAGE, acc, rowm, rowb, cgrp);
        if (++stg == NST) stg = 0;
    }
}

// ---- 3-stage pipelined mainloop for G3 (B trans-loaded from AO) --------------
__device__ __forceinline__ void gemm_main_bt(uint32_t smb, float acc[4][4][4],
    const unsigned short* Ah, const unsigned short* Al, int lda,
    const unsigned short* Bh, const unsigned short* Bl, int ldb, int v0, int K) {
    const int tid = threadIdx.x, lane = tid & 31, w = tid >> 5;
    const int mw = (w & 1) * 64, nw = (w >> 1) * 32;
    const int grp = lane >> 3, rin = lane & 7;
    int rowm[4];
#pragma unroll
    for (int mi = 0; mi < 4; ++mi) rowm[mi] = mw + mi * 16 + rin + ((grp & 1) << 3);
    const int cgrp = grp >> 1;
    const int nch = K >> 5;

#pragma unroll
    for (int s = 0; s < 2; ++s) {
        const uint32_t st = smb + (uint32_t)s * STAGE;
        const int k0 = s << 5;
        cp_tile(st + SM_AHI, Ah, lda, k0, tid);
        cp_tile(st + SM_ALO, Al, lda, k0, tid);
        cp_tile_bt(st + SM_BHI, Bh, ldb, k0, v0, tid);
        cp_tile_bt(st + SM_BLO, Bl, ldb, k0, v0, tid);
        asm volatile("cp.async.commit_group;" ::: "memory");
    }
    uint32_t stg = 0;
    for (int c = 0; c < nch; ++c) {
        if (c == nch - 1) asm volatile("cp.async.wait_group 0;" ::: "memory");
        else              asm volatile("cp.async.wait_group 1;" ::: "memory");
        __syncthreads();
        if (c + 2 < nch) {
            uint32_t s2 = stg + 2; if (s2 >= NST) s2 -= NST;
            const uint32_t st2 = smb + s2 * STAGE;
            const int k0 = (c + 2) << 5;
            cp_tile(st2 + SM_AHI, Ah, lda, k0, tid);
            cp_tile(st2 + SM_ALO, Al, lda, k0, tid);
            cp_tile_bt(st2 + SM_BHI, Bh, ldb, k0, v0, tid);
            cp_tile_bt(st2 + SM_BLO, Bl, ldb, k0, v0, tid);
            asm volatile("cp.async.commit_group;" ::: "memory");
        }
        compute_chunk_bt(smb + stg * STAGE, acc, rowm, nw, rin, grp, cgrp);
        if (++stg == NST) stg = 0;
    }
}

// ---------------------------------------------------------------------------
// Preprocessing
// ---------------------------------------------------------------------------
__global__ void mask_fused(const unsigned char* __restrict__ m) {
    __shared__ int s_notbin, s_odd;
    if (threadIdx.x == 0) { s_notbin = 0; s_odd = 0; }
    __syncthreads();
    int notbin = 0, odd = 0;
    for (int i = threadIdx.x; i < CB * CN; i += blockDim.x) {
        unsigned char v = m[i];
        if (v > 1) notbin = 1;
        if ((i & 3) && v == 1) odd = 1;
    }
    if (notbin) atomicOr(&s_notbin, 1);
    if (odd)    atomicOr(&s_odd, 1);
    __syncthreads();
    const int md = s_notbin ? 2 : (s_odd ? 0 : 1);   // 2=f32, 0=u8, 1=i32
    for (int i = threadIdx.x; i < CB * CN; i += blockDim.x) {
        float v;
        if (md == 0)      v = (m[i] != 0) ? 1.f : 0.f;
        else if (md == 1) v = (((const int*)(const void*)m)[i] != 0) ? 1.f : 0.f;
        else              v = (((const float*)(const void*)m)[i] != 0.f) ? 1.f : 0.f;
        g_maskf[i] = v;
    }
}

// One warp per 512-row: lin dot product + bf16 hi/lo split write.
__global__ void __launch_bounds__(256) lin_split(const float* __restrict__ IN,
                                                 const float* __restrict__ AO,
                                                 const float* __restrict__ a_w,
                                                 const float* __restrict__ b_w) {
    int w = (blockIdx.x * blockDim.x + threadIdx.x) >> 5;
    int lane = threadIdx.x & 31;
    const int nAO = CB * CN;
    if (w >= nAO + CB * CT) return;
    const float* row; const float* wv; float* outd; int idx;
    uint32_t *dhi, *dlo;
    if (w < nAO) {
        idx = w; row = AO + (size_t)w * CAD; wv = a_w; outd = g_lina;
        dhi = (uint32_t*)g_AOhi + (size_t)w * 256;
        dlo = (uint32_t*)g_AOlo + (size_t)w * 256;
    } else {
        idx = w - nAO; row = IN + (size_t)idx * CVD; wv = b_w; outd = g_linb;
        dhi = (uint32_t*)g_INhi + (size_t)idx * 256;
        dlo = (uint32_t*)g_INlo + (size_t)idx * 256;
    }
    float s = 0.f;
#pragma unroll
    for (int k = 0; k < 512; k += 128) {
        int e = k + lane * 4;
        float4 x = *(const float4*)(row + e);
        float4 y = *(const float4*)(wv + e);
        s += x.x * y.x + x.y * y.y + x.z * y.z + x.w * y.w;
        uint32_t h0, l0, h1, l1;
        split2u(x.x, x.y, h0, l0);
        split2u(x.z, x.w, h1, l1);
        dhi[e >> 1] = h0; dhi[(e >> 1) + 1] = h1;
        dlo[e >> 1] = l0; dlo[(e >> 1) + 1] = l1;
    }
#pragma unroll
    for (int o = 16; o; o >>= 1) s += __shfl_xor_sync(0xffffffffu, s, o);
    if (lane == 0) outd[idx] = s;
}

// W(512x512) -> WT hi/lo
__global__ void wt_split(const float* __restrict__ W) {
    __shared__ float t[32][33];
    int tx = threadIdx.x, ty = threadIdx.y;
    int a0 = blockIdx.y * 32, v0 = blockIdx.x * 32;
    for (int i = ty; i < 32; i += 8)
        t[i][tx] = W[(size_t)(a0 + i) * CVD + v0 + tx];
    __syncthreads();
    for (int i = ty; i < 32; i += 8) {
        float x = t[tx][i];
        __nv_bfloat16 h = __float2bfloat16(x);
        __nv_bfloat16 l = __float2bfloat16(x - __bfloat162float(h));
        size_t o = (size_t)(v0 + i) * CAD + a0 + tx;
        g_WThi[o] = __bfloat16_as_ushort(h);
        g_WTlo[o] = __bfloat16_as_ushort(l);
    }
}

// ---------------------------------------------------------------------------
// G1: aM = AO_flat @ WT^T -> aM hi/lo.  grid (4 Ntiles, 128 Mtiles)
// ---------------------------------------------------------------------------
__global__ void __launch_bounds__(256, 2) g1_mma() {
    extern __shared__ char sm[];
    const uint32_t smb = smem_u32(sm);
    const int n0 = blockIdx.x * 128;
    const size_t m0 = (size_t)blockIdx.y * 128;
    float acc[4][4][4];
#pragma unroll
    for (int a = 0; a < 4; ++a)
#pragma unroll
        for (int b = 0; b < 4; ++b)
#pragma unroll
            for (int cc = 0; cc < 4; ++cc) acc[a][b][cc] = 0.f;

    gemm_main(smb, acc, g_AOhi + m0 * CAD, g_AOlo + m0 * CAD, CAD,
              g_WThi + (size_t)n0 * CAD, g_WTlo + (size_t)n0 * CAD, CAD, CAD);

    const int lane = threadIdx.x & 31, w = threadIdx.x >> 5;
    const int mw = (w & 1) * 64, nw = (w >> 1) * 32;
    const int qr = lane >> 2, qc = (lane & 3) * 2;
    uint32_t* ghi = (uint32_t*)g_aMhi;
    uint32_t* glo = (uint32_t*)g_aMlo;
#pragma unroll
    for (int mi = 0; mi < 4; ++mi)
#pragma unroll
        for (int nj = 0; nj < 4; ++nj) {
            size_t r0 = m0 + mw + mi * 16 + qr;
            size_t cp = (size_t)(n0 + nw + nj * 8 + qc) >> 1;
            uint32_t h, l;
            split2u(acc[mi][nj][0], acc[mi][nj][1], h, l);
            ghi[r0 * (CVD >> 1) + cp] = h; glo[r0 * (CVD >> 1) + cp] = l;
            split2u(acc[mi][nj][2], acc[mi][nj][3], h, l);
            ghi[(r0 + 8) * (CVD >> 1) + cp] = h; glo[(r0 + 8) * (CVD >> 1) + cp] = l;
        }
}

// ---------------------------------------------------------------------------
// G2: sim = IN_tile @ aM_b^T + fused tanh/masked-softmax -> attn hi/lo.
//     grid (2 Mtiles, B)
// ---------------------------------------------------------------------------
__global__ void __launch_bounds__(256, 2) g2_mma(const float* __restrict__ biasp) {
    extern __shared__ char sm[];
    const uint32_t smb = smem_u32(sm);
    const int tid = threadIdx.x;
    const int b = blockIdx.y;
    const int m0 = blockIdx.x * 128;
    float* sl  = (float*)(sm + SM_LIN);
    float* sk  = (float*)(sm + SM_MSK);
    float* slb = (float*)(sm + SM_LNB);
    if (tid < 128) {
        sl[tid]  = g_lina[b * CN + tid];
        sk[tid]  = g_maskf[b * CN + tid];
        slb[tid] = g_linb[b * CT + m0 + tid];
    }
    float acc[4][4][4];
#pragma unroll
    for (int a = 0; a < 4; ++a)
#pragma unroll
        for (int bb = 0; bb < 4; ++bb)
#pragma unroll
            for (int cc = 0; cc < 4; ++cc) acc[a][bb][cc] = 0.f;

    gemm_main(smb, acc,
              g_INhi + ((size_t)b * CT + m0) * CVD,
              g_INlo + ((size_t)b * CT + m0) * CVD, CVD,
              g_aMhi + (size_t)b * CN * CVD,
              g_aMlo + (size_t)b * CN * CVD, CVD, CVD);
    __syncthreads();

    const int lane = tid & 31, w = tid >> 5;
    const int mw = (w & 1) * 64, nw = (w >> 1) * 32;
    const int qr = lane >> 2, qc = (lane & 3) * 2;
    const float bs = biasp[0];
    float* ssim = (float*)sm;                      // 128 x 129 floats
#pragma unroll
    for (int mi = 0; mi < 4; ++mi)
#pragma unroll
        for (int nj = 0; nj < 4; ++nj) {
            int c0 = nw + nj * 8 + qc;
            float sla = sl[c0], slA = sl[c0 + 1];
            float mk0 = sk[c0], mk1 = sk[c0 + 1];
#pragma unroll
            for (int p = 0; p < 2; ++p) {
                int r = mw + mi * 16 + qr + p * 8;
                float lb = slb[r] + bs;
                float e0 = mk0 * __expf(tanhf(acc[mi][nj][2 * p] + sla + lb));
                float e1 = mk1 * __expf(tanhf(acc[mi][nj][2 * p + 1] + slA + lb));
                ssim[r * 129 + c0] = e0;
                ssim[r * 129 + c0 + 1] = e1;
            }
        }
    __syncthreads();
    {
        const int r = tid >> 1, half = tid & 1;
        const float* rowp = ssim + r * 129;
        float s = 0.f;
#pragma unroll
        for (int n = 0; n < 64; ++n) s += rowp[half * 64 + n];
        s += __shfl_xor_sync(0xffffffffu, s, 1);
        const float inv = 1.0f / (s + 1e-30f);
        const size_t t = (size_t)b * CT + m0 + r;
        uint32_t* ohi = (uint32_t*)g_athi + t * 64;
        uint32_t* olo = (uint32_t*)g_atlo + t * 64;
#pragma unroll
        for (int jj = 0; jj < 32; ++jj) {
            int j = half * 32 + jj;
            uint32_t h, l;
            split2u(rowp[2 * j] * inv, rowp[2 * j + 1] * inv, h, l);
            ohi[j] = h; olo[j] = l;
        }
    }
}

// ---------------------------------------------------------------------------
// G3: out = attn_tile @ AO_b (B trans).  grid (4 Ntiles, 2 Mtiles, B)
// ---------------------------------------------------------------------------
__global__ void __launch_bounds__(256, 2) g3_mma(float* __restrict__ OUT) {
    extern __shared__ char sm[];
    const uint32_t smb = smem_u32(sm);
    const int b = blockIdx.z;
    const int m0 = blockIdx.y * 128;
    const int n0 = blockIdx.x * 128;      // v-tile base
    float acc[4][4][4];
#pragma unroll
    for (int a = 0; a < 4; ++a)
#pragma unroll
        for (int bb = 0; bb < 4; ++bb)
#pragma unroll
            for (int cc = 0; cc < 4; ++cc) acc[a][bb][cc] = 0.f;

    gemm_main_bt(smb, acc,
                 g_athi + ((size_t)b * CT + m0) * CN,
                 g_atlo + ((size_t)b * CT + m0) * CN, CN,
                 g_AOhi + (size_t)b * CN * CAD,
                 g_AOlo + (size_t)b * CN * CAD, CAD, n0, CN);

    const int lane = threadIdx.x & 31, w = threadIdx.x >> 5;
    const int mw = (w & 1) * 64, nw = (w >> 1) * 32;
    const int qr = lane >> 2, qc = (lane & 3) * 2;
#pragma unroll
    for (int mi = 0; mi < 4; ++mi)
#pragma unroll
        for (int nj = 0; nj < 4; ++nj) {
            size_t r0 = (size_t)b * CT + m0 + mw + mi * 16 + qr;
            int gc = n0 + nw + nj * 8 + qc;
            *(float2*)(OUT + r0 * CAD + gc) =
                make_float2(acc[mi][nj][0], acc[mi][nj][1]);
            *(float2*)(OUT + (r0 + 8) * CAD + gc) =
                make_float2(acc[mi][nj][2], acc[mi][nj][3]);
        }
}

// ---------------------------------------------------------------------------
extern "C" void kernel_launch(void* const* d_in, const int* in_sizes, int n_in,
                              void* d_out, int out_size) {
    const float* inputs = (const float*)d_in[0];
    const float* ao     = (const float*)d_in[1];
    const void*  mask   = d_in[2];
    const float* W      = (const float*)d_in[3];
    const float* a_w    = (const float*)d_in[4];
    const float* b_w    = (const float*)d_in[5];
    const float* bias   = (const float*)d_in[6];
    float* out = (float*)d_out;

    cudaFuncSetAttribute(g1_mma, cudaFuncAttributeMaxDynamicSharedMemorySize, SMEM_G13);
    cudaFuncSetAttribute(g2_mma, cudaFuncAttributeMaxDynamicSharedMemorySize, SMEM_G2);
    cudaFuncSetAttribute(g3_mma, cudaFuncAttributeMaxDynamicSharedMemorySize, SMEM_G13);

    // launch order chosen so g1_mma sits at launch index 3 (the profiled slot)
    mask_fused<<<1, 1024>>>((const unsigned char*)mask);                 // 0
    int nwarps = CB * CN + CB * CT;
    lin_split<<<(nwarps * 32 + 255) / 256, 256>>>(inputs, ao, a_w, b_w); // 1
    wt_split<<<dim3(16, 16), dim3(32, 8)>>>(W);                          // 2
    g1_mma<<<dim3(4, 128), 256, SMEM_G13>>>();                           // 3
    g2_mma<<<dim3(2, CB), 256, SMEM_G2>>>(bias);                         // 4
    g3_mma<<<dim3(4, 2, CB), 256, SMEM_G13>>>(out);                      // 5
}

// round 6
// speedup vs baseline: 2.5143x; 1.0269x over previous
#include <cuda_runtime.h>
#include <cuda_bf16.h>
#include <cstdint>

// ---------------------------------------------------------------------------
// GeneralizedBilinearAttention via mma.sync bf16 (base sm_103 ISA).
//   G1: aM   = AO_flat(16384x512) @ WT(512x512)
//   G2: sim  = IN(256x512) @ aM_b(128x512)^T + fused tanh/masked-softmax
//   G3: out  = attn(256x128) @ AO_b(128x512)  (B via ldmatrix.trans)
// fp32 split to bf16 hi/lo; 3 MMA products (hh + hl + lh), fp32 acc.
// Mainloop: K32 chunks, 3-stage cp.async pipeline, A-frag double buffering,
// chunk-invariant cp.async addressing.
// ---------------------------------------------------------------------------

#define CB 128
#define CT 256
#define CN 128
#define CAD 512
#define CVD 512

__device__ __align__(16) unsigned short g_AOhi[CB * CN * CAD];
__device__ __align__(16) unsigned short g_AOlo[CB * CN * CAD];
__device__ __align__(16) unsigned short g_INhi[CB * CT * CVD];
__device__ __align__(16) unsigned short g_INlo[CB * CT * CVD];
__device__ __align__(16) unsigned short g_WThi[CVD * CAD];
__device__ __align__(16) unsigned short g_WTlo[CVD * CAD];
__device__ __align__(16) unsigned short g_aMhi[CB * CN * CVD];
__device__ __align__(16) unsigned short g_aMlo[CB * CN * CVD];
__device__ __align__(16) unsigned short g_athi[CB * CT * CN];
__device__ __align__(16) unsigned short g_atlo[CB * CT * CN];
__device__ __align__(16) float g_lina[CB * CN];
__device__ __align__(16) float g_linb[CB * CT];
__device__ __align__(16) float g_maskf[CB * CN];

#define TILEB 8192
#define SM_AHI 0
#define SM_ALO TILEB
#define SM_BHI (2 * TILEB)
#define SM_BLO (3 * TILEB)
#define STAGE  (4 * TILEB)
#define NST 3
#define SMEM_MAIN (NST * STAGE)    // 98304
#define SM_LIN SMEM_MAIN
#define SM_MSK (SM_LIN + 512)
#define SM_LNB (SM_MSK + 512)
#define SMEM_G13 SMEM_MAIN
#define SMEM_G2  (SM_LNB + 512)

__device__ __forceinline__ uint32_t smem_u32(const void* p) {
    return (uint32_t)__cvta_generic_to_shared(p);
}
__device__ __forceinline__ uint32_t swz(int row, int c16) {
    return (uint32_t)(row * 64 + ((c16 ^ ((row >> 1) & 3)) << 4));
}
__device__ __forceinline__ uint32_t swzbt(int row, int c16) {
    return (uint32_t)(row * 256 + ((c16 ^ (row & 7)) << 4));
}
__device__ __forceinline__ void ldsm4(uint32_t* r, uint32_t addr) {
    asm volatile("ldmatrix.sync.aligned.m8n8.x4.shared.b16 {%0,%1,%2,%3}, [%4];"
                 : "=r"(r[0]), "=r"(r[1]), "=r"(r[2]), "=r"(r[3]) : "r"(addr));
}
__device__ __forceinline__ void ldsm4t(uint32_t* r, uint32_t addr) {
    asm volatile("ldmatrix.sync.aligned.m8n8.x4.trans.shared.b16 {%0,%1,%2,%3}, [%4];"
                 : "=r"(r[0]), "=r"(r[1]), "=r"(r[2]), "=r"(r[3]) : "r"(addr));
}
__device__ __forceinline__ void mma_bf16(float* c, const uint32_t* a,
                                         uint32_t b0, uint32_t b1) {
    asm volatile("mma.sync.aligned.m16n8k16.row.col.f32.bf16.bf16.f32 "
                 "{%0,%1,%2,%3}, {%4,%5,%6,%7}, {%8,%9}, {%0,%1,%2,%3};"
                 : "+f"(c[0]), "+f"(c[1]), "+f"(c[2]), "+f"(c[3])
                 : "r"(a[0]), "r"(a[1]), "r"(a[2]), "r"(a[3]), "r"(b0), "r"(b1));
}
__device__ __forceinline__ void cpa(uint32_t d, const void* g) {
    asm volatile("cp.async.cg.shared.global [%0], [%1], 16;"
                 :: "r"(d), "l"(g) : "memory");
}
__device__ __forceinline__ void split2u(float x, float y, uint32_t& h, uint32_t& l) {
    __nv_bfloat16 xh = __float2bfloat16(x), yh = __float2bfloat16(y);
    __nv_bfloat16 xl = __float2bfloat16(x - __bfloat162float(xh));
    __nv_bfloat16 yl = __float2bfloat16(y - __bfloat162float(yh));
    h = ((uint32_t)__bfloat16_as_ushort(yh) << 16) | __bfloat16_as_ushort(xh);
    l = ((uint32_t)__bfloat16_as_ushort(yl) << 16) | __bfloat16_as_ushort(xl);
}

// ---- compute one K32 chunk (B k-major), A-frag double buffered ---------------
__device__ __forceinline__ void compute_chunk(uint32_t st, float acc[4][4][4],
                                              const int* rowm, const int* rowb,
                                              int cgrp) {
#pragma unroll
    for (int ks = 0; ks < 2; ++ks) {
        const int cu = 2 * ks + cgrp;
        uint32_t bh[2][4], bl[2][4];
#pragma unroll
        for (int j = 0; j < 2; ++j) {
            ldsm4(bh[j], st + SM_BHI + swz(rowb[j], cu));
            ldsm4(bl[j], st + SM_BLO + swz(rowb[j], cu));
        }
        uint32_t ah[2][4], al[2][4];
        ldsm4(ah[0], st + SM_AHI + swz(rowm[0], cu));
        ldsm4(al[0], st + SM_ALO + swz(rowm[0], cu));
#pragma unroll
        for (int mi = 0; mi < 4; ++mi) {
            const int cur = mi & 1, nxt = cur ^ 1;
            if (mi < 3) {
                ldsm4(ah[nxt], st + SM_AHI + swz(rowm[mi + 1], cu));
                ldsm4(al[nxt], st + SM_ALO + swz(rowm[mi + 1], cu));
            }
#pragma unroll
            for (int nj = 0; nj < 4; ++nj) {
                const int j = nj >> 1, o = nj & 1;
                mma_bf16(acc[mi][nj], ah[cur], bh[j][o], bh[j][o + 2]);
                mma_bf16(acc[mi][nj], ah[cur], bl[j][o], bl[j][o + 2]);
                mma_bf16(acc[mi][nj], al[cur], bh[j][o], bh[j][o + 2]);
            }
        }
    }
}

// ---- compute one K32 chunk, B loaded transposed (G3) -------------------------
__device__ __forceinline__ void compute_chunk_bt(uint32_t st, float acc[4][4][4],
                                                 const int* rowm, int nw,
                                                 int rin, int grp, int cgrp) {
#pragma unroll
    for (int ks = 0; ks < 2; ++ks) {
        const int cu = 2 * ks + cgrp;
        const int browk = 16 * ks + rin + ((grp >> 1) << 3);
        uint32_t bh[2][4], bl[2][4];
#pragma unroll
        for (int j = 0; j < 2; ++j) {
            const int bc = (nw >> 3) + 2 * j + (grp & 1);
            ldsm4t(bh[j], st + SM_BHI + swzbt(browk, bc));
            ldsm4t(bl[j], st + SM_BLO + swzbt(browk, bc));
        }
        uint32_t ah[2][4], al[2][4];
        ldsm4(ah[0], st + SM_AHI + swz(rowm[0], cu));
        ldsm4(al[0], st + SM_ALO + swz(rowm[0], cu));
#pragma unroll
        for (int mi = 0; mi < 4; ++mi) {
            const int cur = mi & 1, nxt = cur ^ 1;
            if (mi < 3) {
                ldsm4(ah[nxt], st + SM_AHI + swz(rowm[mi + 1], cu));
                ldsm4(al[nxt], st + SM_ALO + swz(rowm[mi + 1], cu));
            }
#pragma unroll
            for (int nj = 0; nj < 4; ++nj) {
                const int j = nj >> 1, o = nj & 1;
                mma_bf16(acc[mi][nj], ah[cur], bh[j][o], bh[j][o + 2]);
                mma_bf16(acc[mi][nj], ah[cur], bl[j][o], bl[j][o + 2]);
                mma_bf16(acc[mi][nj], al[cur], bh[j][o], bh[j][o + 2]);
            }
        }
    }
}

// ---- 3-stage pipelined mainloop (standard TN) --------------------------------
__device__ __forceinline__ void gemm_main(uint32_t smb, float acc[4][4][4],
    const unsigned short* Ah, const unsigned short* Al, int lda,
    const unsigned short* Bh, const unsigned short* Bl, int ldb, int K) {
    const int tid = threadIdx.x, lane = tid & 31, w = tid >> 5;
    const int mw = (w & 1) * 64, nw = (w >> 1) * 32;
    const int grp = lane >> 3, rin = lane & 7;
    int rowm[4], rowb[2];
#pragma unroll
    for (int mi = 0; mi < 4; ++mi) rowm[mi] = mw + mi * 16 + rin + ((grp & 1) << 3);
#pragma unroll
    for (int j = 0; j < 2; ++j)    rowb[j] = nw + j * 16 + rin + ((grp & 1) << 3);
    const int cgrp = grp >> 1;
    const int nch = K >> 5;

    // chunk-invariant cp.async addressing
    uint32_t doff[2];
    const unsigned short *pAh[2], *pAl[2], *pBh[2], *pBl[2];
#pragma unroll
    for (int i = 0; i < 2; ++i) {
        int u = i * 256 + tid, row = u >> 2, c = u & 3;
        doff[i] = swz(row, c);
        pAh[i] = Ah + (size_t)row * lda + c * 8;
        pAl[i] = Al + (size_t)row * lda + c * 8;
        pBh[i] = Bh + (size_t)row * ldb + c * 8;
        pBl[i] = Bl + (size_t)row * ldb + c * 8;
    }

#pragma unroll
    for (int s = 0; s < 2; ++s) {
        const uint32_t st = smb + (uint32_t)s * STAGE;
#pragma unroll
        for (int i = 0; i < 2; ++i) {
            cpa(st + SM_AHI + doff[i], pAh[i]);
            cpa(st + SM_ALO + doff[i], pAl[i]);
            cpa(st + SM_BHI + doff[i], pBh[i]);
            cpa(st + SM_BLO + doff[i], pBl[i]);
            pAh[i] += 32; pAl[i] += 32; pBh[i] += 32; pBl[i] += 32;
        }
        asm volatile("cp.async.commit_group;" ::: "memory");
    }
    uint32_t stg = 0;
    for (int c = 0; c < nch; ++c) {
        if (c == nch - 1) asm volatile("cp.async.wait_group 0;" ::: "memory");
        else              asm volatile("cp.async.wait_group 1;" ::: "memory");
        __syncthreads();
        if (c + 2 < nch) {
            uint32_t s2 = stg + 2; if (s2 >= NST) s2 -= NST;
            const uint32_t st2 = smb + s2 * STAGE;
#pragma unroll
            for (int i = 0; i < 2; ++i) {
                cpa(st2 + SM_AHI + doff[i], pAh[i]);
                cpa(st2 + SM_ALO + doff[i], pAl[i]);
                cpa(st2 + SM_BHI + doff[i], pBh[i]);
                cpa(st2 + SM_BLO + doff[i], pBl[i]);
                pAh[i] += 32; pAl[i] += 32; pBh[i] += 32; pBl[i] += 32;
            }
            asm volatile("cp.async.commit_group;" ::: "memory");
        }
        compute_chunk(smb + stg * STAGE, acc, rowm, rowb, cgrp);
        if (++stg == NST) stg = 0;
    }
}

// ---- 3-stage pipelined mainloop for G3 (B trans-loaded) ----------------------
__device__ __forceinline__ void gemm_main_bt(uint32_t smb, float acc[4][4][4],
    const unsigned short* Ah, const unsigned short* Al, int lda,
    const unsigned short* Bh, const unsigned short* Bl, int ldb, int v0, int K) {
    const int tid = threadIdx.x, lane = tid & 31, w = tid >> 5;
    const int mw = (w & 1) * 64, nw = (w >> 1) * 32;
    const int grp = lane >> 3, rin = lane & 7;
    int rowm[4];
#pragma unroll
    for (int mi = 0; mi < 4; ++mi) rowm[mi] = mw + mi * 16 + rin + ((grp & 1) << 3);
    const int cgrp = grp >> 1;
    const int nch = K >> 5;

    uint32_t doffA[2], doffB[2];
    const unsigned short *pAh[2], *pAl[2], *pBh[2], *pBl[2];
    const size_t bstep = (size_t)32 * ldb;
#pragma unroll
    for (int i = 0; i < 2; ++i) {
        int u = i * 256 + tid;
        int rowA = u >> 2, cA = u & 3;
        doffA[i] = swz(rowA, cA);
        pAh[i] = Ah + (size_t)rowA * lda + cA * 8;
        pAl[i] = Al + (size_t)rowA * lda + cA * 8;
        int rowB = u >> 4, cB = u & 15;
        doffB[i] = swzbt(rowB, cB);
        pBh[i] = Bh + (size_t)rowB * ldb + v0 + cB * 8;
        pBl[i] = Bl + (size_t)rowB * ldb + v0 + cB * 8;
    }

#pragma unroll
    for (int s = 0; s < 2; ++s) {
        const uint32_t st = smb + (uint32_t)s * STAGE;
#pragma unroll
        for (int i = 0; i < 2; ++i) {
            cpa(st + SM_AHI + doffA[i], pAh[i]);
            cpa(st + SM_ALO + doffA[i], pAl[i]);
            cpa(st + SM_BHI + doffB[i], pBh[i]);
            cpa(st + SM_BLO + doffB[i], pBl[i]);
            pAh[i] += 32; pAl[i] += 32; pBh[i] += bstep; pBl[i] += bstep;
        }
        asm volatile("cp.async.commit_group;" ::: "memory");
    }
    uint32_t stg = 0;
    for (int c = 0; c < nch; ++c) {
        if (c == nch - 1) asm volatile("cp.async.wait_group 0;" ::: "memory");
        else              asm volatile("cp.async.wait_group 1;" ::: "memory");
        __syncthreads();
        if (c + 2 < nch) {
            uint32_t s2 = stg + 2; if (s2 >= NST) s2 -= NST;
            const uint32_t st2 = smb + s2 * STAGE;
#pragma unroll
            for (int i = 0; i < 2; ++i) {
                cpa(st2 + SM_AHI + doffA[i], pAh[i]);
                cpa(st2 + SM_ALO + doffA[i], pAl[i]);
                cpa(st2 + SM_BHI + doffB[i], pBh[i]);
                cpa(st2 + SM_BLO + doffB[i], pBl[i]);
                pAh[i] += 32; pAl[i] += 32; pBh[i] += bstep; pBl[i] += bstep;
            }
            asm volatile("cp.async.commit_group;" ::: "memory");
        }
        compute_chunk_bt(smb + stg * STAGE, acc, rowm, nw, rin, grp, cgrp);
        if (++stg == NST) stg = 0;
    }
}

// ---------------------------------------------------------------------------
// Preprocessing
// ---------------------------------------------------------------------------
__global__ void mask_fused(const unsigned char* __restrict__ m) {
    __shared__ int s_notbin, s_odd;
    if (threadIdx.x == 0) { s_notbin = 0; s_odd = 0; }
    __syncthreads();
    int notbin = 0, odd = 0;
    for (int i = threadIdx.x; i < CB * CN; i += blockDim.x) {
        unsigned char v = m[i];
        if (v > 1) notbin = 1;
        if ((i & 3) && v == 1) odd = 1;
    }
    if (notbin) atomicOr(&s_notbin, 1);
    if (odd)    atomicOr(&s_odd, 1);
    __syncthreads();
    const int md = s_notbin ? 2 : (s_odd ? 0 : 1);
    for (int i = threadIdx.x; i < CB * CN; i += blockDim.x) {
        float v;
        if (md == 0)      v = (m[i] != 0) ? 1.f : 0.f;
        else if (md == 1) v = (((const int*)(const void*)m)[i] != 0) ? 1.f : 0.f;
        else              v = (((const float*)(const void*)m)[i] != 0.f) ? 1.f : 0.f;
        g_maskf[i] = v;
    }
}

__global__ void __launch_bounds__(256) lin_split(const float* __restrict__ IN,
                                                 const float* __restrict__ AO,
                                                 const float* __restrict__ a_w,
                                                 const float* __restrict__ b_w) {
    int w = (blockIdx.x * blockDim.x + threadIdx.x) >> 5;
    int lane = threadIdx.x & 31;
    const int nAO = CB * CN;
    if (w >= nAO + CB * CT) return;
    const float* row; const float* wv; float* outd; int idx;
    uint32_t *dhi, *dlo;
    if (w < nAO) {
        idx = w; row = AO + (size_t)w * CAD; wv = a_w; outd = g_lina;
        dhi = (uint32_t*)g_AOhi + (size_t)w * 256;
        dlo = (uint32_t*)g_AOlo + (size_t)w * 256;
    } else {
        idx = w - nAO; row = IN + (size_t)idx * CVD; wv = b_w; outd = g_linb;
        dhi = (uint32_t*)g_INhi + (size_t)idx * 256;
        dlo = (uint32_t*)g_INlo + (size_t)idx * 256;
    }
    float s = 0.f;
#pragma unroll
    for (int k = 0; k < 512; k += 128) {
        int e = k + lane * 4;
        float4 x = *(const float4*)(row + e);
        float4 y = *(const float4*)(wv + e);
        s += x.x * y.x + x.y * y.y + x.z * y.z + x.w * y.w;
        uint32_t h0, l0, h1, l1;
        split2u(x.x, x.y, h0, l0);
        split2u(x.z, x.w, h1, l1);
        dhi[e >> 1] = h0; dhi[(e >> 1) + 1] = h1;
        dlo[e >> 1] = l0; dlo[(e >> 1) + 1] = l1;
    }
#pragma unroll
    for (int o = 16; o; o >>= 1) s += __shfl_xor_sync(0xffffffffu, s, o);
    if (lane == 0) outd[idx] = s;
}

__global__ void wt_split(const float* __restrict__ W) {
    __shared__ float t[32][33];
    int tx = threadIdx.x, ty = threadIdx.y;
    int a0 = blockIdx.y * 32, v0 = blockIdx.x * 32;
    for (int i = ty; i < 32; i += 8)
        t[i][tx] = W[(size_t)(a0 + i) * CVD + v0 + tx];
    __syncthreads();
    for (int i = ty; i < 32; i += 8) {
        float x = t[tx][i];
        __nv_bfloat16 h = __float2bfloat16(x);
        __nv_bfloat16 l = __float2bfloat16(x - __bfloat162float(h));
        size_t o = (size_t)(v0 + i) * CAD + a0 + tx;
        g_WThi[o] = __bfloat16_as_ushort(h);
        g_WTlo[o] = __bfloat16_as_ushort(l);
    }
}

// ---------------------------------------------------------------------------
__global__ void __launch_bounds__(256, 2) g1_mma() {
    extern __shared__ char sm[];
    const uint32_t smb = smem_u32(sm);
    const int n0 = blockIdx.x * 128;
    const size_t m0 = (size_t)blockIdx.y * 128;
    float acc[4][4][4];
#pragma unroll
    for (int a = 0; a < 4; ++a)
#pragma unroll
        for (int b = 0; b < 4; ++b)
#pragma unroll
            for (int cc = 0; cc < 4; ++cc) acc[a][b][cc] = 0.f;

    gemm_main(smb, acc, g_AOhi + m0 * CAD, g_AOlo + m0 * CAD, CAD,
              g_WThi + (size_t)n0 * CAD, g_WTlo + (size_t)n0 * CAD, CAD, CAD);

    const int lane = threadIdx.x & 31, w = threadIdx.x >> 5;
    const int mw = (w & 1) * 64, nw = (w >> 1) * 32;
    const int qr = lane >> 2, qc = (lane & 3) * 2;
    uint32_t* ghi = (uint32_t*)g_aMhi;
    uint32_t* glo = (uint32_t*)g_aMlo;
#pragma unroll
    for (int mi = 0; mi < 4; ++mi)
#pragma unroll
        for (int nj = 0; nj < 4; ++nj) {
            size_t r0 = m0 + mw + mi * 16 + qr;
            size_t cp = (size_t)(n0 + nw + nj * 8 + qc) >> 1;
            uint32_t h, l;
            split2u(acc[mi][nj][0], acc[mi][nj][1], h, l);
            ghi[r0 * (CVD >> 1) + cp] = h; glo[r0 * (CVD >> 1) + cp] = l;
            split2u(acc[mi][nj][2], acc[mi][nj][3], h, l);
            ghi[(r0 + 8) * (CVD >> 1) + cp] = h; glo[(r0 + 8) * (CVD >> 1) + cp] = l;
        }
}

__global__ void __launch_bounds__(256, 2) g2_mma(const float* __restrict__ biasp) {
    extern __shared__ char sm[];
    const uint32_t smb = smem_u32(sm);
    const int tid = threadIdx.x;
    const int b = blockIdx.y;
    const int m0 = blockIdx.x * 128;
    float* sl  = (float*)(sm + SM_LIN);
    float* sk  = (float*)(sm + SM_MSK);
    float* slb = (float*)(sm + SM_LNB);
    if (tid < 128) {
        sl[tid]  = g_lina[b * CN + tid];
        sk[tid]  = g_maskf[b * CN + tid];
        slb[tid] = g_linb[b * CT + m0 + tid];
    }
    float acc[4][4][4];
#pragma unroll
    for (int a = 0; a < 4; ++a)
#pragma unroll
        for (int bb = 0; bb < 4; ++bb)
#pragma unroll
            for (int cc = 0; cc < 4; ++cc) acc[a][bb][cc] = 0.f;

    gemm_main(smb, acc,
              g_INhi + ((size_t)b * CT + m0) * CVD,
              g_INlo + ((size_t)b * CT + m0) * CVD, CVD,
              g_aMhi + (size_t)b * CN * CVD,
              g_aMlo + (size_t)b * CN * CVD, CVD, CVD);
    __syncthreads();

    const int lane = tid & 31, w = tid >> 5;
    const int mw = (w & 1) * 64, nw = (w >> 1) * 32;
    const int qr = lane >> 2, qc = (lane & 3) * 2;
    const float bs = biasp[0];
    float* ssim = (float*)sm;
#pragma unroll
    for (int mi = 0; mi < 4; ++mi)
#pragma unroll
        for (int nj = 0; nj < 4; ++nj) {
            int c0 = nw + nj * 8 + qc;
            float sla = sl[c0], slA = sl[c0 + 1];
            float mk0 = sk[c0], mk1 = sk[c0 + 1];
#pragma unroll
            for (int p = 0; p < 2; ++p) {
                int r = mw + mi * 16 + qr + p * 8;
                float lb = slb[r] + bs;
                float e0 = mk0 * __expf(tanhf(acc[mi][nj][2 * p] + sla + lb));
                float e1 = mk1 * __expf(tanhf(acc[mi][nj][2 * p + 1] + slA + lb));
                ssim[r * 129 + c0] = e0;
                ssim[r * 129 + c0 + 1] = e1;
            }
        }
    __syncthreads();
    {
        const int r = tid >> 1, half = tid & 1;
        const float* rowp = ssim + r * 129;
        float s = 0.f;
#pragma unroll
        for (int n = 0; n < 64; ++n) s += rowp[half * 64 + n];
        s += __shfl_xor_sync(0xffffffffu, s, 1);
        const float inv = 1.0f / (s + 1e-30f);
        const size_t t = (size_t)b * CT + m0 + r;
        uint32_t* ohi = (uint32_t*)g_athi + t * 64;
        uint32_t* olo = (uint32_t*)g_atlo + t * 64;
#pragma unroll
        for (int jj = 0; jj < 32; ++jj) {
            int j = half * 32 + jj;
            uint32_t h, l;
            split2u(rowp[2 * j] * inv, rowp[2 * j + 1] * inv, h, l);
            ohi[j] = h; olo[j] = l;
        }
    }
}

__global__ void __launch_bounds__(256, 2) g3_mma(float* __restrict__ OUT) {
    extern __shared__ char sm[];
    const uint32_t smb = smem_u32(sm);
    const int b = blockIdx.z;
    const int m0 = blockIdx.y * 128;
    const int n0 = blockIdx.x * 128;
    float acc[4][4][4];
#pragma unroll
    for (int a = 0; a < 4; ++a)
#pragma unroll
        for (int bb = 0; bb < 4; ++bb)
#pragma unroll
            for (int cc = 0; cc < 4; ++cc) acc[a][bb][cc] = 0.f;

    gemm_main_bt(smb, acc,
                 g_athi + ((size_t)b * CT + m0) * CN,
                 g_atlo + ((size_t)b * CT + m0) * CN, CN,
                 g_AOhi + (size_t)b * CN * CAD,
                 g_AOlo + (size_t)b * CN * CAD, CAD, n0, CN);

    const int lane = threadIdx.x & 31, w = threadIdx.x >> 5;
    const int mw = (w & 1) * 64, nw = (w >> 1) * 32;
    const int qr = lane >> 2, qc = (lane & 3) * 2;
#pragma unroll
    for (int mi = 0; mi < 4; ++mi)
#pragma unroll
        for (int nj = 0; nj < 4; ++nj) {
            size_t r0 = (size_t)b * CT + m0 + mw + mi * 16 + qr;
            int gc = n0 + nw + nj * 8 + qc;
            *(float2*)(OUT + r0 * CAD + gc) =
                make_float2(acc[mi][nj][0], acc[mi][nj][1]);
            *(float2*)(OUT + (r0 + 8) * CAD + gc) =
                make_float2(acc[mi][nj][2], acc[mi][nj][3]);
        }
}

// ---------------------------------------------------------------------------
extern "C" void kernel_launch(void* const* d_in, const int* in_sizes, int n_in,
                              void* d_out, int out_size) {
    const float* inputs = (const float*)d_in[0];
    const float* ao     = (const float*)d_in[1];
    const void*  mask   = d_in[2];
    const float* W      = (const float*)d_in[3];
    const float* a_w    = (const float*)d_in[4];
    const float* b_w    = (const float*)d_in[5];
    const float* bias   = (const float*)d_in[6];
    float* out = (float*)d_out;

    cudaFuncSetAttribute(g1_mma, cudaFuncAttributeMaxDynamicSharedMemorySize, SMEM_G13);
    cudaFuncSetAttribute(g2_mma, cudaFuncAttributeMaxDynamicSharedMemorySize, SMEM_G2);
    cudaFuncSetAttribute(g3_mma, cudaFuncAttributeMaxDynamicSharedMemorySize, SMEM_G13);

    // g1_mma stays at launch index 3 (the profiled slot)
    mask_fused<<<1, 1024>>>((const unsigned char*)mask);                 // 0
    int nwarps = CB * CN + CB * CT;
    lin_split<<<(nwarps * 32 + 255) / 256, 256>>>(inputs, ao, a_w, b_w); // 1
    wt_split<<<dim3(16, 16), dim3(32, 8)>>>(W);                          // 2
    g1_mma<<<dim3(4, 128), 256, SMEM_G13>>>();                           // 3
    g2_mma<<<dim3(2, CB), 256, SMEM_G2>>>(bias);                         // 4
    g3_mma<<<dim3(4, 2, CB), 256, SMEM_G13>>>(out);                      // 5
}

// round 7
// speedup vs baseline: 3.2807x; 1.3048x over previous
#include <cuda_runtime.h>
#include <cuda_fp16.h>
#include <cstdint>

// ---------------------------------------------------------------------------
// GeneralizedBilinearAttention via mma.sync fp16 (base sm_103 ISA).
//   G1: aM   = AOh(16384x512) @ (WTh+WTl)(512x512)
//   G2: sim  = INh(256x512) @ (aMh+aMl)^T + fused tanh/masked-softmax
//   G3: out  = (attnh+attnl)(256x128) @ AOh(128x512)  (B via ldmatrix.trans)
// fp16 hi/lo split on ONE operand per GEMM -> 2 MMA products, fp32 acc.
// Mainloop: K32 chunks, 3-stage cp.async pipeline (24KB/stage).
// ---------------------------------------------------------------------------

#define CB 128
#define CT 256
#define CN 128
#define CAD 512
#define CVD 512

__device__ __align__(16) unsigned short g_AOh[CB * CN * CAD];
__device__ __align__(16) unsigned short g_INh[CB * CT * CVD];
__device__ __align__(16) unsigned short g_WTh[CVD * CAD];
__device__ __align__(16) unsigned short g_WTl[CVD * CAD];
__device__ __align__(16) unsigned short g_aMh[CB * CN * CVD];
__device__ __align__(16) unsigned short g_aMl[CB * CN * CVD];
__device__ __align__(16) unsigned short g_ath[CB * CT * CN];
__device__ __align__(16) unsigned short g_atl[CB * CT * CN];
__device__ __align__(16) float g_lina[CB * CN];
__device__ __align__(16) float g_linb[CB * CT];
__device__ __align__(16) float g_maskf[CB * CN];

// ---- smem: 3 stages x 24KB --------------------------------------------------
#define TILEB 8192
#define SM_T0 0                      // G1/G2: A     | G3: attn-hi
#define SM_T1 TILEB                  // G1/G2: B-hi  | G3: attn-lo
#define SM_T2 (2 * TILEB)            // G1/G2: B-lo  | G3: AO (trans tile)
#define STAGE (3 * TILEB)            // 24576
#define NST 3
#define SMEM_MAIN (NST * STAGE)      // 73728
#define SM_LIN SMEM_MAIN
#define SM_MSK (SM_LIN + 512)
#define SM_LNB (SM_MSK + 512)
#define SMEM_G13 SMEM_MAIN
#define SMEM_G2  (SM_LNB + 512)

__device__ __forceinline__ uint32_t smem_u32(const void* p) {
    return (uint32_t)__cvta_generic_to_shared(p);
}
// 64B-row swizzle (128 rows x 32 fp16): conflict-free ldsm + cp.async.
__device__ __forceinline__ uint32_t swz(int row, int c16) {
    return (uint32_t)(row * 64 + ((c16 ^ ((row >> 1) & 3)) << 4));
}
// 256B-row swizzle (32 rows x 128 fp16) for the G3 trans-B tile.
__device__ __forceinline__ uint32_t swzbt(int row, int c16) {
    return (uint32_t)(row * 256 + ((c16 ^ (row & 7)) << 4));
}
__device__ __forceinline__ void ldsm4(uint32_t* r, uint32_t addr) {
    asm volatile("ldmatrix.sync.aligned.m8n8.x4.shared.b16 {%0,%1,%2,%3}, [%4];"
                 : "=r"(r[0]), "=r"(r[1]), "=r"(r[2]), "=r"(r[3]) : "r"(addr));
}
__device__ __forceinline__ void ldsm4t(uint32_t* r, uint32_t addr) {
    asm volatile("ldmatrix.sync.aligned.m8n8.x4.trans.shared.b16 {%0,%1,%2,%3}, [%4];"
                 : "=r"(r[0]), "=r"(r[1]), "=r"(r[2]), "=r"(r[3]) : "r"(addr));
}
__device__ __forceinline__ void mma_f16(float* c, const uint32_t* a,
                                        uint32_t b0, uint32_t b1) {
    asm volatile("mma.sync.aligned.m16n8k16.row.col.f32.f16.f16.f32 "
                 "{%0,%1,%2,%3}, {%4,%5,%6,%7}, {%8,%9}, {%0,%1,%2,%3};"
                 : "+f"(c[0]), "+f"(c[1]), "+f"(c[2]), "+f"(c[3])
                 : "r"(a[0]), "r"(a[1]), "r"(a[2]), "r"(a[3]), "r"(b0), "r"(b1));
}
__device__ __forceinline__ void cpa(uint32_t d, const void* g) {
    asm volatile("cp.async.cg.shared.global [%0], [%1], 16;"
                 :: "r"(d), "l"(g) : "memory");
}
__device__ __forceinline__ uint32_t pack2h(float x, float y) {
    __half2 h = __floats2half2_rn(x, y);
    return *(uint32_t*)&h;
}
__device__ __forceinline__ void split2h(float x, float y, uint32_t& h, uint32_t& l) {
    __half xh = __float2half_rn(x), yh = __float2half_rn(y);
    __half xl = __float2half_rn(x - __half2float(xh));
    __half yl = __float2half_rn(y - __half2float(yh));
    h = ((uint32_t)__half_as_ushort(yh) << 16) | __half_as_ushort(xh);
    l = ((uint32_t)__half_as_ushort(yl) << 16) | __half_as_ushort(xl);
}

// ---- one K32 chunk: acc += Ah·(Bh+Bl)^T --------------------------------------
__device__ __forceinline__ void compute_chunk(uint32_t st, float acc[4][4][4],
                                              const int* rowm, const int* rowb,
                                              int cgrp) {
#pragma unroll
    for (int ks = 0; ks < 2; ++ks) {
        const int cu = 2 * ks + cgrp;
        uint32_t bh[2][4], bl[2][4];
#pragma unroll
        for (int j = 0; j < 2; ++j) {
            ldsm4(bh[j], st + SM_T1 + swz(rowb[j], cu));
            ldsm4(bl[j], st + SM_T2 + swz(rowb[j], cu));
        }
        uint32_t a2[2][4];
        ldsm4(a2[0], st + SM_T0 + swz(rowm[0], cu));
#pragma unroll
        for (int mi = 0; mi < 4; ++mi) {
            const int cur = mi & 1;
            if (mi < 3) ldsm4(a2[cur ^ 1], st + SM_T0 + swz(rowm[mi + 1], cu));
#pragma unroll
            for (int nj = 0; nj < 4; ++nj) {
                const int j = nj >> 1, o = nj & 1;
                mma_f16(acc[mi][nj], a2[cur], bh[j][o], bh[j][o + 2]);
            }
#pragma unroll
            for (int nj = 0; nj < 4; ++nj) {
                const int j = nj >> 1, o = nj & 1;
                mma_f16(acc[mi][nj], a2[cur], bl[j][o], bl[j][o + 2]);
            }
        }
    }
}

// ---- one K32 chunk (G3): acc += (Ah+Al)·Bt -----------------------------------
__device__ __forceinline__ void compute_chunk_bt(uint32_t st, float acc[4][4][4],
                                                 const int* rowm, int nw,
                                                 int rin, int grp, int cgrp) {
#pragma unroll
    for (int ks = 0; ks < 2; ++ks) {
        const int cu = 2 * ks + cgrp;
        const int browk = 16 * ks + rin + ((grp >> 1) << 3);
        uint32_t bt[2][4];
#pragma unroll
        for (int j = 0; j < 2; ++j) {
            const int bc = (nw >> 3) + 2 * j + (grp & 1);
            ldsm4t(bt[j], st + SM_T2 + swzbt(browk, bc));
        }
        uint32_t ah[2][4], al[2][4];
        ldsm4(ah[0], st + SM_T0 + swz(rowm[0], cu));
        ldsm4(al[0], st + SM_T1 + swz(rowm[0], cu));
#pragma unroll
        for (int mi = 0; mi < 4; ++mi) {
            const int cur = mi & 1;
            if (mi < 3) {
                ldsm4(ah[cur ^ 1], st + SM_T0 + swz(rowm[mi + 1], cu));
                ldsm4(al[cur ^ 1], st + SM_T1 + swz(rowm[mi + 1], cu));
            }
#pragma unroll
            for (int nj = 0; nj < 4; ++nj) {
                const int j = nj >> 1, o = nj & 1;
                mma_f16(acc[mi][nj], ah[cur], bt[j][o], bt[j][o + 2]);
            }
#pragma unroll
            for (int nj = 0; nj < 4; ++nj) {
                const int j = nj >> 1, o = nj & 1;
                mma_f16(acc[mi][nj], al[cur], bt[j][o], bt[j][o + 2]);
            }
        }
    }
}

// ---- 3-stage pipelined mainloop: A single, B hi/lo ---------------------------
__device__ __forceinline__ void gemm_main(uint32_t smb, float acc[4][4][4],
    const unsigned short* A, int lda,
    const unsigned short* Bh, const unsigned short* Bl, int ldb, int K) {
    const int tid = threadIdx.x, lane = tid & 31, w = tid >> 5;
    const int mw = (w & 1) * 64, nw = (w >> 1) * 32;
    const int grp = lane >> 3, rin = lane & 7;
    int rowm[4], rowb[2];
#pragma unroll
    for (int mi = 0; mi < 4; ++mi) rowm[mi] = mw + mi * 16 + rin + ((grp & 1) << 3);
#pragma unroll
    for (int j = 0; j < 2; ++j)    rowb[j] = nw + j * 16 + rin + ((grp & 1) << 3);
    const int cgrp = grp >> 1;
    const int nch = K >> 5;

    uint32_t doff[2];
    const unsigned short *pA[2], *pBh[2], *pBl[2];
#pragma unroll
    for (int i = 0; i < 2; ++i) {
        int u = i * 256 + tid, row = u >> 2, c = u & 3;
        doff[i] = swz(row, c);
        pA[i]  = A  + (size_t)row * lda + c * 8;
        pBh[i] = Bh + (size_t)row * ldb + c * 8;
        pBl[i] = Bl + (size_t)row * ldb + c * 8;
    }
#pragma unroll
    for (int s = 0; s < 2; ++s) {
        const uint32_t st = smb + (uint32_t)s * STAGE;
#pragma unroll
        for (int i = 0; i < 2; ++i) {
            cpa(st + SM_T0 + doff[i], pA[i]);
            cpa(st + SM_T1 + doff[i], pBh[i]);
            cpa(st + SM_T2 + doff[i], pBl[i]);
            pA[i] += 32; pBh[i] += 32; pBl[i] += 32;
        }
        asm volatile("cp.async.commit_group;" ::: "memory");
    }
    uint32_t stg = 0;
    for (int c = 0; c < nch; ++c) {
        if (c == nch - 1) asm volatile("cp.async.wait_group 0;" ::: "memory");
        else              asm volatile("cp.async.wait_group 1;" ::: "memory");
        __syncthreads();
        if (c + 2 < nch) {
            uint32_t s2 = stg + 2; if (s2 >= NST) s2 -= NST;
            const uint32_t st2 = smb + s2 * STAGE;
#pragma unroll
            for (int i = 0; i < 2; ++i) {
                cpa(st2 + SM_T0 + doff[i], pA[i]);
                cpa(st2 + SM_T1 + doff[i], pBh[i]);
                cpa(st2 + SM_T2 + doff[i], pBl[i]);
                pA[i] += 32; pBh[i] += 32; pBl[i] += 32;
            }
            asm volatile("cp.async.commit_group;" ::: "memory");
        }
        compute_chunk(smb + stg * STAGE, acc, rowm, rowb, cgrp);
        if (++stg == NST) stg = 0;
    }
}

// ---- 3-stage pipelined mainloop (G3: A hi/lo, B single trans) ----------------
__device__ __forceinline__ void gemm_main_bt(uint32_t smb, float acc[4][4][4],
    const unsigned short* Ah, const unsigned short* Al, int lda,
    const unsigned short* B, int ldb, int v0, int K) {
    const int tid = threadIdx.x, lane = tid & 31, w = tid >> 5;
    const int mw = (w & 1) * 64, nw = (w >> 1) * 32;
    const int grp = lane >> 3, rin = lane & 7;
    int rowm[4];
#pragma unroll
    for (int mi = 0; mi < 4; ++mi) rowm[mi] = mw + mi * 16 + rin + ((grp & 1) << 3);
    const int cgrp = grp >> 1;
    const int nch = K >> 5;

    uint32_t doffA[2], doffB[2];
    const unsigned short *pAh[2], *pAl[2], *pB[2];
    const size_t bstep = (size_t)32 * ldb;
#pragma unroll
    for (int i = 0; i < 2; ++i) {
        int u = i * 256 + tid;
        int rowA = u >> 2, cA = u & 3;
        doffA[i] = swz(rowA, cA);
        pAh[i] = Ah + (size_t)rowA * lda + cA * 8;
        pAl[i] = Al + (size_t)rowA * lda + cA * 8;
        int rowB = u >> 4, cB = u & 15;
        doffB[i] = swzbt(rowB, cB);
        pB[i] = B + (size_t)rowB * ldb + v0 + cB * 8;
    }
#pragma unroll
    for (int s = 0; s < 2; ++s) {
        const uint32_t st = smb + (uint32_t)s * STAGE;
#pragma unroll
        for (int i = 0; i < 2; ++i) {
            cpa(st + SM_T0 + doffA[i], pAh[i]);
            cpa(st + SM_T1 + doffA[i], pAl[i]);
            cpa(st + SM_T2 + doffB[i], pB[i]);
            pAh[i] += 32; pAl[i] += 32; pB[i] += bstep;
        }
        asm volatile("cp.async.commit_group;" ::: "memory");
    }
    uint32_t stg = 0;
    for (int c = 0; c < nch; ++c) {
        if (c == nch - 1) asm volatile("cp.async.wait_group 0;" ::: "memory");
        else              asm volatile("cp.async.wait_group 1;" ::: "memory");
        __syncthreads();
        if (c + 2 < nch) {
            uint32_t s2 = stg + 2; if (s2 >= NST) s2 -= NST;
            const uint32_t st2 = smb + s2 * STAGE;
#pragma unroll
            for (int i = 0; i < 2; ++i) {
                cpa(st2 + SM_T0 + doffA[i], pAh[i]);
                cpa(st2 + SM_T1 + doffA[i], pAl[i]);
                cpa(st2 + SM_T2 + doffB[i], pB[i]);
                pAh[i] += 32; pAl[i] += 32; pB[i] += bstep;
            }
            asm volatile("cp.async.commit_group;" ::: "memory");
        }
        compute_chunk_bt(smb + stg * STAGE, acc, rowm, nw, rin, grp, cgrp);
        if (++stg == NST) stg = 0;
    }
}

// ---------------------------------------------------------------------------
// Preprocessing
// ---------------------------------------------------------------------------
__global__ void mask_fused(const unsigned char* __restrict__ m) {
    __shared__ int s_notbin, s_odd;
    if (threadIdx.x == 0) { s_notbin = 0; s_odd = 0; }
    __syncthreads();
    int notbin = 0, odd = 0;
    for (int i = threadIdx.x; i < CB * CN; i += blockDim.x) {
        unsigned char v = m[i];
        if (v > 1) notbin = 1;
        if ((i & 3) && v == 1) odd = 1;
    }
    if (notbin) atomicOr(&s_notbin, 1);
    if (odd)    atomicOr(&s_odd, 1);
    __syncthreads();
    const int md = s_notbin ? 2 : (s_odd ? 0 : 1);
    for (int i = threadIdx.x; i < CB * CN; i += blockDim.x) {
        float v;
        if (md == 0)      v = (m[i] != 0) ? 1.f : 0.f;
        else if (md == 1) v = (((const int*)(const void*)m)[i] != 0) ? 1.f : 0.f;
        else              v = (((const float*)(const void*)m)[i] != 0.f) ? 1.f : 0.f;
        g_maskf[i] = v;
    }
}

// One warp per 512-row: lin dot product + fp16 (hi only) write.
__global__ void __launch_bounds__(256) lin_split(const float* __restrict__ IN,
                                                 const float* __restrict__ AO,
                                                 const float* __restrict__ a_w,
                                                 const float* __restrict__ b_w) {
    int w = (blockIdx.x * blockDim.x + threadIdx.x) >> 5;
    int lane = threadIdx.x & 31;
    const int nAO = CB * CN;
    if (w >= nAO + CB * CT) return;
    const float* row; const float* wv; float* outd; int idx;
    uint32_t* dhi;
    if (w < nAO) {
        idx = w; row = AO + (size_t)w * CAD; wv = a_w; outd = g_lina;
        dhi = (uint32_t*)g_AOh + (size_t)w * 256;
    } else {
        idx = w - nAO; row = IN + (size_t)idx * CVD; wv = b_w; outd = g_linb;
        dhi = (uint32_t*)g_INh + (size_t)idx * 256;
    }
    float s = 0.f;
#pragma unroll
    for (int k = 0; k < 512; k += 128) {
        int e = k + lane * 4;
        float4 x = *(const float4*)(row + e);
        float4 y = *(const float4*)(wv + e);
        s += x.x * y.x + x.y * y.y + x.z * y.z + x.w * y.w;
        dhi[e >> 1]       = pack2h(x.x, x.y);
        dhi[(e >> 1) + 1] = pack2h(x.z, x.w);
    }
#pragma unroll
    for (int o = 16; o; o >>= 1) s += __shfl_xor_sync(0xffffffffu, s, o);
    if (lane == 0) outd[idx] = s;
}

// W(512x512) -> WT hi/lo (fp16 split)
__global__ void wt_split(const float* __restrict__ W) {
    __shared__ float t[32][33];
    int tx = threadIdx.x, ty = threadIdx.y;
    int a0 = blockIdx.y * 32, v0 = blockIdx.x * 32;
    for (int i = ty; i < 32; i += 8)
        t[i][tx] = W[(size_t)(a0 + i) * CVD + v0 + tx];
    __syncthreads();
    for (int i = ty; i < 32; i += 8) {
        float x = t[tx][i];
        __half h = __float2half_rn(x);
        __half l = __float2half_rn(x - __half2float(h));
        size_t o = (size_t)(v0 + i) * CAD + a0 + tx;
        g_WTh[o] = __half_as_ushort(h);
        g_WTl[o] = __half_as_ushort(l);
    }
}

// ---------------------------------------------------------------------------
// G1: aM = AOh @ (WTh+WTl)^T -> aM hi/lo.  grid (4 Ntiles, 128 Mtiles)
// ---------------------------------------------------------------------------
__global__ void __launch_bounds__(256, 2) g1_mma() {
    extern __shared__ char sm[];
    const uint32_t smb = smem_u32(sm);
    const int n0 = blockIdx.x * 128;
    const size_t m0 = (size_t)blockIdx.y * 128;
    float acc[4][4][4];
#pragma unroll
    for (int a = 0; a < 4; ++a)
#pragma unroll
        for (int b = 0; b < 4; ++b)
#pragma unroll
            for (int cc = 0; cc < 4; ++cc) acc[a][b][cc] = 0.f;

    gemm_main(smb, acc, g_AOh + m0 * CAD, CAD,
              g_WTh + (size_t)n0 * CAD, g_WTl + (size_t)n0 * CAD, CAD, CAD);

    const int lane = threadIdx.x & 31, w = threadIdx.x >> 5;
    const int mw = (w & 1) * 64, nw = (w >> 1) * 32;
    const int qr = lane >> 2, qc = (lane & 3) * 2;
    uint32_t* ghi = (uint32_t*)g_aMh;
    uint32_t* glo = (uint32_t*)g_aMl;
#pragma unroll
    for (int mi = 0; mi < 4; ++mi)
#pragma unroll
        for (int nj = 0; nj < 4; ++nj) {
            size_t r0 = m0 + mw + mi * 16 + qr;
            size_t cp = (size_t)(n0 + nw + nj * 8 + qc) >> 1;
            uint32_t h, l;
            split2h(acc[mi][nj][0], acc[mi][nj][1], h, l);
            ghi[r0 * (CVD >> 1) + cp] = h; glo[r0 * (CVD >> 1) + cp] = l;
            split2h(acc[mi][nj][2], acc[mi][nj][3], h, l);
            ghi[(r0 + 8) * (CVD >> 1) + cp] = h; glo[(r0 + 8) * (CVD >> 1) + cp] = l;
        }
}

// ---------------------------------------------------------------------------
// G2: sim = INh_tile @ (aMh+aMl)^T + fused tanh/masked-softmax -> attn hi/lo.
//     grid (2 Mtiles, B)
// ---------------------------------------------------------------------------
__global__ void __launch_bounds__(256, 2) g2_mma(const float* __restrict__ biasp) {
    extern __shared__ char sm[];
    const uint32_t smb = smem_u32(sm);
    const int tid = threadIdx.x;
    const int b = blockIdx.y;
    const int m0 = blockIdx.x * 128;
    float* sl  = (float*)(sm + SM_LIN);
    float* sk  = (float*)(sm + SM_MSK);
    float* slb = (float*)(sm + SM_LNB);
    if (tid < 128) {
        sl[tid]  = g_lina[b * CN + tid];
        sk[tid]  = g_maskf[b * CN + tid];
        slb[tid] = g_linb[b * CT + m0 + tid];
    }
    float acc[4][4][4];
#pragma unroll
    for (int a = 0; a < 4; ++a)
#pragma unroll
        for (int bb = 0; bb < 4; ++bb)
#pragma unroll
            for (int cc = 0; cc < 4; ++cc) acc[a][bb][cc] = 0.f;

    gemm_main(smb, acc,
              g_INh + ((size_t)b * CT + m0) * CVD, CVD,
              g_aMh + (size_t)b * CN * CVD,
              g_aMl + (size_t)b * CN * CVD, CVD, CVD);
    __syncthreads();

    const int lane = tid & 31, w = tid >> 5;
    const int mw = (w & 1) * 64, nw = (w >> 1) * 32;
    const int qr = lane >> 2, qc = (lane & 3) * 2;
    const float bs = biasp[0];
    float* ssim = (float*)sm;                      // 128 x 129 floats (66KB)
#pragma unroll
    for (int mi = 0; mi < 4; ++mi)
#pragma unroll
        for (int nj = 0; nj < 4; ++nj) {
            int c0 = nw + nj * 8 + qc;
            float sla = sl[c0], slA = sl[c0 + 1];
            float mk0 = sk[c0], mk1 = sk[c0 + 1];
#pragma unroll
            for (int p = 0; p < 2; ++p) {
                int r = mw + mi * 16 + qr + p * 8;
                float lb = slb[r] + bs;
                float e0 = mk0 * __expf(tanhf(acc[mi][nj][2 * p] + sla + lb));
                float e1 = mk1 * __expf(tanhf(acc[mi][nj][2 * p + 1] + slA + lb));
                ssim[r * 129 + c0] = e0;
                ssim[r * 129 + c0 + 1] = e1;
            }
        }
    __syncthreads();
    {
        const int r = tid >> 1, half = tid & 1;
        const float* rowp = ssim + r * 129;
        float s = 0.f;
#pragma unroll
        for (int n = 0; n < 64; ++n) s += rowp[half * 64 + n];
        s += __shfl_xor_sync(0xffffffffu, s, 1);
        const float inv = 1.0f / (s + 1e-30f);
        const size_t t = (size_t)b * CT + m0 + r;
        uint32_t* ohi = (uint32_t*)g_ath + t * 64;
        uint32_t* olo = (uint32_t*)g_atl + t * 64;
#pragma unroll
        for (int jj = 0; jj < 32; ++jj) {
            int j = half * 32 + jj;
            uint32_t h, l;
            split2h(rowp[2 * j] * inv, rowp[2 * j + 1] * inv, h, l);
            ohi[j] = h; olo[j] = l;
        }
    }
}

// ---------------------------------------------------------------------------
// G3: out = (attnh+attnl) @ AOh (B trans).  grid (4 Ntiles, 2 Mtiles, B)
// ---------------------------------------------------------------------------
__global__ void __launch_bounds__(256, 2) g3_mma(float* __restrict__ OUT) {
    extern __shared__ char sm[];
    const uint32_t smb = smem_u32(sm);
    const int b = blockIdx.z;
    const int m0 = blockIdx.y * 128;
    const int n0 = blockIdx.x * 128;
    float acc[4][4][4];
#pragma unroll
    for (int a = 0; a < 4; ++a)
#pragma unroll
        for (int bb = 0; bb < 4; ++bb)
#pragma unroll
            for (int cc = 0; cc < 4; ++cc) acc[a][bb][cc] = 0.f;

    gemm_main_bt(smb, acc,
                 g_ath + ((size_t)b * CT + m0) * CN,
                 g_atl + ((size_t)b * CT + m0) * CN, CN,
                 g_AOh + (size_t)b * CN * CAD, CAD, n0, CN);

    const int lane = threadIdx.x & 31, w = threadIdx.x >> 5;
    const int mw = (w & 1) * 64, nw = (w >> 1) * 32;
    const int qr = lane >> 2, qc = (lane & 3) * 2;
#pragma unroll
    for (int mi = 0; mi < 4; ++mi)
#pragma unroll
        for (int nj = 0; nj < 4; ++nj) {
            size_t r0 = (size_t)b * CT + m0 + mw + mi * 16 + qr;
            int gc = n0 + nw + nj * 8 + qc;
            *(float2*)(OUT + r0 * CAD + gc) =
                make_float2(acc[mi][nj][0], acc[mi][nj][1]);
            *(float2*)(OUT + (r0 + 8) * CAD + gc) =
                make_float2(acc[mi][nj][2], acc[mi][nj][3]);
        }
}

// ---------------------------------------------------------------------------
extern "C" void kernel_launch(void* const* d_in, const int* in_sizes, int n_in,
                              void* d_out, int out_size) {
    const float* inputs = (const float*)d_in[0];
    const float* ao     = (const float*)d_in[1];
    const void*  mask   = d_in[2];
    const float* W      = (const float*)d_in[3];
    const float* a_w    = (const float*)d_in[4];
    const float* b_w    = (const float*)d_in[5];
    const float* bias   = (const float*)d_in[6];
    float* out = (float*)d_out;

    cudaFuncSetAttribute(g1_mma, cudaFuncAttributeMaxDynamicSharedMemorySize, SMEM_G13);
    cudaFuncSetAttribute(g2_mma, cudaFuncAttributeMaxDynamicSharedMemorySize, SMEM_G2);
    cudaFuncSetAttribute(g3_mma, cudaFuncAttributeMaxDynamicSharedMemorySize, SMEM_G13);

    // g1_mma stays at launch index 3 (the profiled slot)
    mask_fused<<<1, 1024>>>((const unsigned char*)mask);                 // 0
    int nwarps = CB * CN + CB * CT;
    lin_split<<<(nwarps * 32 + 255) / 256, 256>>>(inputs, ao, a_w, b_w); // 1
    wt_split<<<dim3(16, 16), dim3(32, 8)>>>(W);                          // 2
    g1_mma<<<dim3(4, 128), 256, SMEM_G13>>>();                           // 3
    g2_mma<<<dim3(2, CB), 256, SMEM_G2>>>(bias);                         // 4
    g3_mma<<<dim3(4, 2, CB), 256, SMEM_G13>>>(out);                      // 5
}

// round 8
// speedup vs baseline: 3.7500x; 1.1431x over previous
#include <cuda_runtime.h>
#include <cuda_fp16.h>
#include <cstdint>

// ---------------------------------------------------------------------------
// GeneralizedBilinearAttention via mma.sync fp16 (base sm_103 ISA).
//   G1: aM   = AOh(16384x512) @ WTh(512x512)          [1 product]
//   G2: sim  = INh(256x512) @ (aMh+aMl)^T + tanh/masked-softmax  [2 products]
//   G3: out  = (attnh+attnl)(256x128) @ AOh(128x512)  [2 products, B trans]
// fp32 acc everywhere. K32 chunks, 3-stage cp.async pipeline.
// ---------------------------------------------------------------------------

#define CB 128
#define CT 256
#define CN 128
#define CAD 512
#define CVD 512

__device__ __align__(16) unsigned short g_AOh[CB * CN * CAD];
__device__ __align__(16) unsigned short g_INh[CB * CT * CVD];
__device__ __align__(16) unsigned short g_WTh[CVD * CAD];
__device__ __align__(16) unsigned short g_aMh[CB * CN * CVD];
__device__ __align__(16) unsigned short g_aMl[CB * CN * CVD];
__device__ __align__(16) unsigned short g_ath[CB * CT * CN];
__device__ __align__(16) unsigned short g_atl[CB * CT * CN];
__device__ __align__(16) float g_lina[CB * CN];
__device__ __align__(16) float g_linb[CB * CT];
__device__ __align__(16) float g_maskf[CB * CN];

// ---- smem layouts -------------------------------------------------------------
#define TILEB 8192
// 3-tile stage (G2: A, Bh, Bl | G3: attn-hi, attn-lo, AO-trans)
#define SM_T0 0
#define SM_T1 TILEB
#define SM_T2 (2 * TILEB)
#define STAGE  (3 * TILEB)           // 24576
// 2-tile stage (G1: A, Bh)
#define STAGE1 (2 * TILEB)           // 16384
#define NST 3
#define SMEM_MAIN (NST * STAGE)      // 73728
#define SMEM_G1   (NST * STAGE1)     // 49152
#define SM_LIN SMEM_MAIN
#define SM_MSK (SM_LIN + 512)
#define SM_LNB (SM_MSK + 512)
#define SMEM_G3 SMEM_MAIN
#define SMEM_G2 (SM_LNB + 512)

__device__ __forceinline__ uint32_t smem_u32(const void* p) {
    return (uint32_t)__cvta_generic_to_shared(p);
}
__device__ __forceinline__ uint32_t swz(int row, int c16) {
    return (uint32_t)(row * 64 + ((c16 ^ ((row >> 1) & 3)) << 4));
}
__device__ __forceinline__ uint32_t swzbt(int row, int c16) {
    return (uint32_t)(row * 256 + ((c16 ^ (row & 7)) << 4));
}
__device__ __forceinline__ void ldsm4(uint32_t* r, uint32_t addr) {
    asm volatile("ldmatrix.sync.aligned.m8n8.x4.shared.b16 {%0,%1,%2,%3}, [%4];"
                 : "=r"(r[0]), "=r"(r[1]), "=r"(r[2]), "=r"(r[3]) : "r"(addr));
}
__device__ __forceinline__ void ldsm4t(uint32_t* r, uint32_t addr) {
    asm volatile("ldmatrix.sync.aligned.m8n8.x4.trans.shared.b16 {%0,%1,%2,%3}, [%4];"
                 : "=r"(r[0]), "=r"(r[1]), "=r"(r[2]), "=r"(r[3]) : "r"(addr));
}
__device__ __forceinline__ void mma_f16(float* c, const uint32_t* a,
                                        uint32_t b0, uint32_t b1) {
    asm volatile("mma.sync.aligned.m16n8k16.row.col.f32.f16.f16.f32 "
                 "{%0,%1,%2,%3}, {%4,%5,%6,%7}, {%8,%9}, {%0,%1,%2,%3};"
                 : "+f"(c[0]), "+f"(c[1]), "+f"(c[2]), "+f"(c[3])
                 : "r"(a[0]), "r"(a[1]), "r"(a[2]), "r"(a[3]), "r"(b0), "r"(b1));
}
__device__ __forceinline__ void cpa(uint32_t d, const void* g) {
    asm volatile("cp.async.cg.shared.global [%0], [%1], 16;"
                 :: "r"(d), "l"(g) : "memory");
}
__device__ __forceinline__ uint32_t pack2h(float x, float y) {
    __half2 h = __floats2half2_rn(x, y);
    return *(uint32_t*)&h;
}
__device__ __forceinline__ void split2h(float x, float y, uint32_t& h, uint32_t& l) {
    __half xh = __float2half_rn(x), yh = __float2half_rn(y);
    __half xl = __float2half_rn(x - __half2float(xh));
    __half yl = __float2half_rn(y - __half2float(yh));
    h = ((uint32_t)__half_as_ushort(yh) << 16) | __half_as_ushort(xh);
    l = ((uint32_t)__half_as_ushort(yl) << 16) | __half_as_ushort(xl);
}

// ---- one K32 chunk: acc += A·Bh^T (single product, G1) -----------------------
__device__ __forceinline__ void compute_chunk1(uint32_t st, float acc[4][4][4],
                                               const int* rowm, const int* rowb,
                                               int cgrp) {
#pragma unroll
    for (int ks = 0; ks < 2; ++ks) {
        const int cu = 2 * ks + cgrp;
        uint32_t bh[2][4];
#pragma unroll
        for (int j = 0; j < 2; ++j)
            ldsm4(bh[j], st + SM_T1 + swz(rowb[j], cu));
        uint32_t a2[2][4];
        ldsm4(a2[0], st + SM_T0 + swz(rowm[0], cu));
#pragma unroll
        for (int mi = 0; mi < 4; ++mi) {
            const int cur = mi & 1;
            if (mi < 3) ldsm4(a2[cur ^ 1], st + SM_T0 + swz(rowm[mi + 1], cu));
#pragma unroll
            for (int nj = 0; nj < 4; ++nj) {
                const int j = nj >> 1, o = nj & 1;
                mma_f16(acc[mi][nj], a2[cur], bh[j][o], bh[j][o + 2]);
            }
        }
    }
}

// ---- one K32 chunk: acc += A·(Bh+Bl)^T (G2) ----------------------------------
__device__ __forceinline__ void compute_chunk(uint32_t st, float acc[4][4][4],
                                              const int* rowm, const int* rowb,
                                              int cgrp) {
#pragma unroll
    for (int ks = 0; ks < 2; ++ks) {
        const int cu = 2 * ks + cgrp;
        uint32_t bh[2][4], bl[2][4];
#pragma unroll
        for (int j = 0; j < 2; ++j) {
            ldsm4(bh[j], st + SM_T1 + swz(rowb[j], cu));
            ldsm4(bl[j], st + SM_T2 + swz(rowb[j], cu));
        }
        uint32_t a2[2][4];
        ldsm4(a2[0], st + SM_T0 + swz(rowm[0], cu));
#pragma unroll
        for (int mi = 0; mi < 4; ++mi) {
            const int cur = mi & 1;
            if (mi < 3) ldsm4(a2[cur ^ 1], st + SM_T0 + swz(rowm[mi + 1], cu));
#pragma unroll
            for (int nj = 0; nj < 4; ++nj) {
                const int j = nj >> 1, o = nj & 1;
                mma_f16(acc[mi][nj], a2[cur], bh[j][o], bh[j][o + 2]);
            }
#pragma unroll
            for (int nj = 0; nj < 4; ++nj) {
                const int j = nj >> 1, o = nj & 1;
                mma_f16(acc[mi][nj], a2[cur], bl[j][o], bl[j][o + 2]);
            }
        }
    }
}

// ---- one K32 chunk (G3): acc += (Ah+Al)·Bt -----------------------------------
__device__ __forceinline__ void compute_chunk_bt(uint32_t st, float acc[4][4][4],
                                                 const int* rowm, int nw,
                                                 int rin, int grp, int cgrp) {
#pragma unroll
    for (int ks = 0; ks < 2; ++ks) {
        const int cu = 2 * ks + cgrp;
        const int browk = 16 * ks + rin + ((grp >> 1) << 3);
        uint32_t bt[2][4];
#pragma unroll
        for (int j = 0; j < 2; ++j) {
            const int bc = (nw >> 3) + 2 * j + (grp & 1);
            ldsm4t(bt[j], st + SM_T2 + swzbt(browk, bc));
        }
        uint32_t ah[2][4], al[2][4];
        ldsm4(ah[0], st + SM_T0 + swz(rowm[0], cu));
        ldsm4(al[0], st + SM_T1 + swz(rowm[0], cu));
#pragma unroll
        for (int mi = 0; mi < 4; ++mi) {
            const int cur = mi & 1;
            if (mi < 3) {
                ldsm4(ah[cur ^ 1], st + SM_T0 + swz(rowm[mi + 1], cu));
                ldsm4(al[cur ^ 1], st + SM_T1 + swz(rowm[mi + 1], cu));
            }
#pragma unroll
            for (int nj = 0; nj < 4; ++nj) {
                const int j = nj >> 1, o = nj & 1;
                mma_f16(acc[mi][nj], ah[cur], bt[j][o], bt[j][o + 2]);
            }
#pragma unroll
            for (int nj = 0; nj < 4; ++nj) {
                const int j = nj >> 1, o = nj & 1;
                mma_f16(acc[mi][nj], al[cur], bt[j][o], bt[j][o + 2]);
            }
        }
    }
}

// ---- mainloop G1: single product, 2-tile stage --------------------------------
__device__ __forceinline__ void gemm_main1(uint32_t smb, float acc[4][4][4],
    const unsigned short* A, int lda,
    const unsigned short* Bh, int ldb, int K) {
    const int tid = threadIdx.x, lane = tid & 31, w = tid >> 5;
    const int mw = (w & 1) * 64, nw = (w >> 1) * 32;
    const int grp = lane >> 3, rin = lane & 7;
    int rowm[4], rowb[2];
#pragma unroll
    for (int mi = 0; mi < 4; ++mi) rowm[mi] = mw + mi * 16 + rin + ((grp & 1) << 3);
#pragma unroll
    for (int j = 0; j < 2; ++j)    rowb[j] = nw + j * 16 + rin + ((grp & 1) << 3);
    const int cgrp = grp >> 1;
    const int nch = K >> 5;

    uint32_t doff[2];
    const unsigned short *pA[2], *pBh[2];
#pragma unroll
    for (int i = 0; i < 2; ++i) {
        int u = i * 256 + tid, row = u >> 2, c = u & 3;
        doff[i] = swz(row, c);
        pA[i]  = A  + (size_t)row * lda + c * 8;
        pBh[i] = Bh + (size_t)row * ldb + c * 8;
    }
#pragma unroll
    for (int s = 0; s < 2; ++s) {
        const uint32_t st = smb + (uint32_t)s * STAGE1;
#pragma unroll
        for (int i = 0; i < 2; ++i) {
            cpa(st + SM_T0 + doff[i], pA[i]);
            cpa(st + SM_T1 + doff[i], pBh[i]);
            pA[i] += 32; pBh[i] += 32;
        }
        asm volatile("cp.async.commit_group;" ::: "memory");
    }
    uint32_t stg = 0;
    for (int c = 0; c < nch; ++c) {
        if (c == nch - 1) asm volatile("cp.async.wait_group 0;" ::: "memory");
        else              asm volatile("cp.async.wait_group 1;" ::: "memory");
        __syncthreads();
        if (c + 2 < nch) {
            uint32_t s2 = stg + 2; if (s2 >= NST) s2 -= NST;
            const uint32_t st2 = smb + s2 * STAGE1;
#pragma unroll
            for (int i = 0; i < 2; ++i) {
                cpa(st2 + SM_T0 + doff[i], pA[i]);
                cpa(st2 + SM_T1 + doff[i], pBh[i]);
                pA[i] += 32; pBh[i] += 32;
            }
            asm volatile("cp.async.commit_group;" ::: "memory");
        }
        compute_chunk1(smb + stg * STAGE1, acc, rowm, rowb, cgrp);
        if (++stg == NST) stg = 0;
    }
}

// ---- mainloop G2: A single, B hi/lo -------------------------------------------
__device__ __forceinline__ void gemm_main(uint32_t smb, float acc[4][4][4],
    const unsigned short* A, int lda,
    const unsigned short* Bh, const unsigned short* Bl, int ldb, int K) {
    const int tid = threadIdx.x, lane = tid & 31, w = tid >> 5;
    const int mw = (w & 1) * 64, nw = (w >> 1) * 32;
    const int grp = lane >> 3, rin = lane & 7;
    int rowm[4], rowb[2];
#pragma unroll
    for (int mi = 0; mi < 4; ++mi) rowm[mi] = mw + mi * 16 + rin + ((grp & 1) << 3);
#pragma unroll
    for (int j = 0; j < 2; ++j)    rowb[j] = nw + j * 16 + rin + ((grp & 1) << 3);
    const int cgrp = grp >> 1;
    const int nch = K >> 5;

    uint32_t doff[2];
    const unsigned short *pA[2], *pBh[2], *pBl[2];
#pragma unroll
    for (int i = 0; i < 2; ++i) {
        int u = i * 256 + tid, row = u >> 2, c = u & 3;
        doff[i] = swz(row, c);
        pA[i]  = A  + (size_t)row * lda + c * 8;
        pBh[i] = Bh + (size_t)row * ldb + c * 8;
        pBl[i] = Bl + (size_t)row * ldb + c * 8;
    }
#pragma unroll
    for (int s = 0; s < 2; ++s) {
        const uint32_t st = smb + (uint32_t)s * STAGE;
#pragma unroll
        for (int i = 0; i < 2; ++i) {
            cpa(st + SM_T0 + doff[i], pA[i]);
            cpa(st + SM_T1 + doff[i], pBh[i]);
            cpa(st + SM_T2 + doff[i], pBl[i]);
            pA[i] += 32; pBh[i] += 32; pBl[i] += 32;
        }
        asm volatile("cp.async.commit_group;" ::: "memory");
    }
    uint32_t stg = 0;
    for (int c = 0; c < nch; ++c) {
        if (c == nch - 1) asm volatile("cp.async.wait_group 0;" ::: "memory");
        else              asm volatile("cp.async.wait_group 1;" ::: "memory");
        __syncthreads();
        if (c + 2 < nch) {
            uint32_t s2 = stg + 2; if (s2 >= NST) s2 -= NST;
            const uint32_t st2 = smb + s2 * STAGE;
#pragma unroll
            for (int i = 0; i < 2; ++i) {
                cpa(st2 + SM_T0 + doff[i], pA[i]);
                cpa(st2 + SM_T1 + doff[i], pBh[i]);
                cpa(st2 + SM_T2 + doff[i], pBl[i]);
                pA[i] += 32; pBh[i] += 32; pBl[i] += 32;
            }
            asm volatile("cp.async.commit_group;" ::: "memory");
        }
        compute_chunk(smb + stg * STAGE, acc, rowm, rowb, cgrp);
        if (++stg == NST) stg = 0;
    }
}

// ---- mainloop G3: A hi/lo, B single trans --------------------------------------
__device__ __forceinline__ void gemm_main_bt(uint32_t smb, float acc[4][4][4],
    const unsigned short* Ah, const unsigned short* Al, int lda,
    const unsigned short* B, int ldb, int v0, int K) {
    const int tid = threadIdx.x, lane = tid & 31, w = tid >> 5;
    const int mw = (w & 1) * 64, nw = (w >> 1) * 32;
    const int grp = lane >> 3, rin = lane & 7;
    int rowm[4];
#pragma unroll
    for (int mi = 0; mi < 4; ++mi) rowm[mi] = mw + mi * 16 + rin + ((grp & 1) << 3);
    const int cgrp = grp >> 1;
    const int nch = K >> 5;

    uint32_t doffA[2], doffB[2];
    const unsigned short *pAh[2], *pAl[2], *pB[2];
    const size_t bstep = (size_t)32 * ldb;
#pragma unroll
    for (int i = 0; i < 2; ++i) {
        int u = i * 256 + tid;
        int rowA = u >> 2, cA = u & 3;
        doffA[i] = swz(rowA, cA);
        pAh[i] = Ah + (size_t)rowA * lda + cA * 8;
        pAl[i] = Al + (size_t)rowA * lda + cA * 8;
        int rowB = u >> 4, cB = u & 15;
        doffB[i] = swzbt(rowB, cB);
        pB[i] = B + (size_t)rowB * ldb + v0 + cB * 8;
    }
#pragma unroll
    for (int s = 0; s < 2; ++s) {
        const uint32_t st = smb + (uint32_t)s * STAGE;
#pragma unroll
        for (int i = 0; i < 2; ++i) {
            cpa(st + SM_T0 + doffA[i], pAh[i]);
            cpa(st + SM_T1 + doffA[i], pAl[i]);
            cpa(st + SM_T2 + doffB[i], pB[i]);
            pAh[i] += 32; pAl[i] += 32; pB[i] += bstep;
        }
        asm volatile("cp.async.commit_group;" ::: "memory");
    }
    uint32_t stg = 0;
    for (int c = 0; c < nch; ++c) {
        if (c == nch - 1) asm volatile("cp.async.wait_group 0;" ::: "memory");
        else              asm volatile("cp.async.wait_group 1;" ::: "memory");
        __syncthreads();
        if (c + 2 < nch) {
            uint32_t s2 = stg + 2; if (s2 >= NST) s2 -= NST;
            const uint32_t st2 = smb + s2 * STAGE;
#pragma unroll
            for (int i = 0; i < 2; ++i) {
                cpa(st2 + SM_T0 + doffA[i], pAh[i]);
                cpa(st2 + SM_T1 + doffA[i], pAl[i]);
                cpa(st2 + SM_T2 + doffB[i], pB[i]);
                pAh[i] += 32; pAl[i] += 32; pB[i] += bstep;
            }
            asm volatile("cp.async.commit_group;" ::: "memory");
        }
        compute_chunk_bt(smb + stg * STAGE, acc, rowm, nw, rin, grp, cgrp);
        if (++stg == NST) stg = 0;
    }
}

// ---------------------------------------------------------------------------
// Preprocessing
// ---------------------------------------------------------------------------
__global__ void mask_fused(const unsigned char* __restrict__ m) {
    __shared__ int s_notbin, s_odd;
    if (threadIdx.x == 0) { s_notbin = 0; s_odd = 0; }
    __syncthreads();
    int notbin = 0, odd = 0;
    for (int i = threadIdx.x; i < CB * CN; i += blockDim.x) {
        unsigned char v = m[i];
        if (v > 1) notbin = 1;
        if ((i & 3) && v == 1) odd = 1;
    }
    if (notbin) atomicOr(&s_notbin, 1);
    if (odd)    atomicOr(&s_odd, 1);
    __syncthreads();
    const int md = s_notbin ? 2 : (s_odd ? 0 : 1);
    for (int i = threadIdx.x; i < CB * CN; i += blockDim.x) {
        float v;
        if (md == 0)      v = (m[i] != 0) ? 1.f : 0.f;
        else if (md == 1) v = (((const int*)(const void*)m)[i] != 0) ? 1.f : 0.f;
        else              v = (((const float*)(const void*)m)[i] != 0.f) ? 1.f : 0.f;
        g_maskf[i] = v;
    }
}

__global__ void __launch_bounds__(256) lin_split(const float* __restrict__ IN,
                                                 const float* __restrict__ AO,
                                                 const float* __restrict__ a_w,
                                                 const float* __restrict__ b_w) {
    int w = (blockIdx.x * blockDim.x + threadIdx.x) >> 5;
    int lane = threadIdx.x & 31;
    const int nAO = CB * CN;
    if (w >= nAO + CB * CT) return;
    const float* row; const float* wv; float* outd; int idx;
    uint32_t* dhi;
    if (w < nAO) {
        idx = w; row = AO + (size_t)w * CAD; wv = a_w; outd = g_lina;
        dhi = (uint32_t*)g_AOh + (size_t)w * 256;
    } else {
        idx = w - nAO; row = IN + (size_t)idx * CVD; wv = b_w; outd = g_linb;
        dhi = (uint32_t*)g_INh + (size_t)idx * 256;
    }
    float s = 0.f;
#pragma unroll
    for (int k = 0; k < 512; k += 128) {
        int e = k + lane * 4;
        float4 x = *(const float4*)(row + e);
        float4 y = *(const float4*)(wv + e);
        s += x.x * y.x + x.y * y.y + x.z * y.z + x.w * y.w;
        dhi[e >> 1]       = pack2h(x.x, x.y);
        dhi[(e >> 1) + 1] = pack2h(x.z, x.w);
    }
#pragma unroll
    for (int o = 16; o; o >>= 1) s += __shfl_xor_sync(0xffffffffu, s, o);
    if (lane == 0) outd[idx] = s;
}

// W(512x512) -> WT hi (fp16)
__global__ void wt_split(const float* __restrict__ W) {
    __shared__ float t[32][33];
    int tx = threadIdx.x, ty = threadIdx.y;
    int a0 = blockIdx.y * 32, v0 = blockIdx.x * 32;
    for (int i = ty; i < 32; i += 8)
        t[i][tx] = W[(size_t)(a0 + i) * CVD + v0 + tx];
    __syncthreads();
    for (int i = ty; i < 32; i += 8) {
        float x = t[tx][i];
        g_WTh[(size_t)(v0 + i) * CAD + a0 + tx] =
            __half_as_ushort(__float2half_rn(x));
    }
}

// ---------------------------------------------------------------------------
// G1: aM = AOh @ WTh^T -> aM hi/lo.  grid (4 Ntiles, 128 Mtiles)
// ---------------------------------------------------------------------------
__global__ void __launch_bounds__(256, 2) g1_mma() {
    extern __shared__ char sm[];
    const uint32_t smb = smem_u32(sm);
    const int n0 = blockIdx.x * 128;
    const size_t m0 = (size_t)blockIdx.y * 128;
    float acc[4][4][4];
#pragma unroll
    for (int a = 0; a < 4; ++a)
#pragma unroll
        for (int b = 0; b < 4; ++b)
#pragma unroll
            for (int cc = 0; cc < 4; ++cc) acc[a][b][cc] = 0.f;

    gemm_main1(smb, acc, g_AOh + m0 * CAD, CAD,
               g_WTh + (size_t)n0 * CAD, CAD, CAD);

    const int lane = threadIdx.x & 31, w = threadIdx.x >> 5;
    const int mw = (w & 1) * 64, nw = (w >> 1) * 32;
    const int qr = lane >> 2, qc = (lane & 3) * 2;
    uint32_t* ghi = (uint32_t*)g_aMh;
    uint32_t* glo = (uint32_t*)g_aMl;
#pragma unroll
    for (int mi = 0; mi < 4; ++mi)
#pragma unroll
        for (int nj = 0; nj < 4; ++nj) {
            size_t r0 = m0 + mw + mi * 16 + qr;
            size_t cp = (size_t)(n0 + nw + nj * 8 + qc) >> 1;
            uint32_t h, l;
            split2h(acc[mi][nj][0], acc[mi][nj][1], h, l);
            ghi[r0 * (CVD >> 1) + cp] = h; glo[r0 * (CVD >> 1) + cp] = l;
            split2h(acc[mi][nj][2], acc[mi][nj][3], h, l);
            ghi[(r0 + 8) * (CVD >> 1) + cp] = h; glo[(r0 + 8) * (CVD >> 1) + cp] = l;
        }
}

// ---------------------------------------------------------------------------
// G2: sim = INh_tile @ (aMh+aMl)^T + fused tanh/masked-softmax -> attn hi/lo.
// ---------------------------------------------------------------------------
__global__ void __launch_bounds__(256, 2) g2_mma(const float* __restrict__ biasp) {
    extern __shared__ char sm[];
    const uint32_t smb = smem_u32(sm);
    const int tid = threadIdx.x;
    const int b = blockIdx.y;
    const int m0 = blockIdx.x * 128;
    float* sl  = (float*)(sm + SM_LIN);
    float* sk  = (float*)(sm + SM_MSK);
    float* slb = (float*)(sm + SM_LNB);
    if (tid < 128) {
        sl[tid]  = g_lina[b * CN + tid];
        sk[tid]  = g_maskf[b * CN + tid];
        slb[tid] = g_linb[b * CT + m0 + tid];
    }
    float acc[4][4][4];
#pragma unroll
    for (int a = 0; a < 4; ++a)
#pragma unroll
        for (int bb = 0; bb < 4; ++bb)
#pragma unroll
            for (int cc = 0; cc < 4; ++cc) acc[a][bb][cc] = 0.f;

    gemm_main(smb, acc,
              g_INh + ((size_t)b * CT + m0) * CVD, CVD,
              g_aMh + (size_t)b * CN * CVD,
              g_aMl + (size_t)b * CN * CVD, CVD, CVD);
    __syncthreads();

    const int lane = tid & 31, w = tid >> 5;
    const int mw = (w & 1) * 64, nw = (w >> 1) * 32;
    const int qr = lane >> 2, qc = (lane & 3) * 2;
    const float bs = biasp[0];
    float* ssim = (float*)sm;
#pragma unroll
    for (int mi = 0; mi < 4; ++mi)
#pragma unroll
        for (int nj = 0; nj < 4; ++nj) {
            int c0 = nw + nj * 8 + qc;
            float sla = sl[c0], slA = sl[c0 + 1];
            float mk0 = sk[c0], mk1 = sk[c0 + 1];
#pragma unroll
            for (int p = 0; p < 2; ++p) {
                int r = mw + mi * 16 + qr + p * 8;
                float lb = slb[r] + bs;
                float e0 = mk0 * __expf(tanhf(acc[mi][nj][2 * p] + sla + lb));
                float e1 = mk1 * __expf(tanhf(acc[mi][nj][2 * p + 1] + slA + lb));
                ssim[r * 129 + c0] = e0;
                ssim[r * 129 + c0 + 1] = e1;
            }
        }
    __syncthreads();
    {
        const int r = tid >> 1, half = tid & 1;
        const float* rowp = ssim + r * 129;
        float s = 0.f;
#pragma unroll
        for (int n = 0; n < 64; ++n) s += rowp[half * 64 + n];
        s += __shfl_xor_sync(0xffffffffu, s, 1);
        const float inv = 1.0f / (s + 1e-30f);
        const size_t t = (size_t)b * CT + m0 + r;
        uint32_t* ohi = (uint32_t*)g_ath + t * 64;
        uint32_t* olo = (uint32_t*)g_atl + t * 64;
#pragma unroll
        for (int jj = 0; jj < 32; ++jj) {
            int j = half * 32 + jj;
            uint32_t h, l;
            split2h(rowp[2 * j] * inv, rowp[2 * j + 1] * inv, h, l);
            ohi[j] = h; olo[j] = l;
        }
    }
}

// ---------------------------------------------------------------------------
// G3: out = (attnh+attnl) @ AOh (B trans).  grid (4 Ntiles, 2 Mtiles, B)
// ---------------------------------------------------------------------------
__global__ void __launch_bounds__(256, 2) g3_mma(float* __restrict__ OUT) {
    extern __shared__ char sm[];
    const uint32_t smb = smem_u32(sm);
    const int b = blockIdx.z;
    const int m0 = blockIdx.y * 128;
    const int n0 = blockIdx.x * 128;
    float acc[4][4][4];
#pragma unroll
    for (int a = 0; a < 4; ++a)
#pragma unroll
        for (int bb = 0; bb < 4; ++bb)
#pragma unroll
            for (int cc = 0; cc < 4; ++cc) acc[a][bb][cc] = 0.f;

    gemm_main_bt(smb, acc,
                 g_ath + ((size_t)b * CT + m0) * CN,
                 g_atl + ((size_t)b * CT + m0) * CN, CN,
                 g_AOh + (size_t)b * CN * CAD, CAD, n0, CN);

    const int lane = threadIdx.x & 31, w = threadIdx.x >> 5;
    const int mw = (w & 1) * 64, nw = (w >> 1) * 32;
    const int qr = lane >> 2, qc = (lane & 3) * 2;
#pragma unroll
    for (int mi = 0; mi < 4; ++mi)
#pragma unroll
        for (int nj = 0; nj < 4; ++nj) {
            size_t r0 = (size_t)b * CT + m0 + mw + mi * 16 + qr;
            int gc = n0 + nw + nj * 8 + qc;
            *(float2*)(OUT + r0 * CAD + gc) =
                make_float2(acc[mi][nj][0], acc[mi][nj][1]);
            *(float2*)(OUT + (r0 + 8) * CAD + gc) =
                make_float2(acc[mi][nj][2], acc[mi][nj][3]);
        }
}

// ---------------------------------------------------------------------------
extern "C" void kernel_launch(void* const* d_in, const int* in_sizes, int n_in,
                              void* d_out, int out_size) {
    const float* inputs = (const float*)d_in[0];
    const float* ao     = (const float*)d_in[1];
    const void*  mask   = d_in[2];
    const float* W      = (const float*)d_in[3];
    const float* a_w    = (const float*)d_in[4];
    const float* b_w    = (const float*)d_in[5];
    const float* bias   = (const float*)d_in[6];
    float* out = (float*)d_out;

    cudaFuncSetAttribute(g1_mma, cudaFuncAttributeMaxDynamicSharedMemorySize, SMEM_G1);
    cudaFuncSetAttribute(g2_mma, cudaFuncAttributeMaxDynamicSharedMemorySize, SMEM_G2);
    cudaFuncSetAttribute(g3_mma, cudaFuncAttributeMaxDynamicSharedMemorySize, SMEM_G3);

    // g1_mma stays at launch index 3 (the profiled slot)
    mask_fused<<<1, 1024>>>((const unsigned char*)mask);                 // 0
    int nwarps = CB * CN + CB * CT;
    lin_split<<<(nwarps * 32 + 255) / 256, 256>>>(inputs, ao, a_w, b_w); // 1
    wt_split<<<dim3(16, 16), dim3(32, 8)>>>(W);                          // 2
    g1_mma<<<dim3(4, 128), 256, SMEM_G1>>>();                            // 3
    g2_mma<<<dim3(2, CB), 256, SMEM_G2>>>(bias);                         // 4
    g3_mma<<<dim3(4, 2, CB), 256, SMEM_G3>>>(out);                       // 5
}

// round 9
// speedup vs baseline: 4.4265x; 1.1804x over previous
#include <cuda_runtime.h>
#include <cuda_fp16.h>
#include <cstdint>

// ---------------------------------------------------------------------------
// GeneralizedBilinearAttention via mma.sync fp16 (base sm_103 ISA).
//   G1: aM   = AOh(16384x512) @ WTh(512x512)            [1 product, 64x128 CTA]
//   G2: sim  = INh @ (aMh+aMl)^T + tanh/masked-softmax  [2 products]
//   G3: out  = attnh(256x128) @ AOh(128x512)            [1 product, B trans]
// fp32 acc everywhere. K32 chunks, 3-stage cp.async pipeline.
// ---------------------------------------------------------------------------

#define CB 128
#define CT 256
#define CN 128
#define CAD 512
#define CVD 512

__device__ __align__(16) unsigned short g_AOh[CB * CN * CAD];
__device__ __align__(16) unsigned short g_INh[CB * CT * CVD];
__device__ __align__(16) unsigned short g_WTh[CVD * CAD];
__device__ __align__(16) unsigned short g_aMh[CB * CN * CVD];
__device__ __align__(16) unsigned short g_aMl[CB * CN * CVD];
__device__ __align__(16) unsigned short g_ath[CB * CT * CN];
__device__ __align__(16) float g_lina[CB * CN];
__device__ __align__(16) float g_linb[CB * CT];
__device__ __align__(16) float g_maskf[CB * CN];

// ---- smem layouts -------------------------------------------------------------
#define TILEB 8192
// G1: A 64x32 (4KB) + B 128x32 (8KB) = 12KB / stage
#define G1_A   0
#define G1_B   4096
#define STAGE1 12288
// G2: A, Bh, Bl (8KB each) = 24KB / stage
#define SM_T0 0
#define SM_T1 TILEB
#define SM_T2 (2 * TILEB)
#define STAGE2 (3 * TILEB)
// G3: A (attn-hi) + B (AO trans) = 16KB / stage
#define G3_A   0
#define G3_B   TILEB
#define STAGE3 (2 * TILEB)
#define NST 3
#define SMEM_G1 (NST * STAGE1)        // 36864
#define SMEM_G2BASE (NST * STAGE2)    // 73728
#define SM_LIN SMEM_G2BASE
#define SM_MSK (SM_LIN + 512)
#define SM_LNB (SM_MSK + 512)
#define SMEM_G2 (SM_LNB + 512)
#define SMEM_G3 (NST * STAGE3)        // 49152

__device__ __forceinline__ uint32_t smem_u32(const void* p) {
    return (uint32_t)__cvta_generic_to_shared(p);
}
__device__ __forceinline__ uint32_t swz(int row, int c16) {
    return (uint32_t)(row * 64 + ((c16 ^ ((row >> 1) & 3)) << 4));
}
__device__ __forceinline__ uint32_t swzbt(int row, int c16) {
    return (uint32_t)(row * 256 + ((c16 ^ (row & 7)) << 4));
}
__device__ __forceinline__ void ldsm4(uint32_t* r, uint32_t addr) {
    asm volatile("ldmatrix.sync.aligned.m8n8.x4.shared.b16 {%0,%1,%2,%3}, [%4];"
                 : "=r"(r[0]), "=r"(r[1]), "=r"(r[2]), "=r"(r[3]) : "r"(addr));
}
__device__ __forceinline__ void ldsm4t(uint32_t* r, uint32_t addr) {
    asm volatile("ldmatrix.sync.aligned.m8n8.x4.trans.shared.b16 {%0,%1,%2,%3}, [%4];"
                 : "=r"(r[0]), "=r"(r[1]), "=r"(r[2]), "=r"(r[3]) : "r"(addr));
}
__device__ __forceinline__ void mma_f16(float* c, const uint32_t* a,
                                        uint32_t b0, uint32_t b1) {
    asm volatile("mma.sync.aligned.m16n8k16.row.col.f32.f16.f16.f32 "
                 "{%0,%1,%2,%3}, {%4,%5,%6,%7}, {%8,%9}, {%0,%1,%2,%3};"
                 : "+f"(c[0]), "+f"(c[1]), "+f"(c[2]), "+f"(c[3])
                 : "r"(a[0]), "r"(a[1]), "r"(a[2]), "r"(a[3]), "r"(b0), "r"(b1));
}
__device__ __forceinline__ void cpa(uint32_t d, const void* g) {
    asm volatile("cp.async.cg.shared.global [%0], [%1], 16;"
                 :: "r"(d), "l"(g) : "memory");
}
__device__ __forceinline__ uint32_t pack2h(float x, float y) {
    __half2 h = __floats2half2_rn(x, y);
    return *(uint32_t*)&h;
}
__device__ __forceinline__ void split2h(float x, float y, uint32_t& h, uint32_t& l) {
    __half xh = __float2half_rn(x), yh = __float2half_rn(y);
    __half xl = __float2half_rn(x - __half2float(xh));
    __half yl = __float2half_rn(y - __half2float(yh));
    h = ((uint32_t)__half_as_ushort(yh) << 16) | __half_as_ushort(xh);
    l = ((uint32_t)__half_as_ushort(yl) << 16) | __half_as_ushort(xl);
}

// ---------------------------------------------------------------------------
// Fused preprocessing: lin/split rows + W transpose + mask, one launch.
//   blocks [0, 6144)      : one warp per 512-dim row (lin dots + fp16 write)
//   blocks [6144, 6400)   : W -> WT fp16 transpose tiles
//   block  6400           : mask classify + normalize
// ---------------------------------------------------------------------------
#define LIN_BLKS 6144
#define WT_BLKS  256
__global__ void __launch_bounds__(256) pre_fused(
    const float* __restrict__ IN, const float* __restrict__ AO,
    const float* __restrict__ a_w, const float* __restrict__ b_w,
    const float* __restrict__ W, const unsigned char* __restrict__ m) {
    const int bid = blockIdx.x;
    const int tid = threadIdx.x;
    if (bid < LIN_BLKS) {
        int w = bid * 8 + (tid >> 5);
        int lane = tid & 31;
        const int nAO = CB * CN;
        const float* row; const float* wv; float* outd; int idx;
        uint32_t* dhi;
        if (w < nAO) {
            idx = w; row = AO + (size_t)w * CAD; wv = a_w; outd = g_lina;
            dhi = (uint32_t*)g_AOh + (size_t)w * 256;
        } else {
            idx = w - nAO; row = IN + (size_t)idx * CVD; wv = b_w; outd = g_linb;
            dhi = (uint32_t*)g_INh + (size_t)idx * 256;
        }
        float s = 0.f;
#pragma unroll
        for (int k = 0; k < 512; k += 128) {
            int e = k + lane * 4;
            float4 x = *(const float4*)(row + e);
            float4 y = *(const float4*)(wv + e);
            s += x.x * y.x + x.y * y.y + x.z * y.z + x.w * y.w;
            dhi[e >> 1]       = pack2h(x.x, x.y);
            dhi[(e >> 1) + 1] = pack2h(x.z, x.w);
        }
#pragma unroll
        for (int o = 16; o; o >>= 1) s += __shfl_xor_sync(0xffffffffu, s, o);
        if (lane == 0) outd[idx] = s;
    } else if (bid < LIN_BLKS + WT_BLKS) {
        __shared__ float t[32][33];
        const int idx = bid - LIN_BLKS;
        const int v0 = (idx & 15) * 32, a0 = (idx >> 4) * 32;
        const int tx = tid & 31, ty = tid >> 5;
        for (int i = ty; i < 32; i += 8)
            t[i][tx] = W[(size_t)(a0 + i) * CVD + v0 + tx];
        __syncthreads();
        for (int i = ty; i < 32; i += 8)
            g_WTh[(size_t)(v0 + i) * CAD + a0 + tx] =
                __half_as_ushort(__float2half_rn(t[tx][i]));
    } else {
        __shared__ int s_notbin, s_odd;
        if (tid == 0) { s_notbin = 0; s_odd = 0; }
        __syncthreads();
        int notbin = 0, odd = 0;
        for (int i = tid; i < CB * CN; i += 256) {
            unsigned char v = m[i];
            if (v > 1) notbin = 1;
            if ((i & 3) && v == 1) odd = 1;
        }
        if (notbin) atomicOr(&s_notbin, 1);
        if (odd)    atomicOr(&s_odd, 1);
        __syncthreads();
        const int md = s_notbin ? 2 : (s_odd ? 0 : 1);
        for (int i = tid; i < CB * CN; i += 256) {
            float v;
            if (md == 0)      v = (m[i] != 0) ? 1.f : 0.f;
            else if (md == 1) v = (((const int*)(const void*)m)[i] != 0) ? 1.f : 0.f;
            else              v = (((const float*)(const void*)m)[i] != 0.f) ? 1.f : 0.f;
            g_maskf[i] = v;
        }
    }
}

// ---------------------------------------------------------------------------
// G1: aM = AOh @ WTh^T (single product).  CTA tile 64x128, grid (4, 256).
// ---------------------------------------------------------------------------
__global__ void __launch_bounds__(256, 3) g1_mma() {
    extern __shared__ char sm[];
    const uint32_t smb = smem_u32(sm);
    const int tid = threadIdx.x, lane = tid & 31, w = tid >> 5;
    const int n0 = blockIdx.x * 128;
    const size_t m0 = (size_t)blockIdx.y * 64;
    const int mw = (w & 1) * 32, nw = (w >> 1) * 32;
    const int grp = lane >> 3, rin = lane & 7;
    int rowm[2], rowb[2];
#pragma unroll
    for (int mi = 0; mi < 2; ++mi) rowm[mi] = mw + mi * 16 + rin + ((grp & 1) << 3);
#pragma unroll
    for (int j = 0; j < 2; ++j)    rowb[j] = nw + j * 16 + rin + ((grp & 1) << 3);
    const int cgrp = grp >> 1;

    float acc[2][4][4];
#pragma unroll
    for (int a = 0; a < 2; ++a)
#pragma unroll
        for (int b = 0; b < 4; ++b)
#pragma unroll
            for (int cc = 0; cc < 4; ++cc) acc[a][b][cc] = 0.f;

    const unsigned short* A = g_AOh + m0 * CAD;
    const unsigned short* B = g_WTh + (size_t)n0 * CAD;

    // addressing: A 64x32 (1 cpa/thread), B 128x32 (2 cpa/thread)
    uint32_t doffA, doffB[2];
    const unsigned short *pA, *pB[2];
    {
        int rowA = tid >> 2, cA = tid & 3;
        doffA = swz(rowA, cA);
        pA = A + (size_t)rowA * CAD + cA * 8;
#pragma unroll
        for (int i = 0; i < 2; ++i) {
            int u = i * 256 + tid, row = u >> 2, c = u & 3;
            doffB[i] = swz(row, c);
            pB[i] = B + (size_t)row * CAD + c * 8;
        }
    }
#pragma unroll
    for (int s = 0; s < 2; ++s) {
        const uint32_t st = smb + (uint32_t)s * STAGE1;
        cpa(st + G1_A + doffA, pA); pA += 32;
#pragma unroll
        for (int i = 0; i < 2; ++i) {
            cpa(st + G1_B + doffB[i], pB[i]); pB[i] += 32;
        }
        asm volatile("cp.async.commit_group;" ::: "memory");
    }
    uint32_t stg = 0;
    const int nch = CAD >> 5;     // 16
    for (int c = 0; c < nch; ++c) {
        if (c == nch - 1) asm volatile("cp.async.wait_group 0;" ::: "memory");
        else              asm volatile("cp.async.wait_group 1;" ::: "memory");
        __syncthreads();
        if (c + 2 < nch) {
            uint32_t s2 = stg + 2; if (s2 >= NST) s2 -= NST;
            const uint32_t st2 = smb + s2 * STAGE1;
            cpa(st2 + G1_A + doffA, pA); pA += 32;
#pragma unroll
            for (int i = 0; i < 2; ++i) {
                cpa(st2 + G1_B + doffB[i], pB[i]); pB[i] += 32;
            }
            asm volatile("cp.async.commit_group;" ::: "memory");
        }
        const uint32_t st = smb + stg * STAGE1;
#pragma unroll
        for (int ks = 0; ks < 2; ++ks) {
            const int cu = 2 * ks + cgrp;
            uint32_t b0[4], b1[4], a0[4], a1[4];
            ldsm4(b0, st + G1_B + swz(rowb[0], cu));
            ldsm4(b1, st + G1_B + swz(rowb[1], cu));
            ldsm4(a0, st + G1_A + swz(rowm[0], cu));
            ldsm4(a1, st + G1_A + swz(rowm[1], cu));
#pragma unroll
            for (int nj = 0; nj < 4; ++nj) {
                const int o = nj & 1;
                const uint32_t* bb = (nj < 2) ? b0 : b1;
                mma_f16(acc[0][nj], a0, bb[o], bb[o + 2]);
                mma_f16(acc[1][nj], a1, bb[o], bb[o + 2]);
            }
        }
        if (++stg == NST) stg = 0;
    }

    const int qr = lane >> 2, qc = (lane & 3) * 2;
    uint32_t* ghi = (uint32_t*)g_aMh;
    uint32_t* glo = (uint32_t*)g_aMl;
#pragma unroll
    for (int mi = 0; mi < 2; ++mi)
#pragma unroll
        for (int nj = 0; nj < 4; ++nj) {
            size_t r0 = m0 + mw + mi * 16 + qr;
            size_t cp = (size_t)(n0 + nw + nj * 8 + qc) >> 1;
            uint32_t h, l;
            split2h(acc[mi][nj][0], acc[mi][nj][1], h, l);
            ghi[r0 * (CVD >> 1) + cp] = h; glo[r0 * (CVD >> 1) + cp] = l;
            split2h(acc[mi][nj][2], acc[mi][nj][3], h, l);
            ghi[(r0 + 8) * (CVD >> 1) + cp] = h; glo[(r0 + 8) * (CVD >> 1) + cp] = l;
        }
}

// ---------------------------------------------------------------------------
// G2: sim = INh_tile @ (aMh+aMl)^T + fused tanh/masked-softmax -> attn hi.
//     CTA 128x128, grid (2 Mtiles, B).
// ---------------------------------------------------------------------------
__global__ void __launch_bounds__(256, 2) g2_mma(const float* __restrict__ biasp) {
    extern __shared__ char sm[];
    const uint32_t smb = smem_u32(sm);
    const int tid = threadIdx.x;
    const int b = blockIdx.y;
    const int m0 = blockIdx.x * 128;
    float* sl  = (float*)(sm + SM_LIN);
    float* sk  = (float*)(sm + SM_MSK);
    float* slb = (float*)(sm + SM_LNB);
    if (tid < 128) {
        sl[tid]  = g_lina[b * CN + tid];
        sk[tid]  = g_maskf[b * CN + tid];
        slb[tid] = g_linb[b * CT + m0 + tid];
    }
    const int lane = tid & 31, w = tid >> 5;
    const int mw = (w & 1) * 64, nw = (w >> 1) * 32;
    const int grp = lane >> 3, rin = lane & 7;
    int rowm[4], rowb[2];
#pragma unroll
    for (int mi = 0; mi < 4; ++mi) rowm[mi] = mw + mi * 16 + rin + ((grp & 1) << 3);
#pragma unroll
    for (int j = 0; j < 2; ++j)    rowb[j] = nw + j * 16 + rin + ((grp & 1) << 3);
    const int cgrp = grp >> 1;

    float acc[4][4][4];
#pragma unroll
    for (int a = 0; a < 4; ++a)
#pragma unroll
        for (int bb = 0; bb < 4; ++bb)
#pragma unroll
            for (int cc = 0; cc < 4; ++cc) acc[a][bb][cc] = 0.f;

    const unsigned short* A  = g_INh + ((size_t)b * CT + m0) * CVD;
    const unsigned short* Bh = g_aMh + (size_t)b * CN * CVD;
    const unsigned short* Bl = g_aMl + (size_t)b * CN * CVD;

    uint32_t doff[2];
    const unsigned short *pA[2], *pBh[2], *pBl[2];
#pragma unroll
    for (int i = 0; i < 2; ++i) {
        int u = i * 256 + tid, row = u >> 2, c = u & 3;
        doff[i] = swz(row, c);
        pA[i]  = A  + (size_t)row * CVD + c * 8;
        pBh[i] = Bh + (size_t)row * CVD + c * 8;
        pBl[i] = Bl + (size_t)row * CVD + c * 8;
    }
#pragma unroll
    for (int s = 0; s < 2; ++s) {
        const uint32_t st = smb + (uint32_t)s * STAGE2;
#pragma unroll
        for (int i = 0; i < 2; ++i) {
            cpa(st + SM_T0 + doff[i], pA[i]);
            cpa(st + SM_T1 + doff[i], pBh[i]);
            cpa(st + SM_T2 + doff[i], pBl[i]);
            pA[i] += 32; pBh[i] += 32; pBl[i] += 32;
        }
        asm volatile("cp.async.commit_group;" ::: "memory");
    }
    uint32_t stg = 0;
    const int nch = CVD >> 5;
    for (int c = 0; c < nch; ++c) {
        if (c == nch - 1) asm volatile("cp.async.wait_group 0;" ::: "memory");
        else              asm volatile("cp.async.wait_group 1;" ::: "memory");
        __syncthreads();
        if (c + 2 < nch) {
            uint32_t s2 = stg + 2; if (s2 >= NST) s2 -= NST;
            const uint32_t st2 = smb + s2 * STAGE2;
#pragma unroll
            for (int i = 0; i < 2; ++i) {
                cpa(st2 + SM_T0 + doff[i], pA[i]);
                cpa(st2 + SM_T1 + doff[i], pBh[i]);
                cpa(st2 + SM_T2 + doff[i], pBl[i]);
                pA[i] += 32; pBh[i] += 32; pBl[i] += 32;
            }
            asm volatile("cp.async.commit_group;" ::: "memory");
        }
        const uint32_t st = smb + stg * STAGE2;
#pragma unroll
        for (int ks = 0; ks < 2; ++ks) {
            const int cu = 2 * ks + cgrp;
            uint32_t bh[2][4], bl[2][4];
#pragma unroll
            for (int j = 0; j < 2; ++j) {
                ldsm4(bh[j], st + SM_T1 + swz(rowb[j], cu));
                ldsm4(bl[j], st + SM_T2 + swz(rowb[j], cu));
            }
            uint32_t a2[2][4];
            ldsm4(a2[0], st + SM_T0 + swz(rowm[0], cu));
#pragma unroll
            for (int mi = 0; mi < 4; ++mi) {
                const int cur = mi & 1;
                if (mi < 3) ldsm4(a2[cur ^ 1], st + SM_T0 + swz(rowm[mi + 1], cu));
#pragma unroll
                for (int nj = 0; nj < 4; ++nj) {
                    const int j = nj >> 1, o = nj & 1;
                    mma_f16(acc[mi][nj], a2[cur], bh[j][o], bh[j][o + 2]);
                }
#pragma unroll
                for (int nj = 0; nj < 4; ++nj) {
                    const int j = nj >> 1, o = nj & 1;
                    mma_f16(acc[mi][nj], a2[cur], bl[j][o], bl[j][o + 2]);
                }
            }
        }
        if (++stg == NST) stg = 0;
    }
    __syncthreads();

    const int qr = lane >> 2, qc = (lane & 3) * 2;
    const float bs = biasp[0];
    float* ssim = (float*)sm;                       // 128 x 129 floats
#pragma unroll
    for (int mi = 0; mi < 4; ++mi)
#pragma unroll
        for (int nj = 0; nj < 4; ++nj) {
            int c0 = nw + nj * 8 + qc;
            float sla = sl[c0], slA = sl[c0 + 1];
            float mk0 = sk[c0], mk1 = sk[c0 + 1];
#pragma unroll
            for (int p = 0; p < 2; ++p) {
                int r = mw + mi * 16 + qr + p * 8;
                float lb = slb[r] + bs;
                float e0 = mk0 * __expf(tanhf(acc[mi][nj][2 * p] + sla + lb));
                float e1 = mk1 * __expf(tanhf(acc[mi][nj][2 * p + 1] + slA + lb));
                ssim[r * 129 + c0] = e0;
                ssim[r * 129 + c0 + 1] = e1;
            }
        }
    __syncthreads();
    {
        const int r = tid >> 1, half = tid & 1;
        const float* rowp = ssim + r * 129;
        float s = 0.f;
#pragma unroll
        for (int n = 0; n < 64; ++n) s += rowp[half * 64 + n];
        s += __shfl_xor_sync(0xffffffffu, s, 1);
        const float inv = 1.0f / (s + 1e-30f);
        const size_t t = (size_t)b * CT + m0 + r;
        uint32_t* ohi = (uint32_t*)g_ath + t * 64;
#pragma unroll
        for (int jj = 0; jj < 32; ++jj) {
            int j = half * 32 + jj;
            ohi[j] = pack2h(rowp[2 * j] * inv, rowp[2 * j + 1] * inv);
        }
    }
}

// ---------------------------------------------------------------------------
// G3: out = attnh @ AOh (single product, B trans).  grid (4, 2, B).
// ---------------------------------------------------------------------------
__global__ void __launch_bounds__(256, 2) g3_mma(float* __restrict__ OUT) {
    extern __shared__ char sm[];
    const uint32_t smb = smem_u32(sm);
    const int tid = threadIdx.x, lane = tid & 31, w = tid >> 5;
    const int b = blockIdx.z;
    const int m0 = blockIdx.y * 128;
    const int n0 = blockIdx.x * 128;
    const int mw = (w & 1) * 64, nw = (w >> 1) * 32;
    const int grp = lane >> 3, rin = lane & 7;
    int rowm[4];
#pragma unroll
    for (int mi = 0; mi < 4; ++mi) rowm[mi] = mw + mi * 16 + rin + ((grp & 1) << 3);
    const int cgrp = grp >> 1;

    float acc[4][4][4];
#pragma unroll
    for (int a = 0; a < 4; ++a)
#pragma unroll
        for (int bb = 0; bb < 4; ++bb)
#pragma unroll
            for (int cc = 0; cc < 4; ++cc) acc[a][bb][cc] = 0.f;

    const unsigned short* A = g_ath + ((size_t)b * CT + m0) * CN;
    const unsigned short* B = g_AOh + (size_t)b * CN * CAD;

    uint32_t doffA[2], doffB[2];
    const unsigned short *pA[2], *pB[2];
    const size_t bstep = (size_t)32 * CAD;
#pragma unroll
    for (int i = 0; i < 2; ++i) {
        int u = i * 256 + tid;
        int rowA = u >> 2, cA = u & 3;
        doffA[i] = swz(rowA, cA);
        pA[i] = A + (size_t)rowA * CN + cA * 8;
        int rowB = u >> 4, cB = u & 15;
        doffB[i] = swzbt(rowB, cB);
        pB[i] = B + (size_t)rowB * CAD + n0 + cB * 8;
    }
#pragma unroll
    for (int s = 0; s < 2; ++s) {
        const uint32_t st = smb + (uint32_t)s * STAGE3;
#pragma unroll
        for (int i = 0; i < 2; ++i) {
            cpa(st + G3_A + doffA[i], pA[i]);
            cpa(st + G3_B + doffB[i], pB[i]);
            pA[i] += 32; pB[i] += bstep;
        }
        asm volatile("cp.async.commit_group;" ::: "memory");
    }
    uint32_t stg = 0;
    const int nch = CN >> 5;      // 4
    for (int c = 0; c < nch; ++c) {
        if (c == nch - 1) asm volatile("cp.async.wait_group 0;" ::: "memory");
        else              asm volatile("cp.async.wait_group 1;" ::: "memory");
        __syncthreads();
        if (c + 2 < nch) {
            uint32_t s2 = stg + 2; if (s2 >= NST) s2 -= NST;
            const uint32_t st2 = smb + s2 * STAGE3;
#pragma unroll
            for (int i = 0; i < 2; ++i) {
                cpa(st2 + G3_A + doffA[i], pA[i]);
                cpa(st2 + G3_B + doffB[i], pB[i]);
                pA[i] += 32; pB[i] += bstep;
            }
            asm volatile("cp.async.commit_group;" ::: "memory");
        }
        const uint32_t st = smb + stg * STAGE3;
#pragma unroll
        for (int ks = 0; ks < 2; ++ks) {
            const int cu = 2 * ks + cgrp;
            const int browk = 16 * ks + rin + ((grp >> 1) << 3);
            uint32_t bt[2][4];
#pragma unroll
            for (int j = 0; j < 2; ++j) {
                const int bc = (nw >> 3) + 2 * j + (grp & 1);
                ldsm4t(bt[j], st + G3_B + swzbt(browk, bc));
            }
            uint32_t a2[2][4];
            ldsm4(a2[0], st + G3_A + swz(rowm[0], cu));
#pragma unroll
            for (int mi = 0; mi < 4; ++mi) {
                const int cur = mi & 1;
                if (mi < 3) ldsm4(a2[cur ^ 1], st + G3_A + swz(rowm[mi + 1], cu));
#pragma unroll
                for (int nj = 0; nj < 4; ++nj) {
                    const int j = nj >> 1, o = nj & 1;
                    mma_f16(acc[mi][nj], a2[cur], bt[j][o], bt[j][o + 2]);
                }
            }
        }
        if (++stg == NST) stg = 0;
    }

    const int qr = lane >> 2, qc = (lane & 3) * 2;
#pragma unroll
    for (int mi = 0; mi < 4; ++mi)
#pragma unroll
        for (int nj = 0; nj < 4; ++nj) {
            size_t r0 = (size_t)b * CT + m0 + mw + mi * 16 + qr;
            int gc = n0 + nw + nj * 8 + qc;
            *(float2*)(OUT + r0 * CAD + gc) =
                make_float2(acc[mi][nj][0], acc[mi][nj][1]);
            *(float2*)(OUT + (r0 + 8) * CAD + gc) =
                make_float2(acc[mi][nj][2], acc[mi][nj][3]);
        }
}

// ---------------------------------------------------------------------------
extern "C" void kernel_launch(void* const* d_in, const int* in_sizes, int n_in,
                              void* d_out, int out_size) {
    const float* inputs = (const float*)d_in[0];
    const float* ao     = (const float*)d_in[1];
    const void*  mask   = d_in[2];
    const float* W      = (const float*)d_in[3];
    const float* a_w    = (const float*)d_in[4];
    const float* b_w    = (const float*)d_in[5];
    const float* bias   = (const float*)d_in[6];
    float* out = (float*)d_out;

    cudaFuncSetAttribute(g1_mma, cudaFuncAttributeMaxDynamicSharedMemorySize, SMEM_G1);
    cudaFuncSetAttribute(g2_mma, cudaFuncAttributeMaxDynamicSharedMemorySize, SMEM_G2);
    cudaFuncSetAttribute(g3_mma, cudaFuncAttributeMaxDynamicSharedMemorySize, SMEM_G3);

    pre_fused<<<LIN_BLKS + WT_BLKS + 1, 256>>>(
        inputs, ao, a_w, b_w, W, (const unsigned char*)mask);        // 0
    g1_mma<<<dim3(4, 256), 256, SMEM_G1>>>();                        // 1
    g2_mma<<<dim3(2, CB), 256, SMEM_G2>>>(bias);                     // 2
    g3_mma<<<dim3(4, 2, CB), 256, SMEM_G3>>>(out);                   // 3
}

// round 10
// speedup vs baseline: 4.5331x; 1.0241x over previous
#include <cuda_runtime.h>
#include <cuda_fp16.h>
#include <cstdint>

// ---------------------------------------------------------------------------
// GeneralizedBilinearAttention via mma.sync fp16 (base sm_103 ISA).
//   G1 : aM  = AOh(16384x512) @ WTh(512x512)            [1 product, 64x128 CTA]
//   G23: sim = INh @ (aMh+aMl)^T -> tanh/masked-softmax -> attn (smem, fp16)
//        out = attn @ AOh  (B via ldmatrix.trans)       [fused, no attn gmem]
// fp32 acc. K32 chunks, 3-stage cp.async pipelines.
// ---------------------------------------------------------------------------

#define CB 128
#define CT 256
#define CN 128
#define CAD 512
#define CVD 512

__device__ __align__(16) unsigned short g_AOh[CB * CN * CAD];
__device__ __align__(16) unsigned short g_INh[CB * CT * CVD];
__device__ __align__(16) unsigned short g_WTh[CVD * CAD];
__device__ __align__(16) unsigned short g_aMh[CB * CN * CVD];
__device__ __align__(16) unsigned short g_aMl[CB * CN * CVD];
__device__ __align__(16) float g_lina[CB * CN];
__device__ __align__(16) float g_linb[CB * CT];
__device__ __align__(16) float g_maskf[CB * CN];

// ---- smem layouts -------------------------------------------------------------
#define TILEB 8192
// G1: A 64x32 (4KB) + B 128x32 (8KB) = 12KB / stage
#define G1_A   0
#define G1_B   4096
#define STAGE1 12288
#define SMEM_G1 (3 * STAGE1)
// G23 phase 1: A, Bh, Bl (8KB each) = 24KB / stage, 3 stages = 72KB
#define SM_T0 0
#define SM_T1 TILEB
#define SM_T2 (2 * TILEB)
#define STAGE2 (3 * TILEB)
// G23 phase 2 (overlays phase-1 stages): attn 4x8KB at 0, B stages at 32KB
#define PH2_ATT 0
#define PH2_B   32768
// aux region above the stages
#define SM_LIN (3 * STAGE2)          // 73728
#define SM_MSK (SM_LIN + 512)
#define SM_LNB (SM_MSK + 512)
#define SM_RED (SM_LNB + 512)        // 128 rows x 4 floats = 2KB
#define SMEM_G23 (SM_RED + 2048)     // 77312

__device__ __forceinline__ uint32_t smem_u32(const void* p) {
    return (uint32_t)__cvta_generic_to_shared(p);
}
__device__ __forceinline__ uint32_t swz(int row, int c16) {
    return (uint32_t)(row * 64 + ((c16 ^ ((row >> 1) & 3)) << 4));
}
__device__ __forceinline__ uint32_t swzbt(int row, int c16) {
    return (uint32_t)(row * 256 + ((c16 ^ (row & 7)) << 4));
}
__device__ __forceinline__ void ldsm4(uint32_t* r, uint32_t addr) {
    asm volatile("ldmatrix.sync.aligned.m8n8.x4.shared.b16 {%0,%1,%2,%3}, [%4];"
                 : "=r"(r[0]), "=r"(r[1]), "=r"(r[2]), "=r"(r[3]) : "r"(addr));
}
__device__ __forceinline__ void ldsm4t(uint32_t* r, uint32_t addr) {
    asm volatile("ldmatrix.sync.aligned.m8n8.x4.trans.shared.b16 {%0,%1,%2,%3}, [%4];"
                 : "=r"(r[0]), "=r"(r[1]), "=r"(r[2]), "=r"(r[3]) : "r"(addr));
}
__device__ __forceinline__ void mma_f16(float* c, const uint32_t* a,
                                        uint32_t b0, uint32_t b1) {
    asm volatile("mma.sync.aligned.m16n8k16.row.col.f32.f16.f16.f32 "
                 "{%0,%1,%2,%3}, {%4,%5,%6,%7}, {%8,%9}, {%0,%1,%2,%3};"
                 : "+f"(c[0]), "+f"(c[1]), "+f"(c[2]), "+f"(c[3])
                 : "r"(a[0]), "r"(a[1]), "r"(a[2]), "r"(a[3]), "r"(b0), "r"(b1));
}
__device__ __forceinline__ void cpa(uint32_t d, const void* g) {
    asm volatile("cp.async.cg.shared.global [%0], [%1], 16;"
                 :: "r"(d), "l"(g) : "memory");
}
__device__ __forceinline__ uint32_t pack2h(float x, float y) {
    __half2 h = __floats2half2_rn(x, y);
    return *(uint32_t*)&h;
}
__device__ __forceinline__ void split2h(float x, float y, uint32_t& h, uint32_t& l) {
    __half xh = __float2half_rn(x), yh = __float2half_rn(y);
    __half xl = __float2half_rn(x - __half2float(xh));
    __half yl = __float2half_rn(y - __half2float(yh));
    h = ((uint32_t)__half_as_ushort(yh) << 16) | __half_as_ushort(xh);
    l = ((uint32_t)__half_as_ushort(yl) << 16) | __half_as_ushort(xl);
}

// ---------------------------------------------------------------------------
// Fused preprocessing (one launch).
// ---------------------------------------------------------------------------
#define LIN_BLKS 6144
#define WT_BLKS  256
__global__ void __launch_bounds__(256) pre_fused(
    const float* __restrict__ IN, const float* __restrict__ AO,
    const float* __restrict__ a_w, const float* __restrict__ b_w,
    const float* __restrict__ W, const unsigned char* __restrict__ m) {
    const int bid = blockIdx.x;
    const int tid = threadIdx.x;
    if (bid < LIN_BLKS) {
        int w = bid * 8 + (tid >> 5);
        int lane = tid & 31;
        const int nAO = CB * CN;
        const float* row; const float* wv; float* outd; int idx;
        uint32_t* dhi;
        if (w < nAO) {
            idx = w; row = AO + (size_t)w * CAD; wv = a_w; outd = g_lina;
            dhi = (uint32_t*)g_AOh + (size_t)w * 256;
        } else {
            idx = w - nAO; row = IN + (size_t)idx * CVD; wv = b_w; outd = g_linb;
            dhi = (uint32_t*)g_INh + (size_t)idx * 256;
        }
        float s = 0.f;
#pragma unroll
        for (int k = 0; k < 512; k += 128) {
            int e = k + lane * 4;
            float4 x = *(const float4*)(row + e);
            float4 y = *(const float4*)(wv + e);
            s += x.x * y.x + x.y * y.y + x.z * y.z + x.w * y.w;
            dhi[e >> 1]       = pack2h(x.x, x.y);
            dhi[(e >> 1) + 1] = pack2h(x.z, x.w);
        }
#pragma unroll
        for (int o = 16; o; o >>= 1) s += __shfl_xor_sync(0xffffffffu, s, o);
        if (lane == 0) outd[idx] = s;
    } else if (bid < LIN_BLKS + WT_BLKS) {
        __shared__ float t[32][33];
        const int idx = bid - LIN_BLKS;
        const int v0 = (idx & 15) * 32, a0 = (idx >> 4) * 32;
        const int tx = tid & 31, ty = tid >> 5;
        for (int i = ty; i < 32; i += 8)
            t[i][tx] = W[(size_t)(a0 + i) * CVD + v0 + tx];
        __syncthreads();
        for (int i = ty; i < 32; i += 8)
            g_WTh[(size_t)(v0 + i) * CAD + a0 + tx] =
                __half_as_ushort(__float2half_rn(t[tx][i]));
    } else {
        __shared__ int s_notbin, s_odd;
        if (tid == 0) { s_notbin = 0; s_odd = 0; }
        __syncthreads();
        int notbin = 0, odd = 0;
        for (int i = tid; i < CB * CN; i += 256) {
            unsigned char v = m[i];
            if (v > 1) notbin = 1;
            if ((i & 3) && v == 1) odd = 1;
        }
        if (notbin) atomicOr(&s_notbin, 1);
        if (odd)    atomicOr(&s_odd, 1);
        __syncthreads();
        const int md = s_notbin ? 2 : (s_odd ? 0 : 1);
        for (int i = tid; i < CB * CN; i += 256) {
            float v;
            if (md == 0)      v = (m[i] != 0) ? 1.f : 0.f;
            else if (md == 1) v = (((const int*)(const void*)m)[i] != 0) ? 1.f : 0.f;
            else              v = (((const float*)(const void*)m)[i] != 0.f) ? 1.f : 0.f;
            g_maskf[i] = v;
        }
    }
}

// ---------------------------------------------------------------------------
// G1: aM = AOh @ WTh^T (single product).  CTA tile 64x128, grid (4, 256).
// ---------------------------------------------------------------------------
__global__ void __launch_bounds__(256, 3) g1_mma() {
    extern __shared__ char sm[];
    const uint32_t smb = smem_u32(sm);
    const int tid = threadIdx.x, lane = tid & 31, w = tid >> 5;
    const int n0 = blockIdx.x * 128;
    const size_t m0 = (size_t)blockIdx.y * 64;
    const int mw = (w & 1) * 32, nw = (w >> 1) * 32;
    const int grp = lane >> 3, rin = lane & 7;
    int rowm[2], rowb[2];
#pragma unroll
    for (int mi = 0; mi < 2; ++mi) rowm[mi] = mw + mi * 16 + rin + ((grp & 1) << 3);
#pragma unroll
    for (int j = 0; j < 2; ++j)    rowb[j] = nw + j * 16 + rin + ((grp & 1) << 3);
    const int cgrp = grp >> 1;

    float acc[2][4][4];
#pragma unroll
    for (int a = 0; a < 2; ++a)
#pragma unroll
        for (int b = 0; b < 4; ++b)
#pragma unroll
            for (int cc = 0; cc < 4; ++cc) acc[a][b][cc] = 0.f;

    const unsigned short* A = g_AOh + m0 * CAD;
    const unsigned short* B = g_WTh + (size_t)n0 * CAD;

    uint32_t doffA, doffB[2];
    const unsigned short *pA, *pB[2];
    {
        int rowA = tid >> 2, cA = tid & 3;
        doffA = swz(rowA, cA);
        pA = A + (size_t)rowA * CAD + cA * 8;
#pragma unroll
        for (int i = 0; i < 2; ++i) {
            int u = i * 256 + tid, row = u >> 2, c = u & 3;
            doffB[i] = swz(row, c);
            pB[i] = B + (size_t)row * CAD + c * 8;
        }
    }
#pragma unroll
    for (int s = 0; s < 2; ++s) {
        const uint32_t st = smb + (uint32_t)s * STAGE1;
        cpa(st + G1_A + doffA, pA); pA += 32;
#pragma unroll
        for (int i = 0; i < 2; ++i) {
            cpa(st + G1_B + doffB[i], pB[i]); pB[i] += 32;
        }
        asm volatile("cp.async.commit_group;" ::: "memory");
    }
    uint32_t stg = 0;
    const int nch = CAD >> 5;
    for (int c = 0; c < nch; ++c) {
        if (c == nch - 1) asm volatile("cp.async.wait_group 0;" ::: "memory");
        else              asm volatile("cp.async.wait_group 1;" ::: "memory");
        __syncthreads();
        if (c + 2 < nch) {
            uint32_t s2 = stg + 2; if (s2 >= 3) s2 -= 3;
            const uint32_t st2 = smb + s2 * STAGE1;
            cpa(st2 + G1_A + doffA, pA); pA += 32;
#pragma unroll
            for (int i = 0; i < 2; ++i) {
                cpa(st2 + G1_B + doffB[i], pB[i]); pB[i] += 32;
            }
            asm volatile("cp.async.commit_group;" ::: "memory");
        }
        const uint32_t st = smb + stg * STAGE1;
#pragma unroll
        for (int ks = 0; ks < 2; ++ks) {
            const int cu = 2 * ks + cgrp;
            uint32_t b0[4], b1[4], a0[4], a1[4];
            ldsm4(b0, st + G1_B + swz(rowb[0], cu));
            ldsm4(b1, st + G1_B + swz(rowb[1], cu));
            ldsm4(a0, st + G1_A + swz(rowm[0], cu));
            ldsm4(a1, st + G1_A + swz(rowm[1], cu));
#pragma unroll
            for (int nj = 0; nj < 4; ++nj) {
                const int o = nj & 1;
                const uint32_t* bb = (nj < 2) ? b0 : b1;
                mma_f16(acc[0][nj], a0, bb[o], bb[o + 2]);
                mma_f16(acc[1][nj], a1, bb[o], bb[o + 2]);
            }
        }
        if (++stg == 3) stg = 0;
    }

    const int qr = lane >> 2, qc = (lane & 3) * 2;
    uint32_t* ghi = (uint32_t*)g_aMh;
    uint32_t* glo = (uint32_t*)g_aMl;
#pragma unroll
    for (int mi = 0; mi < 2; ++mi)
#pragma unroll
        for (int nj = 0; nj < 4; ++nj) {
            size_t r0 = m0 + mw + mi * 16 + qr;
            size_t cp = (size_t)(n0 + nw + nj * 8 + qc) >> 1;
            uint32_t h, l;
            split2h(acc[mi][nj][0], acc[mi][nj][1], h, l);
            ghi[r0 * (CVD >> 1) + cp] = h; glo[r0 * (CVD >> 1) + cp] = l;
            split2h(acc[mi][nj][2], acc[mi][nj][3], h, l);
            ghi[(r0 + 8) * (CVD >> 1) + cp] = h; glo[(r0 + 8) * (CVD >> 1) + cp] = l;
        }
}

// ---------------------------------------------------------------------------
// G23: sim = INh @ (aMh+aMl)^T -> softmax -> attn (smem) -> out = attn @ AOh.
//      grid (2 Mtiles, B), 256 threads, 2 CTAs/SM.
// ---------------------------------------------------------------------------
__global__ void __launch_bounds__(256, 2) g23_mma(const float* __restrict__ biasp,
                                                  float* __restrict__ OUT) {
    extern __shared__ char sm[];
    const uint32_t smb = smem_u32(sm);
    const int tid = threadIdx.x;
    const int b = blockIdx.y;
    const int m0 = blockIdx.x * 128;
    float* sl  = (float*)(sm + SM_LIN);
    float* sk  = (float*)(sm + SM_MSK);
    float* slb = (float*)(sm + SM_LNB);
    float* red = (float*)(sm + SM_RED);
    if (tid < 128) {
        sl[tid]  = g_lina[b * CN + tid];
        sk[tid]  = g_maskf[b * CN + tid];
        slb[tid] = g_linb[b * CT + m0 + tid];
    }
    const int lane = tid & 31, w = tid >> 5;
    const int mw = (w & 1) * 64, nw = (w >> 1) * 32;
    const int grp = lane >> 3, rin = lane & 7;
    int rowm[4], rowb[2];
#pragma unroll
    for (int mi = 0; mi < 4; ++mi) rowm[mi] = mw + mi * 16 + rin + ((grp & 1) << 3);
#pragma unroll
    for (int j = 0; j < 2; ++j)    rowb[j] = nw + j * 16 + rin + ((grp & 1) << 3);
    const int cgrp = grp >> 1;

    float acc[4][4][4];
#pragma unroll
    for (int a = 0; a < 4; ++a)
#pragma unroll
        for (int bb = 0; bb < 4; ++bb)
#pragma unroll
            for (int cc = 0; cc < 4; ++cc) acc[a][bb][cc] = 0.f;

    // ---------------- phase 1: sim mainloop (2 products) ----------------
    const unsigned short* A  = g_INh + ((size_t)b * CT + m0) * CVD;
    const unsigned short* Bh = g_aMh + (size_t)b * CN * CVD;
    const unsigned short* Bl = g_aMl + (size_t)b * CN * CVD;

    uint32_t doff[2];
    const unsigned short *pA[2], *pBh[2], *pBl[2];
#pragma unroll
    for (int i = 0; i < 2; ++i) {
        int u = i * 256 + tid, row = u >> 2, c = u & 3;
        doff[i] = swz(row, c);
        pA[i]  = A  + (size_t)row * CVD + c * 8;
        pBh[i] = Bh + (size_t)row * CVD + c * 8;
        pBl[i] = Bl + (size_t)row * CVD + c * 8;
    }
#pragma unroll
    for (int s = 0; s < 2; ++s) {
        const uint32_t st = smb + (uint32_t)s * STAGE2;
#pragma unroll
        for (int i = 0; i < 2; ++i) {
            cpa(st + SM_T0 + doff[i], pA[i]);
            cpa(st + SM_T1 + doff[i], pBh[i]);
            cpa(st + SM_T2 + doff[i], pBl[i]);
            pA[i] += 32; pBh[i] += 32; pBl[i] += 32;
        }
        asm volatile("cp.async.commit_group;" ::: "memory");
    }
    uint32_t stg = 0;
    const int nch = CVD >> 5;
    for (int c = 0; c < nch; ++c) {
        if (c == nch - 1) asm volatile("cp.async.wait_group 0;" ::: "memory");
        else              asm volatile("cp.async.wait_group 1;" ::: "memory");
        __syncthreads();
        if (c + 2 < nch) {
            uint32_t s2 = stg + 2; if (s2 >= 3) s2 -= 3;
            const uint32_t st2 = smb + s2 * STAGE2;
#pragma unroll
            for (int i = 0; i < 2; ++i) {
                cpa(st2 + SM_T0 + doff[i], pA[i]);
                cpa(st2 + SM_T1 + doff[i], pBh[i]);
                cpa(st2 + SM_T2 + doff[i], pBl[i]);
                pA[i] += 32; pBh[i] += 32; pBl[i] += 32;
            }
            asm volatile("cp.async.commit_group;" ::: "memory");
        }
        const uint32_t st = smb + stg * STAGE2;
#pragma unroll
        for (int ks = 0; ks < 2; ++ks) {
            const int cu = 2 * ks + cgrp;
            uint32_t bh[2][4], bl[2][4];
#pragma unroll
            for (int j = 0; j < 2; ++j) {
                ldsm4(bh[j], st + SM_T1 + swz(rowb[j], cu));
                ldsm4(bl[j], st + SM_T2 + swz(rowb[j], cu));
            }
            uint32_t a2[2][4];
            ldsm4(a2[0], st + SM_T0 + swz(rowm[0], cu));
#pragma unroll
            for (int mi = 0; mi < 4; ++mi) {
                const int cur = mi & 1;
                if (mi < 3) ldsm4(a2[cur ^ 1], st + SM_T0 + swz(rowm[mi + 1], cu));
#pragma unroll
                for (int nj = 0; nj < 4; ++nj) {
                    const int j = nj >> 1, o = nj & 1;
                    mma_f16(acc[mi][nj], a2[cur], bh[j][o], bh[j][o + 2]);
                }
#pragma unroll
                for (int nj = 0; nj < 4; ++nj) {
                    const int j = nj >> 1, o = nj & 1;
                    mma_f16(acc[mi][nj], a2[cur], bl[j][o], bl[j][o + 2]);
                }
            }
        }
        if (++stg == 3) stg = 0;
    }
    __syncthreads();   // phase-1 smem dead beyond this point

    // ---- phase-2 B preloads (overlap with softmax epilogue) ----
    uint32_t doffB2[2];
    const unsigned short* pB2[2];
#pragma unroll
    for (int i = 0; i < 2; ++i) {
        int u = i * 256 + tid;
        int rowB = u >> 4, cB = u & 15;
        doffB2[i] = swzbt(rowB, cB);
        pB2[i] = g_AOh + (size_t)b * CN * CAD + (size_t)rowB * CAD + cB * 8;
    }
#pragma unroll
    for (int s = 0; s < 2; ++s) {
        // tile idx s: v0i = s>>2 (=0), kc = s&3 (=s)
        const uint32_t st = smb + PH2_B + (uint32_t)s * TILEB;
#pragma unroll
        for (int i = 0; i < 2; ++i)
            cpa(st + doffB2[i], pB2[i] + (size_t)(s * 32) * CAD);
        asm volatile("cp.async.commit_group;" ::: "memory");
    }

    // ---- softmax epilogue (register-resident, tiny reductions) ----
    const int qr = lane >> 2, qc = (lane & 3) * 2;
    const float bs = biasp[0];
    float part[4][2];
#pragma unroll
    for (int mi = 0; mi < 4; ++mi)
#pragma unroll
        for (int p = 0; p < 2; ++p) part[mi][p] = 0.f;
#pragma unroll
    for (int mi = 0; mi < 4; ++mi)
#pragma unroll
        for (int nj = 0; nj < 4; ++nj) {
            int c0 = nw + nj * 8 + qc;
            float sla = sl[c0], slA = sl[c0 + 1];
            float mk0 = sk[c0], mk1 = sk[c0 + 1];
#pragma unroll
            for (int p = 0; p < 2; ++p) {
                int r = mw + mi * 16 + qr + p * 8;
                float lb = slb[r] + bs;
                float e0 = mk0 * __expf(tanhf(acc[mi][nj][2 * p] + sla + lb));
                float e1 = mk1 * __expf(tanhf(acc[mi][nj][2 * p + 1] + slA + lb));
                acc[mi][nj][2 * p]     = e0;
                acc[mi][nj][2 * p + 1] = e1;
                part[mi][p] += e0 + e1;
            }
        }
#pragma unroll
    for (int mi = 0; mi < 4; ++mi)
#pragma unroll
        for (int p = 0; p < 2; ++p) {
            part[mi][p] += __shfl_xor_sync(0xffffffffu, part[mi][p], 1);
            part[mi][p] += __shfl_xor_sync(0xffffffffu, part[mi][p], 2);
        }
    if ((lane & 3) == 0) {
#pragma unroll
        for (int mi = 0; mi < 4; ++mi)
#pragma unroll
            for (int p = 0; p < 2; ++p) {
                int r = mw + mi * 16 + qr + p * 8;
                red[r * 4 + (w >> 1)] = part[mi][p];
            }
    }
    __syncthreads();
    // normalize + write attn fp16 into smem (mainloop-A swizzle layout)
#pragma unroll
    for (int mi = 0; mi < 4; ++mi)
#pragma unroll
        for (int p = 0; p < 2; ++p) {
            int r = mw + mi * 16 + qr + p * 8;
            float4 rv = *(float4*)&red[r * 4];
            float inv = 1.0f / (rv.x + rv.y + rv.z + rv.w + 1e-30f);
#pragma unroll
            for (int nj = 0; nj < 4; ++nj) {
                uint32_t addr = smb + PH2_ATT + (uint32_t)(nw >> 5) * TILEB
                              + swz(r, nj) + qc * 2;
                uint32_t pk = pack2h(acc[mi][nj][2 * p] * inv,
                                     acc[mi][nj][2 * p + 1] * inv);
                asm volatile("st.shared.b32 [%0], %1;" :: "r"(addr), "r"(pk)
                             : "memory");
            }
        }

    // ---------------- phase 2: out = attn @ AOh (B trans) ----------------
    float acc2[4][4][4];
#pragma unroll
    for (int a = 0; a < 4; ++a)
#pragma unroll
        for (int bb = 0; bb < 4; ++bb)
#pragma unroll
            for (int cc = 0; cc < 4; ++cc) acc2[a][bb][cc] = 0.f;

    uint32_t stg2 = 0;
    for (int idx = 0; idx < 16; ++idx) {
        if (idx == 15) asm volatile("cp.async.wait_group 0;" ::: "memory");
        else           asm volatile("cp.async.wait_group 1;" ::: "memory");
        __syncthreads();   // also orders attn STS (first iteration)
        if (idx + 2 < 16) {
            uint32_t s2 = stg2 + 2; if (s2 >= 3) s2 -= 3;
            const uint32_t st2 = smb + PH2_B + s2 * TILEB;
            const int nidx = idx + 2;
            const size_t boff = (size_t)((nidx & 3) * 32) * CAD + (nidx >> 2) * 128;
#pragma unroll
            for (int i = 0; i < 2; ++i)
                cpa(st2 + doffB2[i], pB2[i] + boff);
            asm volatile("cp.async.commit_group;" ::: "memory");
        }
        const uint32_t stB = smb + PH2_B + stg2 * TILEB;
        const uint32_t stA = smb + PH2_ATT + (uint32_t)(idx & 3) * TILEB;
#pragma unroll
        for (int ks = 0; ks < 2; ++ks) {
            const int cu = 2 * ks + cgrp;
            const int browk = 16 * ks + rin + ((grp >> 1) << 3);
            uint32_t bt[2][4];
#pragma unroll
            for (int j = 0; j < 2; ++j) {
                const int bc = (nw >> 3) + 2 * j + (grp & 1);
                ldsm4t(bt[j], stB + swzbt(browk, bc));
            }
            uint32_t a2[2][4];
            ldsm4(a2[0], stA + swz(rowm[0], cu));
#pragma unroll
            for (int mi = 0; mi < 4; ++mi) {
                const int cur = mi & 1;
                if (mi < 3) ldsm4(a2[cur ^ 1], stA + swz(rowm[mi + 1], cu));
#pragma unroll
                for (int nj = 0; nj < 4; ++nj) {
                    const int j = nj >> 1, o = nj & 1;
                    mma_f16(acc2[mi][nj], a2[cur], bt[j][o], bt[j][o + 2]);
                }
            }
        }
        if ((idx & 3) == 3) {
            const int v0 = (idx >> 2) * 128;
#pragma unroll
            for (int mi = 0; mi < 4; ++mi)
#pragma unroll
                for (int nj = 0; nj < 4; ++nj) {
                    size_t r0 = (size_t)b * CT + m0 + mw + mi * 16 + qr;
                    int gc = v0 + nw + nj * 8 + qc;
                    *(float2*)(OUT + r0 * CAD + gc) =
                        make_float2(acc2[mi][nj][0], acc2[mi][nj][1]);
                    *(float2*)(OUT + (r0 + 8) * CAD + gc) =
                        make_float2(acc2[mi][nj][2], acc2[mi][nj][3]);
                    acc2[mi][nj][0] = 0.f; acc2[mi][nj][1] = 0.f;
                    acc2[mi][nj][2] = 0.f; acc2[mi][nj][3] = 0.f;
                }
        }
        if (++stg2 == 3) stg2 = 0;
    }
}

// ---------------------------------------------------------------------------
extern "C" void kernel_launch(void* const* d_in, const int* in_sizes, int n_in,
                              void* d_out, int out_size) {
    const float* inputs = (const float*)d_in[0];
    const float* ao     = (const float*)d_in[1];
    const void*  mask   = d_in[2];
    const float* W      = (const float*)d_in[3];
    const float* a_w    = (const float*)d_in[4];
    const float* b_w    = (const float*)d_in[5];
    const float* bias   = (const float*)d_in[6];
    float* out = (float*)d_out;

    cudaFuncSetAttribute(g1_mma,  cudaFuncAttributeMaxDynamicSharedMemorySize, SMEM_G1);
    cudaFuncSetAttribute(g23_mma, cudaFuncAttributeMaxDynamicSharedMemorySize, SMEM_G23);

    pre_fused<<<LIN_BLKS + WT_BLKS + 1, 256>>>(
        inputs, ao, a_w, b_w, W, (const unsigned char*)mask);        // 0
    g1_mma<<<dim3(4, 256), 256, SMEM_G1>>>();                        // 1
    g23_mma<<<dim3(2, CB), 256, SMEM_G23>>>(bias, out);              // 2
}

// round 11
// speedup vs baseline: 4.7526x; 1.0484x over previous
#include <cuda_runtime.h>
#include <cuda_fp16.h>
#include <cstdint>

// ---------------------------------------------------------------------------
// GeneralizedBilinearAttention via mma.sync fp16 (base sm_103 ISA).
//   pre_a: AO rows (lina + AOh) + W->WTh + mask            (~52 MB traffic)
//   g1x  : aM = AOh @ WTh^T  (64x128 CTA tiles)  +  co-scheduled IN-row CTAs
//          (linb + INh fp16 convert) hiding their DRAM under g1's tensor work
//   g23  : sim = INh @ (aMh+aMl)^T -> tanh/masked-softmax -> attn (smem)
//          -> out = attn @ AOh (B via ldmatrix.trans), fully fused
// fp32 acc. K32 chunks, 3-stage cp.async pipelines.
// ---------------------------------------------------------------------------

#define CB 128
#define CT 256
#define CN 128
#define CAD 512
#define CVD 512

__device__ __align__(16) unsigned short g_AOh[CB * CN * CAD];
__device__ __align__(16) unsigned short g_INh[CB * CT * CVD];
__device__ __align__(16) unsigned short g_WTh[CVD * CAD];
__device__ __align__(16) unsigned short g_aMh[CB * CN * CVD];
__device__ __align__(16) unsigned short g_aMl[CB * CN * CVD];
__device__ __align__(16) float g_lina[CB * CN];
__device__ __align__(16) float g_linb[CB * CT];
__device__ __align__(16) float g_maskf[CB * CN];

// ---- smem layouts -------------------------------------------------------------
#define TILEB 8192
#define G1_A   0
#define G1_B   4096
#define STAGE1 12288
#define SMEM_G1 (3 * STAGE1)
#define SM_T0 0
#define SM_T1 TILEB
#define SM_T2 (2 * TILEB)
#define STAGE2 (3 * TILEB)
#define PH2_ATT 0
#define PH2_B   32768
#define SM_LIN (3 * STAGE2)
#define SM_MSK (SM_LIN + 512)
#define SM_LNB (SM_MSK + 512)
#define SM_RED (SM_LNB + 512)
#define SMEM_G23 (SM_RED + 2048)

__device__ __forceinline__ uint32_t smem_u32(const void* p) {
    return (uint32_t)__cvta_generic_to_shared(p);
}
__device__ __forceinline__ uint32_t swz(int row, int c16) {
    return (uint32_t)(row * 64 + ((c16 ^ ((row >> 1) & 3)) << 4));
}
__device__ __forceinline__ uint32_t swzbt(int row, int c16) {
    return (uint32_t)(row * 256 + ((c16 ^ (row & 7)) << 4));
}
__device__ __forceinline__ void ldsm4(uint32_t* r, uint32_t addr) {
    asm volatile("ldmatrix.sync.aligned.m8n8.x4.shared.b16 {%0,%1,%2,%3}, [%4];"
                 : "=r"(r[0]), "=r"(r[1]), "=r"(r[2]), "=r"(r[3]) : "r"(addr));
}
__device__ __forceinline__ void ldsm4t(uint32_t* r, uint32_t addr) {
    asm volatile("ldmatrix.sync.aligned.m8n8.x4.trans.shared.b16 {%0,%1,%2,%3}, [%4];"
                 : "=r"(r[0]), "=r"(r[1]), "=r"(r[2]), "=r"(r[3]) : "r"(addr));
}
__device__ __forceinline__ void mma_f16(float* c, const uint32_t* a,
                                        uint32_t b0, uint32_t b1) {
    asm volatile("mma.sync.aligned.m16n8k16.row.col.f32.f16.f16.f32 "
                 "{%0,%1,%2,%3}, {%4,%5,%6,%7}, {%8,%9}, {%0,%1,%2,%3};"
                 : "+f"(c[0]), "+f"(c[1]), "+f"(c[2]), "+f"(c[3])
                 : "r"(a[0]), "r"(a[1]), "r"(a[2]), "r"(a[3]), "r"(b0), "r"(b1));
}
__device__ __forceinline__ void cpa(uint32_t d, const void* g) {
    asm volatile("cp.async.cg.shared.global [%0], [%1], 16;"
                 :: "r"(d), "l"(g) : "memory");
}
__device__ __forceinline__ uint32_t pack2h(float x, float y) {
    __half2 h = __floats2half2_rn(x, y);
    return *(uint32_t*)&h;
}
__device__ __forceinline__ void split2h(float x, float y, uint32_t& h, uint32_t& l) {
    __half xh = __float2half_rn(x), yh = __float2half_rn(y);
    __half xl = __float2half_rn(x - __half2float(xh));
    __half yl = __float2half_rn(y - __half2float(yh));
    h = ((uint32_t)__half_as_ushort(yh) << 16) | __half_as_ushort(xh);
    l = ((uint32_t)__half_as_ushort(yl) << 16) | __half_as_ushort(xl);
}

// ---------------------------------------------------------------------------
// pre_a: AO rows (lina + AOh) [256 blks] + W->WTh [256 blks] + mask [1 blk].
// ---------------------------------------------------------------------------
#define PA_LIN 256
#define PA_WT  256
__global__ void __launch_bounds__(256) pre_a(
    const float* __restrict__ AO, const float* __restrict__ a_w,
    const float* __restrict__ W, const unsigned char* __restrict__ m) {
    const int bid = blockIdx.x;
    const int tid = threadIdx.x;
    if (bid < PA_LIN) {
        const int idx = bid * 8 + (tid >> 5);       // AO row 0..2047... (CB*CN=16384/8=2048)
        const int lane = tid & 31;
        // 2048 blocks would be needed for 16384 rows at 8/blk; use 8 rows/warp:
        // each warp handles 8 rows strided by 2048
        for (int rr = 0; rr < 8; ++rr) {
            const int r = idx + rr * 2048;
            const float* row = AO + (size_t)r * CAD;
            uint2* dst = (uint2*)g_AOh + (size_t)r * 128;
            float s = 0.f;
#pragma unroll
            for (int k = 0; k < 512; k += 128) {
                int e = k + lane * 4;
                float4 x = *(const float4*)(row + e);
                float4 y = *(const float4*)(a_w + e);
                s += x.x * y.x + x.y * y.y + x.z * y.z + x.w * y.w;
                dst[e >> 2] = make_uint2(pack2h(x.x, x.y), pack2h(x.z, x.w));
            }
#pragma unroll
            for (int o = 16; o; o >>= 1) s += __shfl_xor_sync(0xffffffffu, s, o);
            if (lane == 0) g_lina[r] = s;
        }
    } else if (bid < PA_LIN + PA_WT) {
        __shared__ float t[32][33];
        const int idx = bid - PA_LIN;
        const int v0 = (idx & 15) * 32, a0 = (idx >> 4) * 32;
        const int tx = tid & 31, ty = tid >> 5;
        for (int i = ty; i < 32; i += 8)
            t[i][tx] = W[(size_t)(a0 + i) * CVD + v0 + tx];
        __syncthreads();
        for (int i = ty; i < 32; i += 8)
            g_WTh[(size_t)(v0 + i) * CAD + a0 + tx] =
                __half_as_ushort(__float2half_rn(t[tx][i]));
    } else {
        __shared__ int s_notbin, s_odd;
        if (tid == 0) { s_notbin = 0; s_odd = 0; }
        __syncthreads();
        int notbin = 0, odd = 0;
        for (int i = tid; i < CB * CN; i += 256) {
            unsigned char v = m[i];
            if (v > 1) notbin = 1;
            if ((i & 3) && v == 1) odd = 1;
        }
        if (notbin) atomicOr(&s_notbin, 1);
        if (odd)    atomicOr(&s_odd, 1);
        __syncthreads();
        const int md = s_notbin ? 2 : (s_odd ? 0 : 1);
        for (int i = tid; i < CB * CN; i += 256) {
            float v;
            if (md == 0)      v = (m[i] != 0) ? 1.f : 0.f;
            else if (md == 1) v = (((const int*)(const void*)m)[i] != 0) ? 1.f : 0.f;
            else              v = (((const float*)(const void*)m)[i] != 0.f) ? 1.f : 0.f;
            g_maskf[i] = v;
        }
    }
}

// ---------------------------------------------------------------------------
// g1x: grid (4+16, 256).
//   blockIdx.x <  4 : GEMM CTA — aM tile = AOh @ WTh^T (64x128, 1 product)
//   blockIdx.x >= 4 : IN-row CTA — linb + INh fp16 convert (8 rows/warp... 1 row/warp)
//     rows: ((x-4) + y*16)*8 + warp  -> 16*256*8 = 32768 rows
// ---------------------------------------------------------------------------
__global__ void __launch_bounds__(256, 3) g1x(const float* __restrict__ IN,
                                              const float* __restrict__ b_w) {
    extern __shared__ char sm[];
    const int tid = threadIdx.x;
    if (blockIdx.x >= 4) {
        const int r = (((int)blockIdx.x - 4) + (int)blockIdx.y * 16) * 8 + (tid >> 5);
        const int lane = tid & 31;
        const float* row = IN + (size_t)r * CVD;
        uint2* dst = (uint2*)g_INh + (size_t)r * 128;
        float s = 0.f;
#pragma unroll
        for (int k = 0; k < 512; k += 128) {
            int e = k + lane * 4;
            float4 x = *(const float4*)(row + e);
            float4 y = *(const float4*)(b_w + e);
            s += x.x * y.x + x.y * y.y + x.z * y.z + x.w * y.w;
            dst[e >> 2] = make_uint2(pack2h(x.x, x.y), pack2h(x.z, x.w));
        }
#pragma unroll
        for (int o = 16; o; o >>= 1) s += __shfl_xor_sync(0xffffffffu, s, o);
        if (lane == 0) g_linb[r] = s;
        return;
    }

    const uint32_t smb = smem_u32(sm);
    const int lane = tid & 31, w = tid >> 5;
    const int n0 = blockIdx.x * 128;
    const size_t m0 = (size_t)blockIdx.y * 64;
    const int mw = (w & 1) * 32, nw = (w >> 1) * 32;
    const int grp = lane >> 3, rin = lane & 7;
    int rowm[2], rowb[2];
#pragma unroll
    for (int mi = 0; mi < 2; ++mi) rowm[mi] = mw + mi * 16 + rin + ((grp & 1) << 3);
#pragma unroll
    for (int j = 0; j < 2; ++j)    rowb[j] = nw + j * 16 + rin + ((grp & 1) << 3);
    const int cgrp = grp >> 1;

    float acc[2][4][4];
#pragma unroll
    for (int a = 0; a < 2; ++a)
#pragma unroll
        for (int b = 0; b < 4; ++b)
#pragma unroll
            for (int cc = 0; cc < 4; ++cc) acc[a][b][cc] = 0.f;

    const unsigned short* A = g_AOh + m0 * CAD;
    const unsigned short* B = g_WTh + (size_t)n0 * CAD;

    uint32_t doffA, doffB[2];
    const unsigned short *pA, *pB[2];
    {
        int rowA = tid >> 2, cA = tid & 3;
        doffA = swz(rowA, cA);
        pA = A + (size_t)rowA * CAD + cA * 8;
#pragma unroll
        for (int i = 0; i < 2; ++i) {
            int u = i * 256 + tid, row = u >> 2, c = u & 3;
            doffB[i] = swz(row, c);
            pB[i] = B + (size_t)row * CAD + c * 8;
        }
    }
#pragma unroll
    for (int s = 0; s < 2; ++s) {
        const uint32_t st = smb + (uint32_t)s * STAGE1;
        cpa(st + G1_A + doffA, pA); pA += 32;
#pragma unroll
        for (int i = 0; i < 2; ++i) {
            cpa(st + G1_B + doffB[i], pB[i]); pB[i] += 32;
        }
        asm volatile("cp.async.commit_group;" ::: "memory");
    }
    uint32_t stg = 0;
    const int nch = CAD >> 5;
    for (int c = 0; c < nch; ++c) {
        if (c == nch - 1) asm volatile("cp.async.wait_group 0;" ::: "memory");
        else              asm volatile("cp.async.wait_group 1;" ::: "memory");
        __syncthreads();
        if (c + 2 < nch) {
            uint32_t s2 = stg + 2; if (s2 >= 3) s2 -= 3;
            const uint32_t st2 = smb + s2 * STAGE1;
            cpa(st2 + G1_A + doffA, pA); pA += 32;
#pragma unroll
            for (int i = 0; i < 2; ++i) {
                cpa(st2 + G1_B + doffB[i], pB[i]); pB[i] += 32;
            }
            asm volatile("cp.async.commit_group;" ::: "memory");
        }
        const uint32_t st = smb + stg * STAGE1;
#pragma unroll
        for (int ks = 0; ks < 2; ++ks) {
            const int cu = 2 * ks + cgrp;
            uint32_t b0[4], b1[4], a0[4], a1[4];
            ldsm4(b0, st + G1_B + swz(rowb[0], cu));
            ldsm4(b1, st + G1_B + swz(rowb[1], cu));
            ldsm4(a0, st + G1_A + swz(rowm[0], cu));
            ldsm4(a1, st + G1_A + swz(rowm[1], cu));
#pragma unroll
            for (int nj = 0; nj < 4; ++nj) {
                const int o = nj & 1;
                const uint32_t* bb = (nj < 2) ? b0 : b1;
                mma_f16(acc[0][nj], a0, bb[o], bb[o + 2]);
                mma_f16(acc[1][nj], a1, bb[o], bb[o + 2]);
            }
        }
        if (++stg == 3) stg = 0;
    }

    const int qr = lane >> 2, qc = (lane & 3) * 2;
    uint32_t* ghi = (uint32_t*)g_aMh;
    uint32_t* glo = (uint32_t*)g_aMl;
#pragma unroll
    for (int mi = 0; mi < 2; ++mi)
#pragma unroll
        for (int nj = 0; nj < 4; ++nj) {
            size_t r0 = m0 + mw + mi * 16 + qr;
            size_t cp = (size_t)(n0 + nw + nj * 8 + qc) >> 1;
            uint32_t h, l;
            split2h(acc[mi][nj][0], acc[mi][nj][1], h, l);
            ghi[r0 * (CVD >> 1) + cp] = h; glo[r0 * (CVD >> 1) + cp] = l;
            split2h(acc[mi][nj][2], acc[mi][nj][3], h, l);
            ghi[(r0 + 8) * (CVD >> 1) + cp] = h; glo[(r0 + 8) * (CVD >> 1) + cp] = l;
        }
}

// ---------------------------------------------------------------------------
// G23: sim = INh @ (aMh+aMl)^T -> softmax -> attn (smem) -> out = attn @ AOh.
//      grid (2 Mtiles, B), 256 threads, 2 CTAs/SM.
// ---------------------------------------------------------------------------
__global__ void __launch_bounds__(256, 2) g23_mma(const float* __restrict__ biasp,
                                                  float* __restrict__ OUT) {
    extern __shared__ char sm[];
    const uint32_t smb = smem_u32(sm);
    const int tid = threadIdx.x;
    const int b = blockIdx.y;
    const int m0 = blockIdx.x * 128;
    float* sl  = (float*)(sm + SM_LIN);
    float* sk  = (float*)(sm + SM_MSK);
    float* slb = (float*)(sm + SM_LNB);
    float* red = (float*)(sm + SM_RED);
    if (tid < 128) {
        sl[tid]  = g_lina[b * CN + tid];
        sk[tid]  = g_maskf[b * CN + tid];
        slb[tid] = g_linb[b * CT + m0 + tid];
    }
    const int lane = tid & 31, w = tid >> 5;
    const int mw = (w & 1) * 64, nw = (w >> 1) * 32;
    const int grp = lane >> 3, rin = lane & 7;
    int rowm[4], rowb[2];
#pragma unroll
    for (int mi = 0; mi < 4; ++mi) rowm[mi] = mw + mi * 16 + rin + ((grp & 1) << 3);
#pragma unroll
    for (int j = 0; j < 2; ++j)    rowb[j] = nw + j * 16 + rin + ((grp & 1) << 3);
    const int cgrp = grp >> 1;

    float acc[4][4][4];
#pragma unroll
    for (int a = 0; a < 4; ++a)
#pragma unroll
        for (int bb = 0; bb < 4; ++bb)
#pragma unroll
            for (int cc = 0; cc < 4; ++cc) acc[a][bb][cc] = 0.f;

    // ---------------- phase 1: sim mainloop (2 products) ----------------
    const unsigned short* A  = g_INh + ((size_t)b * CT + m0) * CVD;
    const unsigned short* Bh = g_aMh + (size_t)b * CN * CVD;
    const unsigned short* Bl = g_aMl + (size_t)b * CN * CVD;

    uint32_t doff[2];
    const unsigned short *pA[2], *pBh[2], *pBl[2];
#pragma unroll
    for (int i = 0; i < 2; ++i) {
        int u = i * 256 + tid, row = u >> 2, c = u & 3;
        doff[i] = swz(row, c);
        pA[i]  = A  + (size_t)row * CVD + c * 8;
        pBh[i] = Bh + (size_t)row * CVD + c * 8;
        pBl[i] = Bl + (size_t)row * CVD + c * 8;
    }
#pragma unroll
    for (int s = 0; s < 2; ++s) {
        const uint32_t st = smb + (uint32_t)s * STAGE2;
#pragma unroll
        for (int i = 0; i < 2; ++i) {
            cpa(st + SM_T0 + doff[i], pA[i]);
            cpa(st + SM_T1 + doff[i], pBh[i]);
            cpa(st + SM_T2 + doff[i], pBl[i]);
            pA[i] += 32; pBh[i] += 32; pBl[i] += 32;
        }
        asm volatile("cp.async.commit_group;" ::: "memory");
    }
    uint32_t stg = 0;
    const int nch = CVD >> 5;
    for (int c = 0; c < nch; ++c) {
        if (c == nch - 1) asm volatile("cp.async.wait_group 0;" ::: "memory");
        else              asm volatile("cp.async.wait_group 1;" ::: "memory");
        __syncthreads();
        if (c + 2 < nch) {
            uint32_t s2 = stg + 2; if (s2 >= 3) s2 -= 3;
            const uint32_t st2 = smb + s2 * STAGE2;
#pragma unroll
            for (int i = 0; i < 2; ++i) {
                cpa(st2 + SM_T0 + doff[i], pA[i]);
                cpa(st2 + SM_T1 + doff[i], pBh[i]);
                cpa(st2 + SM_T2 + doff[i], pBl[i]);
                pA[i] += 32; pBh[i] += 32; pBl[i] += 32;
            }
            asm volatile("cp.async.commit_group;" ::: "memory");
        }
        const uint32_t st = smb + stg * STAGE2;
#pragma unroll
        for (int ks = 0; ks < 2; ++ks) {
            const int cu = 2 * ks + cgrp;
            uint32_t bh[2][4], bl[2][4];
#pragma unroll
            for (int j = 0; j < 2; ++j) {
                ldsm4(bh[j], st + SM_T1 + swz(rowb[j], cu));
                ldsm4(bl[j], st + SM_T2 + swz(rowb[j], cu));
            }
            uint32_t a2[2][4];
            ldsm4(a2[0], st + SM_T0 + swz(rowm[0], cu));
#pragma unroll
            for (int mi = 0; mi < 4; ++mi) {
                const int cur = mi & 1;
                if (mi < 3) ldsm4(a2[cur ^ 1], st + SM_T0 + swz(rowm[mi + 1], cu));
#pragma unroll
                for (int nj = 0; nj < 4; ++nj) {
                    const int j = nj >> 1, o = nj & 1;
                    mma_f16(acc[mi][nj], a2[cur], bh[j][o], bh[j][o + 2]);
                }
#pragma unroll
                for (int nj = 0; nj < 4; ++nj) {
                    const int j = nj >> 1, o = nj & 1;
                    mma_f16(acc[mi][nj], a2[cur], bl[j][o], bl[j][o + 2]);
                }
            }
        }
        if (++stg == 3) stg = 0;
    }
    __syncthreads();

    // ---- phase-2 B preloads (overlap with softmax epilogue) ----
    uint32_t doffB2[2];
    const unsigned short* pB2[2];
#pragma unroll
    for (int i = 0; i < 2; ++i) {
        int u = i * 256 + tid;
        int rowB = u >> 4, cB = u & 15;
        doffB2[i] = swzbt(rowB, cB);
        pB2[i] = g_AOh + (size_t)b * CN * CAD + (size_t)rowB * CAD + cB * 8;
    }
#pragma unroll
    for (int s = 0; s < 2; ++s) {
        const uint32_t st = smb + PH2_B + (uint32_t)s * TILEB;
#pragma unroll
        for (int i = 0; i < 2; ++i)
            cpa(st + doffB2[i], pB2[i] + (size_t)(s * 32) * CAD);
        asm volatile("cp.async.commit_group;" ::: "memory");
    }

    // ---- softmax epilogue (register-resident) ----
    const int qr = lane >> 2, qc = (lane & 3) * 2;
    const float bs = biasp[0];
    float part[4][2];
#pragma unroll
    for (int mi = 0; mi < 4; ++mi)
#pragma unroll
        for (int p = 0; p < 2; ++p) part[mi][p] = 0.f;
#pragma unroll
    for (int mi = 0; mi < 4; ++mi)
#pragma unroll
        for (int nj = 0; nj < 4; ++nj) {
            int c0 = nw + nj * 8 + qc;
            float sla = sl[c0], slA = sl[c0 + 1];
            float mk0 = sk[c0], mk1 = sk[c0 + 1];
#pragma unroll
            for (int p = 0; p < 2; ++p) {
                int r = mw + mi * 16 + qr + p * 8;
                float lb = slb[r] + bs;
                float e0 = mk0 * __expf(tanhf(acc[mi][nj][2 * p] + sla + lb));
                float e1 = mk1 * __expf(tanhf(acc[mi][nj][2 * p + 1] + slA + lb));
                acc[mi][nj][2 * p]     = e0;
                acc[mi][nj][2 * p + 1] = e1;
                part[mi][p] += e0 + e1;
            }
        }
#pragma unroll
    for (int mi = 0; mi < 4; ++mi)
#pragma unroll
        for (int p = 0; p < 2; ++p) {
            part[mi][p] += __shfl_xor_sync(0xffffffffu, part[mi][p], 1);
            part[mi][p] += __shfl_xor_sync(0xffffffffu, part[mi][p], 2);
        }
    if ((lane & 3) == 0) {
#pragma unroll
        for (int mi = 0; mi < 4; ++mi)
#pragma unroll
            for (int p = 0; p < 2; ++p) {
                int r = mw + mi * 16 + qr + p * 8;
                red[r * 4 + (w >> 1)] = part[mi][p];
            }
    }
    __syncthreads();
#pragma unroll
    for (int mi = 0; mi < 4; ++mi)
#pragma unroll
        for (int p = 0; p < 2; ++p) {
            int r = mw + mi * 16 + qr + p * 8;
            float4 rv = *(float4*)&red[r * 4];
            float inv = 1.0f / (rv.x + rv.y + rv.z + rv.w + 1e-30f);
#pragma unroll
            for (int nj = 0; nj < 4; ++nj) {
                uint32_t addr = smb + PH2_ATT + (uint32_t)(nw >> 5) * TILEB
                              + swz(r, nj) + qc * 2;
                uint32_t pk = pack2h(acc[mi][nj][2 * p] * inv,
                                     acc[mi][nj][2 * p + 1] * inv);
                asm volatile("st.shared.b32 [%0], %1;" :: "r"(addr), "r"(pk)
                             : "memory");
            }
        }

    // ---------------- phase 2: out = attn @ AOh (B trans) ----------------
    float acc2[4][4][4];
#pragma unroll
    for (int a = 0; a < 4; ++a)
#pragma unroll
        for (int bb = 0; bb < 4; ++bb)
#pragma unroll
            for (int cc = 0; cc < 4; ++cc) acc2[a][bb][cc] = 0.f;

    uint32_t stg2 = 0;
    for (int idx = 0; idx < 16; ++idx) {
        if (idx == 15) asm volatile("cp.async.wait_group 0;" ::: "memory");
        else           asm volatile("cp.async.wait_group 1;" ::: "memory");
        __syncthreads();
        if (idx + 2 < 16) {
            uint32_t s2 = stg2 + 2; if (s2 >= 3) s2 -= 3;
            const uint32_t st2 = smb + PH2_B + s2 * TILEB;
            const int nidx = idx + 2;
            const size_t boff = (size_t)((nidx & 3) * 32) * CAD + (nidx >> 2) * 128;
#pragma unroll
            for (int i = 0; i < 2; ++i)
                cpa(st2 + doffB2[i], pB2[i] + boff);
            asm volatile("cp.async.commit_group;" ::: "memory");
        }
        const uint32_t stB = smb + PH2_B + stg2 * TILEB;
        const uint32_t stA = smb + PH2_ATT + (uint32_t)(idx & 3) * TILEB;
#pragma unroll
        for (int ks = 0; ks < 2; ++ks) {
            const int cu = 2 * ks + cgrp;
            const int browk = 16 * ks + rin + ((grp >> 1) << 3);
            uint32_t bt[2][4];
#pragma unroll
            for (int j = 0; j < 2; ++j) {
                const int bc = (nw >> 3) + 2 * j + (grp & 1);
                ldsm4t(bt[j], stB + swzbt(browk, bc));
            }
            uint32_t a2[2][4];
            ldsm4(a2[0], stA + swz(rowm[0], cu));
#pragma unroll
            for (int mi = 0; mi < 4; ++mi) {
                const int cur = mi & 1;
                if (mi < 3) ldsm4(a2[cur ^ 1], stA + swz(rowm[mi + 1], cu));
#pragma unroll
                for (int nj = 0; nj < 4; ++nj) {
                    const int j = nj >> 1, o = nj & 1;
                    mma_f16(acc2[mi][nj], a2[cur], bt[j][o], bt[j][o + 2]);
                }
            }
        }
        if ((idx & 3) == 3) {
            const int v0 = (idx >> 2) * 128;
#pragma unroll
            for (int mi = 0; mi < 4; ++mi)
#pragma unroll
                for (int nj = 0; nj < 4; ++nj) {
                    size_t r0 = (size_t)b * CT + m0 + mw + mi * 16 + qr;
                    int gc = v0 + nw + nj * 8 + qc;
                    *(float2*)(OUT + r0 * CAD + gc) =
                        make_float2(acc2[mi][nj][0], acc2[mi][nj][1]);
                    *(float2*)(OUT + (r0 + 8) * CAD + gc) =
                        make_float2(acc2[mi][nj][2], acc2[mi][nj][3]);
                    acc2[mi][nj][0] = 0.f; acc2[mi][nj][1] = 0.f;
                    acc2[mi][nj][2] = 0.f; acc2[mi][nj][3] = 0.f;
                }
        }
        if (++stg2 == 3) stg2 = 0;
    }
}

// ---------------------------------------------------------------------------
extern "C" void kernel_launch(void* const* d_in, const int* in_sizes, int n_in,
                              void* d_out, int out_size) {
    const float* inputs = (const float*)d_in[0];
    const float* ao     = (const float*)d_in[1];
    const void*  mask   = d_in[2];
    const float* W      = (const float*)d_in[3];
    const float* a_w    = (const float*)d_in[4];
    const float* b_w    = (const float*)d_in[5];
    const float* bias   = (const float*)d_in[6];
    float* out = (float*)d_out;

    cudaFuncSetAttribute(g1x,     cudaFuncAttributeMaxDynamicSharedMemorySize, SMEM_G1);
    cudaFuncSetAttribute(g23_mma, cudaFuncAttributeMaxDynamicSharedMemorySize, SMEM_G23);

    pre_a<<<PA_LIN + PA_WT + 1, 256>>>(ao, a_w, W,
                                       (const unsigned char*)mask);   // 0
    g1x<<<dim3(20, 256), 256, SMEM_G1>>>(inputs, b_w);                // 1
    g23_mma<<<dim3(2, CB), 256, SMEM_G23>>>(bias, out);               // 2
}

// round 12
// speedup vs baseline: 5.4137x; 1.1391x over previous
#include <cuda_runtime.h>
#include <cuda_fp16.h>
#include <cstdint>

// ---------------------------------------------------------------------------
// GeneralizedBilinearAttention via mma.sync fp16 (base sm_103 ISA).
//   pre_a: AO rows (lina + AOh fp16) + W->WTh + mask
//   g1x  : aM = AOh @ WTh^T (64x128 tiles, 1 product) + co-scheduled IN rows
//   g23  : sim = INh @ aMh^T (1 product) -> tanh/masked-softmax -> attn(smem)
//          -> out = attn @ AOh (B via ldmatrix.trans), fully fused
// fp32 acc. K32 chunks, 3-stage cp.async pipelines.
// ---------------------------------------------------------------------------

#define CB 128
#define CT 256
#define CN 128
#define CAD 512
#define CVD 512

__device__ __align__(16) unsigned short g_AOh[CB * CN * CAD];
__device__ __align__(16) unsigned short g_INh[CB * CT * CVD];
__device__ __align__(16) unsigned short g_WTh[CVD * CAD];
__device__ __align__(16) unsigned short g_aMh[CB * CN * CVD];
__device__ __align__(16) float g_lina[CB * CN];
__device__ __align__(16) float g_linb[CB * CT];
__device__ __align__(16) float g_maskf[CB * CN];

// ---- smem layouts -------------------------------------------------------------
#define TILEB 8192
// g1: A 64x32 (4KB) + B 128x32 (8KB)
#define G1_A   0
#define G1_B   4096
#define STAGE1 12288
#define SMEM_G1 (3 * STAGE1)
// g23 phase 1: A, Bh (8KB each) = 16KB/stage, 3 stages = 48KB
#define SM_T0 0
#define SM_T1 TILEB
#define STAGE2 (2 * TILEB)
// g23 phase 2 overlay: attn 4x8KB at 0, B stages at 32KB (3x8KB)
#define PH2_ATT 0
#define PH2_B   32768
#define SM_LIN  57344
#define SM_MSK (SM_LIN + 512)
#define SM_LNB (SM_MSK + 512)
#define SM_RED (SM_LNB + 512)
#define SMEM_G23 (SM_RED + 2048)     // 60928

__device__ __forceinline__ uint32_t smem_u32(const void* p) {
    return (uint32_t)__cvta_generic_to_shared(p);
}
__device__ __forceinline__ uint32_t swz(int row, int c16) {
    return (uint32_t)(row * 64 + ((c16 ^ ((row >> 1) & 3)) << 4));
}
__device__ __forceinline__ uint32_t swzbt(int row, int c16) {
    return (uint32_t)(row * 256 + ((c16 ^ (row & 7)) << 4));
}
__device__ __forceinline__ void ldsm4(uint32_t* r, uint32_t addr) {
    asm volatile("ldmatrix.sync.aligned.m8n8.x4.shared.b16 {%0,%1,%2,%3}, [%4];"
                 : "=r"(r[0]), "=r"(r[1]), "=r"(r[2]), "=r"(r[3]) : "r"(addr));
}
__device__ __forceinline__ void ldsm4t(uint32_t* r, uint32_t addr) {
    asm volatile("ldmatrix.sync.aligned.m8n8.x4.trans.shared.b16 {%0,%1,%2,%3}, [%4];"
                 : "=r"(r[0]), "=r"(r[1]), "=r"(r[2]), "=r"(r[3]) : "r"(addr));
}
__device__ __forceinline__ void mma_f16(float* c, const uint32_t* a,
                                        uint32_t b0, uint32_t b1) {
    asm volatile("mma.sync.aligned.m16n8k16.row.col.f32.f16.f16.f32 "
                 "{%0,%1,%2,%3}, {%4,%5,%6,%7}, {%8,%9}, {%0,%1,%2,%3};"
                 : "+f"(c[0]), "+f"(c[1]), "+f"(c[2]), "+f"(c[3])
                 : "r"(a[0]), "r"(a[1]), "r"(a[2]), "r"(a[3]), "r"(b0), "r"(b1));
}
__device__ __forceinline__ void cpa(uint32_t d, const void* g) {
    asm volatile("cp.async.cg.shared.global [%0], [%1], 16;"
                 :: "r"(d), "l"(g) : "memory");
}
__device__ __forceinline__ uint32_t pack2h(float x, float y) {
    __half2 h = __floats2half2_rn(x, y);
    return *(uint32_t*)&h;
}

// ---------------------------------------------------------------------------
// pre_a: AO rows [2048 blks x 8 warps x 1 row] + W->WTh [256] + mask [1].
// ---------------------------------------------------------------------------
#define PA_LIN 2048
#define PA_WT  256
__global__ void __launch_bounds__(256) pre_a(
    const float* __restrict__ AO, const float* __restrict__ a_w,
    const float* __restrict__ W, const unsigned char* __restrict__ m) {
    const int bid = blockIdx.x;
    const int tid = threadIdx.x;
    if (bid < PA_LIN) {
        const int r = bid * 8 + (tid >> 5);
        const int lane = tid & 31;
        const float* row = AO + (size_t)r * CAD;
        uint2* dst = (uint2*)g_AOh + (size_t)r * 128;
        float s = 0.f;
#pragma unroll
        for (int k = 0; k < 512; k += 128) {
            int e = k + lane * 4;
            float4 x = *(const float4*)(row + e);
            float4 y = *(const float4*)(a_w + e);
            s += x.x * y.x + x.y * y.y + x.z * y.z + x.w * y.w;
            dst[e >> 2] = make_uint2(pack2h(x.x, x.y), pack2h(x.z, x.w));
        }
#pragma unroll
        for (int o = 16; o; o >>= 1) s += __shfl_xor_sync(0xffffffffu, s, o);
        if (lane == 0) g_lina[r] = s;
    } else if (bid < PA_LIN + PA_WT) {
        __shared__ float t[32][33];
        const int idx = bid - PA_LIN;
        const int v0 = (idx & 15) * 32, a0 = (idx >> 4) * 32;
        const int tx = tid & 31, ty = tid >> 5;
        for (int i = ty; i < 32; i += 8)
            t[i][tx] = W[(size_t)(a0 + i) * CVD + v0 + tx];
        __syncthreads();
        for (int i = ty; i < 32; i += 8)
            g_WTh[(size_t)(v0 + i) * CAD + a0 + tx] =
                __half_as_ushort(__float2half_rn(t[tx][i]));
    } else {
        __shared__ int s_notbin, s_odd;
        if (tid == 0) { s_notbin = 0; s_odd = 0; }
        __syncthreads();
        int notbin = 0, odd = 0;
        for (int i = tid; i < CB * CN; i += 256) {
            unsigned char v = m[i];
            if (v > 1) notbin = 1;
            if ((i & 3) && v == 1) odd = 1;
        }
        if (notbin) atomicOr(&s_notbin, 1);
        if (odd)    atomicOr(&s_odd, 1);
        __syncthreads();
        const int md = s_notbin ? 2 : (s_odd ? 0 : 1);
        for (int i = tid; i < CB * CN; i += 256) {
            float v;
            if (md == 0)      v = (m[i] != 0) ? 1.f : 0.f;
            else if (md == 1) v = (((const int*)(const void*)m)[i] != 0) ? 1.f : 0.f;
            else              v = (((const float*)(const void*)m)[i] != 0.f) ? 1.f : 0.f;
            g_maskf[i] = v;
        }
    }
}

// ---------------------------------------------------------------------------
// g1x: grid (4+16, 256).
//   x <  4 : GEMM CTA — aM tile = AOh @ WTh^T (64x128, 1 product)
//   x >= 4 : IN-row CTA — linb + INh fp16 convert (1 row/warp)
// ---------------------------------------------------------------------------
__global__ void __launch_bounds__(256, 3) g1x(const float* __restrict__ IN,
                                              const float* __restrict__ b_w) {
    extern __shared__ char sm[];
    const int tid = threadIdx.x;
    if (blockIdx.x >= 4) {
        const int r = (((int)blockIdx.x - 4) + (int)blockIdx.y * 16) * 8 + (tid >> 5);
        const int lane = tid & 31;
        const float* row = IN + (size_t)r * CVD;
        uint2* dst = (uint2*)g_INh + (size_t)r * 128;
        float s = 0.f;
#pragma unroll
        for (int k = 0; k < 512; k += 128) {
            int e = k + lane * 4;
            float4 x = *(const float4*)(row + e);
            float4 y = *(const float4*)(b_w + e);
            s += x.x * y.x + x.y * y.y + x.z * y.z + x.w * y.w;
            dst[e >> 2] = make_uint2(pack2h(x.x, x.y), pack2h(x.z, x.w));
        }
#pragma unroll
        for (int o = 16; o; o >>= 1) s += __shfl_xor_sync(0xffffffffu, s, o);
        if (lane == 0) g_linb[r] = s;
        return;
    }

    const uint32_t smb = smem_u32(sm);
    const int lane = tid & 31, w = tid >> 5;
    const int n0 = blockIdx.x * 128;
    const size_t m0 = (size_t)blockIdx.y * 64;
    const int mw = (w & 1) * 32, nw = (w >> 1) * 32;
    const int grp = lane >> 3, rin = lane & 7;
    int rowm[2], rowb[2];
#pragma unroll
    for (int mi = 0; mi < 2; ++mi) rowm[mi] = mw + mi * 16 + rin + ((grp & 1) << 3);
#pragma unroll
    for (int j = 0; j < 2; ++j)    rowb[j] = nw + j * 16 + rin + ((grp & 1) << 3);
    const int cgrp = grp >> 1;

    float acc[2][4][4];
#pragma unroll
    for (int a = 0; a < 2; ++a)
#pragma unroll
        for (int b = 0; b < 4; ++b)
#pragma unroll
            for (int cc = 0; cc < 4; ++cc) acc[a][b][cc] = 0.f;

    const unsigned short* A = g_AOh + m0 * CAD;
    const unsigned short* B = g_WTh + (size_t)n0 * CAD;

    uint32_t doffA, doffB[2];
    const unsigned short *pA, *pB[2];
    {
        int rowA = tid >> 2, cA = tid & 3;
        doffA = swz(rowA, cA);
        pA = A + (size_t)rowA * CAD + cA * 8;
#pragma unroll
        for (int i = 0; i < 2; ++i) {
            int u = i * 256 + tid, row = u >> 2, c = u & 3;
            doffB[i] = swz(row, c);
            pB[i] = B + (size_t)row * CAD + c * 8;
        }
    }
#pragma unroll
    for (int s = 0; s < 2; ++s) {
        const uint32_t st = smb + (uint32_t)s * STAGE1;
        cpa(st + G1_A + doffA, pA); pA += 32;
#pragma unroll
        for (int i = 0; i < 2; ++i) {
            cpa(st + G1_B + doffB[i], pB[i]); pB[i] += 32;
        }
        asm volatile("cp.async.commit_group;" ::: "memory");
    }
    uint32_t stg = 0;
    const int nch = CAD >> 5;
    for (int c = 0; c < nch; ++c) {
        if (c == nch - 1) asm volatile("cp.async.wait_group 0;" ::: "memory");
        else              asm volatile("cp.async.wait_group 1;" ::: "memory");
        __syncthreads();
        if (c + 2 < nch) {
            uint32_t s2 = stg + 2; if (s2 >= 3) s2 -= 3;
            const uint32_t st2 = smb + s2 * STAGE1;
            cpa(st2 + G1_A + doffA, pA); pA += 32;
#pragma unroll
            for (int i = 0; i < 2; ++i) {
                cpa(st2 + G1_B + doffB[i], pB[i]); pB[i] += 32;
            }
            asm volatile("cp.async.commit_group;" ::: "memory");
        }
        const uint32_t st = smb + stg * STAGE1;
#pragma unroll
        for (int ks = 0; ks < 2; ++ks) {
            const int cu = 2 * ks + cgrp;
            uint32_t b0[4], b1[4], a0[4], a1[4];
            ldsm4(b0, st + G1_B + swz(rowb[0], cu));
            ldsm4(b1, st + G1_B + swz(rowb[1], cu));
            ldsm4(a0, st + G1_A + swz(rowm[0], cu));
            ldsm4(a1, st + G1_A + swz(rowm[1], cu));
#pragma unroll
            for (int nj = 0; nj < 4; ++nj) {
                const int o = nj & 1;
                const uint32_t* bb = (nj < 2) ? b0 : b1;
                mma_f16(acc[0][nj], a0, bb[o], bb[o + 2]);
                mma_f16(acc[1][nj], a1, bb[o], bb[o + 2]);
            }
        }
        if (++stg == 3) stg = 0;
    }

    const int qr = lane >> 2, qc = (lane & 3) * 2;
    uint32_t* ghi = (uint32_t*)g_aMh;
#pragma unroll
    for (int mi = 0; mi < 2; ++mi)
#pragma unroll
        for (int nj = 0; nj < 4; ++nj) {
            size_t r0 = m0 + mw + mi * 16 + qr;
            size_t cp = (size_t)(n0 + nw + nj * 8 + qc) >> 1;
            ghi[r0 * (CVD >> 1) + cp] =
                pack2h(acc[mi][nj][0], acc[mi][nj][1]);
            ghi[(r0 + 8) * (CVD >> 1) + cp] =
                pack2h(acc[mi][nj][2], acc[mi][nj][3]);
        }
}

// ---------------------------------------------------------------------------
// G23: sim = INh @ aMh^T (1 product) -> softmax -> attn(smem) -> out = attn @ AOh.
//      grid (2 Mtiles, B), 256 threads, 2 CTAs/SM.
// ---------------------------------------------------------------------------
__global__ void __launch_bounds__(256, 2) g23_mma(const float* __restrict__ biasp,
                                                  float* __restrict__ OUT) {
    extern __shared__ char sm[];
    const uint32_t smb = smem_u32(sm);
    const int tid = threadIdx.x;
    const int b = blockIdx.y;
    const int m0 = blockIdx.x * 128;
    float* sl  = (float*)(sm + SM_LIN);
    float* sk  = (float*)(sm + SM_MSK);
    float* slb = (float*)(sm + SM_LNB);
    float* red = (float*)(sm + SM_RED);
    if (tid < 128) {
        sl[tid]  = g_lina[b * CN + tid];
        sk[tid]  = g_maskf[b * CN + tid];
        slb[tid] = g_linb[b * CT + m0 + tid];
    }
    const int lane = tid & 31, w = tid >> 5;
    const int mw = (w & 1) * 64, nw = (w >> 1) * 32;
    const int grp = lane >> 3, rin = lane & 7;
    int rowm[4], rowb[2];
#pragma unroll
    for (int mi = 0; mi < 4; ++mi) rowm[mi] = mw + mi * 16 + rin + ((grp & 1) << 3);
#pragma unroll
    for (int j = 0; j < 2; ++j)    rowb[j] = nw + j * 16 + rin + ((grp & 1) << 3);
    const int cgrp = grp >> 1;

    float acc[4][4][4];
#pragma unroll
    for (int a = 0; a < 4; ++a)
#pragma unroll
        for (int bb = 0; bb < 4; ++bb)
#pragma unroll
            for (int cc = 0; cc < 4; ++cc) acc[a][bb][cc] = 0.f;

    // ---------------- phase 1: sim mainloop (1 product) ----------------
    const unsigned short* A  = g_INh + ((size_t)b * CT + m0) * CVD;
    const unsigned short* Bh = g_aMh + (size_t)b * CN * CVD;

    uint32_t doff[2];
    const unsigned short *pA[2], *pBh[2];
#pragma unroll
    for (int i = 0; i < 2; ++i) {
        int u = i * 256 + tid, row = u >> 2, c = u & 3;
        doff[i] = swz(row, c);
        pA[i]  = A  + (size_t)row * CVD + c * 8;
        pBh[i] = Bh + (size_t)row * CVD + c * 8;
    }
#pragma unroll
    for (int s = 0; s < 2; ++s) {
        const uint32_t st = smb + (uint32_t)s * STAGE2;
#pragma unroll
        for (int i = 0; i < 2; ++i) {
            cpa(st + SM_T0 + doff[i], pA[i]);
            cpa(st + SM_T1 + doff[i], pBh[i]);
            pA[i] += 32; pBh[i] += 32;
        }
        asm volatile("cp.async.commit_group;" ::: "memory");
    }
    uint32_t stg = 0;
    const int nch = CVD >> 5;
    for (int c = 0; c < nch; ++c) {
        if (c == nch - 1) asm volatile("cp.async.wait_group 0;" ::: "memory");
        else              asm volatile("cp.async.wait_group 1;" ::: "memory");
        __syncthreads();
        if (c + 2 < nch) {
            uint32_t s2 = stg + 2; if (s2 >= 3) s2 -= 3;
            const uint32_t st2 = smb + s2 * STAGE2;
#pragma unroll
            for (int i = 0; i < 2; ++i) {
                cpa(st2 + SM_T0 + doff[i], pA[i]);
                cpa(st2 + SM_T1 + doff[i], pBh[i]);
                pA[i] += 32; pBh[i] += 32;
            }
            asm volatile("cp.async.commit_group;" ::: "memory");
        }
        const uint32_t st = smb + stg * STAGE2;
#pragma unroll
        for (int ks = 0; ks < 2; ++ks) {
            const int cu = 2 * ks + cgrp;
            uint32_t bh[2][4];
#pragma unroll
            for (int j = 0; j < 2; ++j)
                ldsm4(bh[j], st + SM_T1 + swz(rowb[j], cu));
            uint32_t a2[2][4];
            ldsm4(a2[0], st + SM_T0 + swz(rowm[0], cu));
#pragma unroll
            for (int mi = 0; mi < 4; ++mi) {
                const int cur = mi & 1;
                if (mi < 3) ldsm4(a2[cur ^ 1], st + SM_T0 + swz(rowm[mi + 1], cu));
#pragma unroll
                for (int nj = 0; nj < 4; ++nj) {
                    const int j = nj >> 1, o = nj & 1;
                    mma_f16(acc[mi][nj], a2[cur], bh[j][o], bh[j][o + 2]);
                }
            }
        }
        if (++stg == 3) stg = 0;
    }
    __syncthreads();

    // ---- phase-2 B preloads (overlap with softmax epilogue) ----
    uint32_t doffB2[2];
    const unsigned short* pB2[2];
#pragma unroll
    for (int i = 0; i < 2; ++i) {
        int u = i * 256 + tid;
        int rowB = u >> 4, cB = u & 15;
        doffB2[i] = swzbt(rowB, cB);
        pB2[i] = g_AOh + (size_t)b * CN * CAD + (size_t)rowB * CAD + cB * 8;
    }
#pragma unroll
    for (int s = 0; s < 2; ++s) {
        const uint32_t st = smb + PH2_B + (uint32_t)s * TILEB;
#pragma unroll
        for (int i = 0; i < 2; ++i)
            cpa(st + doffB2[i], pB2[i] + (size_t)(s * 32) * CAD);
        asm volatile("cp.async.commit_group;" ::: "memory");
    }

    // ---- softmax epilogue (register-resident) ----
    const int qr = lane >> 2, qc = (lane & 3) * 2;
    const float bs = biasp[0];
    float part[4][2];
#pragma unroll
    for (int mi = 0; mi < 4; ++mi)
#pragma unroll
        for (int p = 0; p < 2; ++p) part[mi][p] = 0.f;
#pragma unroll
    for (int mi = 0; mi < 4; ++mi)
#pragma unroll
        for (int nj = 0; nj < 4; ++nj) {
            int c0 = nw + nj * 8 + qc;
            float sla = sl[c0], slA = sl[c0 + 1];
            float mk0 = sk[c0], mk1 = sk[c0 + 1];
#pragma unroll
            for (int p = 0; p < 2; ++p) {
                int r = mw + mi * 16 + qr + p * 8;
                float lb = slb[r] + bs;
                float e0 = mk0 * __expf(tanhf(acc[mi][nj][2 * p] + sla + lb));
                float e1 = mk1 * __expf(tanhf(acc[mi][nj][2 * p + 1] + slA + lb));
                acc[mi][nj][2 * p]     = e0;
                acc[mi][nj][2 * p + 1] = e1;
                part[mi][p] += e0 + e1;
            }
        }
#pragma unroll
    for (int mi = 0; mi < 4; ++mi)
#pragma unroll
        for (int p = 0; p < 2; ++p) {
            part[mi][p] += __shfl_xor_sync(0xffffffffu, part[mi][p], 1);
            part[mi][p] += __shfl_xor_sync(0xffffffffu, part[mi][p], 2);
        }
    if ((lane & 3) == 0) {
#pragma unroll
        for (int mi = 0; mi < 4; ++mi)
#pragma unroll
            for (int p = 0; p < 2; ++p) {
                int r = mw + mi * 16 + qr + p * 8;
                red[r * 4 + (w >> 1)] = part[mi][p];
            }
    }
    __syncthreads();
#pragma unroll
    for (int mi = 0; mi < 4; ++mi)
#pragma unroll
        for (int p = 0; p < 2; ++p) {
            int r = mw + mi * 16 + qr + p * 8;
            float4 rv = *(float4*)&red[r * 4];
            float inv = 1.0f / (rv.x + rv.y + rv.z + rv.w + 1e-30f);
#pragma unroll
            for (int nj = 0; nj < 4; ++nj) {
                uint32_t addr = smb + PH2_ATT + (uint32_t)(nw >> 5) * TILEB
                              + swz(r, nj) + qc * 2;
                uint32_t pk = pack2h(acc[mi][nj][2 * p] * inv,
                                     acc[mi][nj][2 * p + 1] * inv);
                asm volatile("st.shared.b32 [%0], %1;" :: "r"(addr), "r"(pk)
                             : "memory");
            }
        }

    // ---------------- phase 2: out = attn @ AOh (B trans) ----------------
    float acc2[4][4][4];
#pragma unroll
    for (int a = 0; a < 4; ++a)
#pragma unroll
        for (int bb = 0; bb < 4; ++bb)
#pragma unroll
            for (int cc = 0; cc < 4; ++cc) acc2[a][bb][cc] = 0.f;

    uint32_t stg2 = 0;
    for (int idx = 0; idx < 16; ++idx) {
        if (idx == 15) asm volatile("cp.async.wait_group 0;" ::: "memory");
        else           asm volatile("cp.async.wait_group 1;" ::: "memory");
        __syncthreads();
        if (idx + 2 < 16) {
            uint32_t s2 = stg2 + 2; if (s2 >= 3) s2 -= 3;
            const uint32_t st2 = smb + PH2_B + s2 * TILEB;
            const int nidx = idx + 2;
            const size_t boff = (size_t)((nidx & 3) * 32) * CAD + (nidx >> 2) * 128;
#pragma unroll
            for (int i = 0; i < 2; ++i)
                cpa(st2 + doffB2[i], pB2[i] + boff);
            asm volatile("cp.async.commit_group;" ::: "memory");
        }
        const uint32_t stB = smb + PH2_B + stg2 * TILEB;
        const uint32_t stA = smb + PH2_ATT + (uint32_t)(idx & 3) * TILEB;
#pragma unroll
        for (int ks = 0; ks < 2; ++ks) {
            const int cu = 2 * ks + cgrp;
            const int browk = 16 * ks + rin + ((grp >> 1) << 3);
            uint32_t bt[2][4];
#pragma unroll
            for (int j = 0; j < 2; ++j) {
                const int bc = (nw >> 3) + 2 * j + (grp & 1);
                ldsm4t(bt[j], stB + swzbt(browk, bc));
            }
            uint32_t a2[2][4];
            ldsm4(a2[0], stA + swz(rowm[0], cu));
#pragma unroll
            for (int mi = 0; mi < 4; ++mi) {
                const int cur = mi & 1;
                if (mi < 3) ldsm4(a2[cur ^ 1], stA + swz(rowm[mi + 1], cu));
#pragma unroll
                for (int nj = 0; nj < 4; ++nj) {
                    const int j = nj >> 1, o = nj & 1;
                    mma_f16(acc2[mi][nj], a2[cur], bt[j][o], bt[j][o + 2]);
                }
            }
        }
        if ((idx & 3) == 3) {
            const int v0 = (idx >> 2) * 128;
#pragma unroll
            for (int mi = 0; mi < 4; ++mi)
#pragma unroll
                for (int nj = 0; nj < 4; ++nj) {
                    size_t r0 = (size_t)b * CT + m0 + mw + mi * 16 + qr;
                    int gc = v0 + nw + nj * 8 + qc;
                    *(float2*)(OUT + r0 * CAD + gc) =
                        make_float2(acc2[mi][nj][0], acc2[mi][nj][1]);
                    *(float2*)(OUT + (r0 + 8) * CAD + gc) =
                        make_float2(acc2[mi][nj][2], acc2[mi][nj][3]);
                    acc2[mi][nj][0] = 0.f; acc2[mi][nj][1] = 0.f;
                    acc2[mi][nj][2] = 0.f; acc2[mi][nj][3] = 0.f;
                }
        }
        if (++stg2 == 3) stg2 = 0;
    }
}

// ---------------------------------------------------------------------------
extern "C" void kernel_launch(void* const* d_in, const int* in_sizes, int n_in,
                              void* d_out, int out_size) {
    const float* inputs = (const float*)d_in[0];
    const float* ao     = (const float*)d_in[1];
    const void*  mask   = d_in[2];
    const float* W      = (const float*)d_in[3];
    const float* a_w    = (const float*)d_in[4];
    const float* b_w    = (const float*)d_in[5];
    const float* bias   = (const float*)d_in[6];
    float* out = (float*)d_out;

    cudaFuncSetAttribute(g1x,     cudaFuncAttributeMaxDynamicSharedMemorySize, SMEM_G1);
    cudaFuncSetAttribute(g23_mma, cudaFuncAttributeMaxDynamicSharedMemorySize, SMEM_G23);

    pre_a<<<PA_LIN + PA_WT + 1, 256>>>(ao, a_w, W,
                                       (const unsigned char*)mask);   // 0
    g1x<<<dim3(20, 256), 256, SMEM_G1>>>(inputs, b_w);                // 1
    g23_mma<<<dim3(2, CB), 256, SMEM_G23>>>(bias, out);               // 2
}